// round 1
// baseline (speedup 1.0000x reference)
#include <cuda_runtime.h>
#include <math.h>

// ---------------------------------------------------------------------------
// Model_24730421690434: encoder GEMM -> context norm -> 33-step memory-LSTM
//   B=512, T=32, P*P=1024, Z=128, K=256, H=512, 4H=2048, Y=4, M=T+1=33
// Strategy: fp32 baseline.
//   prep:      transpose/fuse weights, zero state        (1 launch)
//   enc_gemm:  z = X[16384,1024] @ W_enc[1024,128]       (1 launch)
//   ctx_norm:  per-(b,z) normalize over T                (1 launch)
//   recur:     persistent kernel, 33 steps, grid barrier (1 launch)
// ---------------------------------------------------------------------------

#define NB 128
#define NT 256

#define BD 512      // batch
#define TD 32       // seq len
#define ZD 128      // z size
#define KD 256      // key size
#define HD 512      // hidden
#define YD 4
#define MD 33       // T+1
#define G4 2048     // 4*H
#define KIN 784     // padded inner dim: [0,257) key_r | [257,260) pad | [260,772) h | [772,784) pad
#define OFFH 260

// ------------------------------- device state ------------------------------
__device__ __align__(256) float d_WgT[KIN * G4];     // fused transposed [W_ih | W_hh]
__device__ __align__(256) float d_biasg[G4];         // b_ih + b_hh
__device__ __align__(256) float d_WkT[HD * KD];      // W_key^T
__device__ __align__(256) float d_zbuf[BD * TD * ZD]; // normalized z (== M_v slots 0..31)
__device__ __align__(256) float d_xin[BD * KIN];     // [key_r | h] per batch row
__device__ __align__(256) float d_cst[BD * HD];      // LSTM cell state
__device__ __align__(256) float d_gates[BD * G4];
__device__ __align__(256) float d_Mk[(size_t)BD * MD * KD];
__device__ __align__(256) float d_wk[BD * MD];
__device__ __align__(256) float d_ck[BD * MD];
__device__ unsigned g_cnt;
__device__ unsigned g_gen;

__device__ __forceinline__ float sigm(float x) { return 1.f / (1.f + expf(-x)); }

// sense-reversal grid barrier; count self-resets so it is launch-invariant
__device__ __forceinline__ void gridBarrier() {
    __syncthreads();
    if (threadIdx.x == 0) {
        unsigned gen = *(volatile unsigned*)&g_gen;
        __threadfence();
        unsigned t = atomicAdd(&g_cnt, 1u);
        if (t == NB - 1u) {
            g_cnt = 0u;
            __threadfence();
            atomicAdd(&g_gen, 1u);
        } else {
            while (*(volatile unsigned*)&g_gen == gen) { __nanosleep(64); }
        }
        __threadfence();
    }
    __syncthreads();
}

// ------------------- 64x128 fp32 tile GEMM (BK=16, 256 thr) ----------------
__device__ __forceinline__ void mm64x128(const float* __restrict__ A, int lda,
                                         const float* __restrict__ B, int ldb,
                                         int m0, int n0, int Kt,
                                         float (&acc)[4][8], float* As, float* Bs)
{
    const int tid = threadIdx.x;
    const int tx = tid & 15, ty = tid >> 4;
#pragma unroll
    for (int i = 0; i < 4; i++)
#pragma unroll
        for (int j = 0; j < 8; j++) acc[i][j] = 0.f;

    for (int k0 = 0; k0 < Kt; k0 += 16) {
        {   // A tile 64x16, stored transposed As[k][m]
            int r = tid >> 2, q = tid & 3;
            float4 av = *(const float4*)(A + (size_t)(m0 + r) * lda + k0 + q * 4);
            As[(q * 4 + 0) * 64 + r] = av.x;
            As[(q * 4 + 1) * 64 + r] = av.y;
            As[(q * 4 + 2) * 64 + r] = av.z;
            As[(q * 4 + 3) * 64 + r] = av.w;
        }
#pragma unroll
        for (int jj = 0; jj < 2; jj++) {  // B tile 16x128
            int idx = tid + jj * 256;
            int kk = idx >> 5, qq = idx & 31;
            *(float4*)(Bs + kk * 128 + qq * 4) =
                *(const float4*)(B + (size_t)(k0 + kk) * ldb + n0 + qq * 4);
        }
        __syncthreads();
#pragma unroll
        for (int kk = 0; kk < 16; kk++) {
            float a[4];
#pragma unroll
            for (int i = 0; i < 4; i++) a[i] = As[kk * 64 + ty * 4 + i];
            float4 b0 = *(const float4*)(Bs + kk * 128 + tx * 8);
            float4 b1 = *(const float4*)(Bs + kk * 128 + tx * 8 + 4);
            float bb[8] = {b0.x, b0.y, b0.z, b0.w, b1.x, b1.y, b1.z, b1.w};
#pragma unroll
            for (int i = 0; i < 4; i++)
#pragma unroll
                for (int j = 0; j < 8; j++) acc[i][j] = fmaf(a[i], bb[j], acc[i][j]);
        }
        __syncthreads();
    }
}

// ------------------------------- prep kernel -------------------------------
__global__ void __launch_bounds__(NT) prep_kernel(
    const float* __restrict__ W_ih, const float* __restrict__ W_hh,
    const float* __restrict__ b_ih, const float* __restrict__ b_hh,
    const float* __restrict__ W_key)
{
    for (int idx = blockIdx.x * blockDim.x + threadIdx.x; idx < KIN * G4;
         idx += gridDim.x * blockDim.x) {
        int k = idx >> 11, n = idx & 2047;
        float v = 0.f;
        if (k < 257)                 v = W_ih[n * 257 + k];
        else if (k >= OFFH && k < OFFH + HD) v = W_hh[n * HD + (k - OFFH)];
        d_WgT[idx] = v;
        if (idx < HD * KD) {
            int kk = idx >> 8, nn = idx & 255;
            d_WkT[idx] = W_key[nn * HD + kk];
        }
        if (idx < G4)       d_biasg[idx] = b_ih[idx] + b_hh[idx];
        if (idx < BD * KIN) d_xin[idx] = 0.f;
        if (idx < BD * HD)  d_cst[idx] = 0.f;
    }
}

// ------------------------------ encoder GEMM -------------------------------
__global__ void __launch_bounds__(NT) enc_gemm(const float* __restrict__ X,
                                               const float* __restrict__ W)
{
    __shared__ float As[16 * 64];
    __shared__ float Bs[16 * 128];
    int m0 = blockIdx.x * 64;
    float acc[4][8];
    mm64x128(X, 1024, W, 128, m0, 0, 1024, acc, As, Bs);
    int tx = threadIdx.x & 15, ty = threadIdx.x >> 4;
#pragma unroll
    for (int i = 0; i < 4; i++)
#pragma unroll
        for (int j = 0; j < 8; j++)
            d_zbuf[(size_t)(m0 + ty * 4 + i) * ZD + tx * 8 + j] = acc[i][j];
}

// ------------------------------ context norm -------------------------------
__global__ void __launch_bounds__(128) ctx_norm(const float* __restrict__ gamma,
                                                const float* __restrict__ beta)
{
    int b = blockIdx.x, z = threadIdx.x;
    float v[TD];
    float s = 0.f;
#pragma unroll
    for (int t = 0; t < TD; t++) { v[t] = d_zbuf[((b * TD) + t) * ZD + z]; s += v[t]; }
    float mu = s * (1.f / TD);
    float q = 0.f;
#pragma unroll
    for (int t = 0; t < TD; t++) { float d = v[t] - mu; q += d * d; }
    float inv = rsqrtf(q * (1.f / TD) + 1e-8f);
    float ga = gamma[z], be = beta[z];
#pragma unroll
    for (int t = 0; t < TD; t++)
        d_zbuf[((b * TD) + t) * ZD + z] = (v[t] - mu) * inv * ga + be;
}

// ------------------------- persistent recurrence ---------------------------
__global__ void __launch_bounds__(NT) recur(
    const float* __restrict__ b_key, const float* __restrict__ W_g,
    const float* __restrict__ b_g,   const float* __restrict__ cgain,
    const float* __restrict__ cbias, const float* __restrict__ W_y,
    const float* __restrict__ b_y,   void* outp, int out_size)
{
    __shared__ float As[16 * 64];
    __shared__ float Bs[16 * 128];
    __shared__ float s_sc[256];
    const int tid = threadIdx.x;
    const int bx = blockIdx.x;
    const int lane = tid & 31, wid = tid >> 5;

    for (int t = 0; t < MD; t++) {
        // ---------------- Phase A: gate GEMM (+ attention scores) ----------
        {
            int m0 = (bx >> 4) * 64;
            int n0 = (bx & 15) * 128;
            float acc[4][8];
            mm64x128(d_xin, KIN, d_WgT, G4, m0, n0, KIN, acc, As, Bs);
            int tx = tid & 15, ty = tid >> 4;
#pragma unroll
            for (int i = 0; i < 4; i++)
#pragma unroll
                for (int j = 0; j < 8; j++) {
                    int row = m0 + ty * 4 + i, col = n0 + tx * 8 + j;
                    d_gates[(size_t)row * G4 + col] = acc[i][j] + d_biasg[col];
                }
        }
        if (t >= 1 && t < TD) {  // scores + softmax + confidence
            int bb = bx * 4 + (tid >> 6);
            int m = tid & 63;
            float s = 0.f;
            if (m < t) {
                const float* zt = d_zbuf + (size_t)(bb * TD + t) * ZD;
                const float* zm = d_zbuf + (size_t)(bb * TD + m) * ZD;
#pragma unroll 4
                for (int i = 0; i < ZD; i++) s += zt[i] * zm[i];
                d_ck[bb * MD + m] = sigm(s * cgain[0] + cbias[0]);
            }
            s_sc[tid] = s;
            __syncthreads();
            if (m == 0) {
                float mx = -3.4e38f;
                for (int mm = 0; mm < t; mm++) mx = fmaxf(mx, s_sc[tid + mm]);
                float sum = 0.f;
                for (int mm = 0; mm < t; mm++) {
                    float e = expf(s_sc[tid + mm] - mx);
                    d_wk[bb * MD + mm] = e;
                    sum += e;
                }
                float inv = 1.f / sum;
                for (int mm = 0; mm < t; mm++) d_wk[bb * MD + mm] *= inv;
            }
        }
        gridBarrier();

        // ---------------- Phase B: LSTM cell pointwise ----------------------
        {
            int base = bx * NT + tid;
#pragma unroll
            for (int u = 0; u < 8; u++) {
                int e = base + u * (NB * NT);
                int b = e >> 9, j = e & 511;
                const float* gr = d_gates + (size_t)b * G4;
                float gi = gr[j], gf = gr[512 + j], gg = gr[1024 + j], go = gr[1536 + j];
                float c = sigm(gf) * d_cst[e] + sigm(gi) * tanhf(gg);
                d_cst[e] = c;
                d_xin[b * KIN + OFFH + j] = sigm(go) * tanhf(c);
            }
        }
        gridBarrier();

        // ---------------- Phase C: key_w GEMM | attention | output ---------
        if (t < TD) {
            if (bx < 64) {  // key_w = relu(h @ W_key^T + b_key) -> M_k[:,t,:]
                int m0 = (bx >> 3) * 64, n0 = (bx & 7) * 32;
                float acc[4][2];
#pragma unroll
                for (int i = 0; i < 4; i++) { acc[i][0] = 0.f; acc[i][1] = 0.f; }
                for (int k0 = 0; k0 < HD; k0 += 16) {
                    int r = tid >> 2, q = tid & 3;
                    float4 av = *(const float4*)(d_xin + (size_t)(m0 + r) * KIN + OFFH + k0 + q * 4);
                    As[(q * 4 + 0) * 64 + r] = av.x;
                    As[(q * 4 + 1) * 64 + r] = av.y;
                    As[(q * 4 + 2) * 64 + r] = av.z;
                    As[(q * 4 + 3) * 64 + r] = av.w;
                    if (tid < 128) {
                        int kk = tid >> 3, qq = tid & 7;
                        *(float4*)(Bs + kk * 32 + qq * 4) =
                            *(const float4*)(d_WkT + (size_t)(k0 + kk) * KD + n0 + qq * 4);
                    }
                    __syncthreads();
#pragma unroll
                    for (int kk = 0; kk < 16; kk++) {
                        float a[4];
#pragma unroll
                        for (int i = 0; i < 4; i++) a[i] = As[kk * 64 + (tid >> 4) * 4 + i];
                        float bb0 = Bs[kk * 32 + (tid & 15) * 2];
                        float bb1 = Bs[kk * 32 + (tid & 15) * 2 + 1];
#pragma unroll
                        for (int i = 0; i < 4; i++) {
                            acc[i][0] = fmaf(a[i], bb0, acc[i][0]);
                            acc[i][1] = fmaf(a[i], bb1, acc[i][1]);
                        }
                    }
                    __syncthreads();
                }
                int tx = tid & 15, ty = tid >> 4;
#pragma unroll
                for (int i = 0; i < 4; i++)
#pragma unroll
                    for (int j = 0; j < 2; j++) {
                        int row = m0 + ty * 4 + i, col = n0 + tx * 2 + j;
                        float v = acc[i][j] + b_key[col];
                        d_Mk[((size_t)row * MD + t) * KD + col] = v > 0.f ? v : 0.f;
                    }
            } else {  // gate g + attention read -> key_r (xin[0:257))
                int bb = (bx - 64) * 8 + wid;
                const float* hb = d_xin + (size_t)bb * KIN + OFFH;
                float s = 0.f;
                for (int l = lane; l < HD; l += 32) s += hb[l] * W_g[l];
#pragma unroll
                for (int o = 16; o; o >>= 1) s += __shfl_xor_sync(0xffffffffu, s, o);
                float gv = sigm(s + b_g[0]);
                const float* wkb = d_wk + bb * MD;
                const float* ckb = d_ck + bb * MD;
                const float* mkb = d_Mk + (size_t)bb * MD * KD;
                for (int d = lane; d < 257; d += 32) {
                    float a = 0.f;
                    if (d < 256) { for (int m = 0; m < t; m++) a += wkb[m] * mkb[m * KD + d]; }
                    else         { for (int m = 0; m < t; m++) a += wkb[m] * ckb[m]; }
                    d_xin[bb * KIN + d] = gv * a;  // zero at t==0 (empty sum)
                }
            }
            gridBarrier();
        } else {  // t == 32: y_lin + argmax, write outputs
            if (bx >= 64) {
                int bb = (bx - 64) * 8 + wid;
                const float* hb = d_xin + (size_t)bb * KIN + OFFH;
                float yv[4];
#pragma unroll
                for (int yi = 0; yi < YD; yi++) {
                    float s = 0.f;
                    for (int l = lane; l < HD; l += 32) s += hb[l] * W_y[yi * HD + l];
#pragma unroll
                    for (int o = 16; o; o >>= 1) s += __shfl_xor_sync(0xffffffffu, s, o);
                    yv[yi] = s + b_y[yi];
                }
                if (lane == 0) {
                    int am = 0; float bst = yv[0];
#pragma unroll
                    for (int yi = 1; yi < YD; yi++)
                        if (yv[yi] > bst) { bst = yv[yi]; am = yi; }
                    if (out_size >= BD * YD) {
                        float* of = (float*)outp;
                        of[bb * 4 + 0] = yv[0];
                        of[bb * 4 + 1] = yv[1];
                        of[bb * 4 + 2] = yv[2];
                        of[bb * 4 + 3] = yv[3];
                        if (out_size >= BD * YD + BD) of[BD * YD + bb] = (float)am;
                    } else {
                        ((int*)outp)[bb] = am;  // argmax-only output variant
                    }
                }
            }
        }
    }
}

// ------------------------------- launcher ----------------------------------
extern "C" void kernel_launch(void* const* d_in, const int* in_sizes, int n_in,
                              void* d_out, int out_size)
{
    const float* x_seq  = (const float*)d_in[0];
    const float* W_enc  = (const float*)d_in[1];
    const float* gamma  = (const float*)d_in[2];
    const float* beta   = (const float*)d_in[3];
    const float* W_ih   = (const float*)d_in[4];
    const float* W_hh   = (const float*)d_in[5];
    const float* b_ih   = (const float*)d_in[6];
    const float* b_hh   = (const float*)d_in[7];
    const float* W_key  = (const float*)d_in[8];
    const float* b_key  = (const float*)d_in[9];
    const float* W_g    = (const float*)d_in[10];
    const float* b_g    = (const float*)d_in[11];
    const float* cgain  = (const float*)d_in[12];
    const float* cbias  = (const float*)d_in[13];
    const float* W_y    = (const float*)d_in[14];
    const float* b_y    = (const float*)d_in[15];

    prep_kernel<<<1024, NT>>>(W_ih, W_hh, b_ih, b_hh, W_key);
    enc_gemm<<<256, NT>>>(x_seq, W_enc);
    ctx_norm<<<BD, 128>>>(gamma, beta);
    recur<<<NB, NT>>>(b_key, W_g, b_g, cgain, cbias, W_y, b_y, d_out, out_size);
}

// round 2
// speedup vs baseline: 1.0084x; 1.0084x over previous
#include <cuda_runtime.h>
#include <math.h>

// ---------------------------------------------------------------------------
// Model_24730421690434: encoder GEMM -> context norm -> 33-step memory-LSTM
//   B=512, T=32, P*P=1024, Z=128, K=256, H=512, 4H=2048, Y=4, M=T+1=33
// Strategy: fp32 baseline.
//   prep:      transpose/fuse weights, zero state        (1 launch)
//   enc_gemm:  z = X[16384,1024] @ W_enc[1024,128]       (1 launch)
//   ctx_norm:  per-(b,z) normalize over T                (1 launch)
//   recur:     persistent kernel, 33 steps, grid barrier (1 launch)
// ---------------------------------------------------------------------------

#define NB 128
#define NT 256

#define BD 512      // batch
#define TD 32       // seq len
#define ZD 128      // z size
#define KD 256      // key size
#define HD 512      // hidden
#define YD 4
#define MD 33       // T+1
#define G4 2048     // 4*H
#define KIN 784     // padded inner dim: [0,257) key_r | [257,260) pad | [260,772) h | [772,784) pad
#define OFFH 260

// ------------------------------- device state ------------------------------
__device__ __align__(256) float d_WgT[KIN * G4];     // fused transposed [W_ih | W_hh]
__device__ __align__(256) float d_biasg[G4];         // b_ih + b_hh
__device__ __align__(256) float d_WkT[HD * KD];      // W_key^T
__device__ __align__(256) float d_zbuf[BD * TD * ZD]; // normalized z (== M_v slots 0..31)
__device__ __align__(256) float d_xin[BD * KIN];     // [key_r | h] per batch row
__device__ __align__(256) float d_cst[BD * HD];      // LSTM cell state
__device__ __align__(256) float d_gates[BD * G4];
__device__ __align__(256) float d_Mk[(size_t)BD * MD * KD];
__device__ __align__(256) float d_wk[BD * MD];
__device__ __align__(256) float d_ck[BD * MD];
__device__ unsigned g_cnt;
__device__ unsigned g_gen;

__device__ __forceinline__ float sigm(float x) { return 1.f / (1.f + expf(-x)); }

// sense-reversal grid barrier; count self-resets so it is launch-invariant
__device__ __forceinline__ void gridBarrier() {
    __syncthreads();
    if (threadIdx.x == 0) {
        unsigned gen = *(volatile unsigned*)&g_gen;
        __threadfence();
        unsigned t = atomicAdd(&g_cnt, 1u);
        if (t == NB - 1u) {
            g_cnt = 0u;
            __threadfence();
            atomicAdd(&g_gen, 1u);
        } else {
            while (*(volatile unsigned*)&g_gen == gen) { __nanosleep(64); }
        }
        __threadfence();
    }
    __syncthreads();
}

// ------------------- 64x128 fp32 tile GEMM (BK=16, 256 thr) ----------------
__device__ __forceinline__ void mm64x128(const float* __restrict__ A, int lda,
                                         const float* __restrict__ B, int ldb,
                                         int m0, int n0, int Kt,
                                         float (&acc)[4][8], float* As, float* Bs)
{
    const int tid = threadIdx.x;
    const int tx = tid & 15, ty = tid >> 4;
#pragma unroll
    for (int i = 0; i < 4; i++)
#pragma unroll
        for (int j = 0; j < 8; j++) acc[i][j] = 0.f;

    for (int k0 = 0; k0 < Kt; k0 += 16) {
        {   // A tile 64x16, stored transposed As[k][m]
            int r = tid >> 2, q = tid & 3;
            float4 av = *(const float4*)(A + (size_t)(m0 + r) * lda + k0 + q * 4);
            As[(q * 4 + 0) * 64 + r] = av.x;
            As[(q * 4 + 1) * 64 + r] = av.y;
            As[(q * 4 + 2) * 64 + r] = av.z;
            As[(q * 4 + 3) * 64 + r] = av.w;
        }
#pragma unroll
        for (int jj = 0; jj < 2; jj++) {  // B tile 16x128
            int idx = tid + jj * 256;
            int kk = idx >> 5, qq = idx & 31;
            *(float4*)(Bs + kk * 128 + qq * 4) =
                *(const float4*)(B + (size_t)(k0 + kk) * ldb + n0 + qq * 4);
        }
        __syncthreads();
#pragma unroll
        for (int kk = 0; kk < 16; kk++) {
            float a[4];
#pragma unroll
            for (int i = 0; i < 4; i++) a[i] = As[kk * 64 + ty * 4 + i];
            float4 b0 = *(const float4*)(Bs + kk * 128 + tx * 8);
            float4 b1 = *(const float4*)(Bs + kk * 128 + tx * 8 + 4);
            float bb[8] = {b0.x, b0.y, b0.z, b0.w, b1.x, b1.y, b1.z, b1.w};
#pragma unroll
            for (int i = 0; i < 4; i++)
#pragma unroll
                for (int j = 0; j < 8; j++) acc[i][j] = fmaf(a[i], bb[j], acc[i][j]);
        }
        __syncthreads();
    }
}

// ------------------------------- prep kernel -------------------------------
__global__ void __launch_bounds__(NT) prep_kernel(
    const float* __restrict__ W_ih, const float* __restrict__ W_hh,
    const float* __restrict__ b_ih, const float* __restrict__ b_hh,
    const float* __restrict__ W_key)
{
    for (int idx = blockIdx.x * blockDim.x + threadIdx.x; idx < KIN * G4;
         idx += gridDim.x * blockDim.x) {
        int k = idx >> 11, n = idx & 2047;
        float v = 0.f;
        if (k < 257)                 v = W_ih[n * 257 + k];
        else if (k >= OFFH && k < OFFH + HD) v = W_hh[n * HD + (k - OFFH)];
        d_WgT[idx] = v;
        if (idx < HD * KD) {
            int kk = idx >> 8, nn = idx & 255;
            d_WkT[idx] = W_key[nn * HD + kk];
        }
        if (idx < G4)       d_biasg[idx] = b_ih[idx] + b_hh[idx];
        if (idx < BD * KIN) d_xin[idx] = 0.f;
        if (idx < BD * HD)  d_cst[idx] = 0.f;
    }
}

// ------------------------------ encoder GEMM -------------------------------
__global__ void __launch_bounds__(NT) enc_gemm(const float* __restrict__ X,
                                               const float* __restrict__ W)
{
    __shared__ float As[16 * 64];
    __shared__ float Bs[16 * 128];
    int m0 = blockIdx.x * 64;
    float acc[4][8];
    mm64x128(X, 1024, W, 128, m0, 0, 1024, acc, As, Bs);
    int tx = threadIdx.x & 15, ty = threadIdx.x >> 4;
#pragma unroll
    for (int i = 0; i < 4; i++)
#pragma unroll
        for (int j = 0; j < 8; j++)
            d_zbuf[(size_t)(m0 + ty * 4 + i) * ZD + tx * 8 + j] = acc[i][j];
}

// ------------------------------ context norm -------------------------------
__global__ void __launch_bounds__(128) ctx_norm(const float* __restrict__ gamma,
                                                const float* __restrict__ beta)
{
    int b = blockIdx.x, z = threadIdx.x;
    float v[TD];
    float s = 0.f;
#pragma unroll
    for (int t = 0; t < TD; t++) { v[t] = d_zbuf[((b * TD) + t) * ZD + z]; s += v[t]; }
    float mu = s * (1.f / TD);
    float q = 0.f;
#pragma unroll
    for (int t = 0; t < TD; t++) { float d = v[t] - mu; q += d * d; }
    float inv = rsqrtf(q * (1.f / TD) + 1e-8f);
    float ga = gamma[z], be = beta[z];
#pragma unroll
    for (int t = 0; t < TD; t++)
        d_zbuf[((b * TD) + t) * ZD + z] = (v[t] - mu) * inv * ga + be;
}

// ------------------------- persistent recurrence ---------------------------
__global__ void __launch_bounds__(NT) recur(
    const float* __restrict__ b_key, const float* __restrict__ W_g,
    const float* __restrict__ b_g,   const float* __restrict__ cgain,
    const float* __restrict__ cbias, const float* __restrict__ W_y,
    const float* __restrict__ b_y,   void* outp, int out_size)
{
    __shared__ float As[16 * 64];
    __shared__ float Bs[16 * 128];
    __shared__ float s_sc[256];
    const int tid = threadIdx.x;
    const int bx = blockIdx.x;
    const int lane = tid & 31, wid = tid >> 5;

    for (int t = 0; t < MD; t++) {
        // ---------------- Phase A: gate GEMM (+ attention scores) ----------
        {
            int m0 = (bx >> 4) * 64;
            int n0 = (bx & 15) * 128;
            float acc[4][8];
            mm64x128(d_xin, KIN, d_WgT, G4, m0, n0, KIN, acc, As, Bs);
            int tx = tid & 15, ty = tid >> 4;
#pragma unroll
            for (int i = 0; i < 4; i++)
#pragma unroll
                for (int j = 0; j < 8; j++) {
                    int row = m0 + ty * 4 + i, col = n0 + tx * 8 + j;
                    d_gates[(size_t)row * G4 + col] = acc[i][j] + d_biasg[col];
                }
        }
        if (t >= 1 && t < TD) {  // scores + softmax + confidence
            int bb = bx * 4 + (tid >> 6);
            int m = tid & 63;
            float s = 0.f;
            if (m < t) {
                const float* zt = d_zbuf + (size_t)(bb * TD + t) * ZD;
                const float* zm = d_zbuf + (size_t)(bb * TD + m) * ZD;
#pragma unroll 4
                for (int i = 0; i < ZD; i++) s += zt[i] * zm[i];
                d_ck[bb * MD + m] = sigm(s * cgain[0] + cbias[0]);
            }
            s_sc[tid] = s;
            __syncthreads();
            if (m == 0) {
                float mx = -3.4e38f;
                for (int mm = 0; mm < t; mm++) mx = fmaxf(mx, s_sc[tid + mm]);
                float sum = 0.f;
                for (int mm = 0; mm < t; mm++) {
                    float e = expf(s_sc[tid + mm] - mx);
                    d_wk[bb * MD + mm] = e;
                    sum += e;
                }
                float inv = 1.f / sum;
                for (int mm = 0; mm < t; mm++) d_wk[bb * MD + mm] *= inv;
            }
        }
        gridBarrier();

        // ---------------- Phase B: LSTM cell pointwise ----------------------
        {
            int base = bx * NT + tid;
#pragma unroll
            for (int u = 0; u < 8; u++) {
                int e = base + u * (NB * NT);
                int b = e >> 9, j = e & 511;
                const float* gr = d_gates + (size_t)b * G4;
                float gi = gr[j], gf = gr[512 + j], gg = gr[1024 + j], go = gr[1536 + j];
                float c = sigm(gf) * d_cst[e] + sigm(gi) * tanhf(gg);
                d_cst[e] = c;
                d_xin[b * KIN + OFFH + j] = sigm(go) * tanhf(c);
            }
        }
        gridBarrier();

        // ---------------- Phase C: key_w GEMM | attention | output ---------
        if (t < TD) {
            if (bx < 64) {  // key_w = relu(h @ W_key^T + b_key) -> M_k[:,t,:]
                int m0 = (bx >> 3) * 64, n0 = (bx & 7) * 32;
                float acc[4][2];
#pragma unroll
                for (int i = 0; i < 4; i++) { acc[i][0] = 0.f; acc[i][1] = 0.f; }
                for (int k0 = 0; k0 < HD; k0 += 16) {
                    int r = tid >> 2, q = tid & 3;
                    float4 av = *(const float4*)(d_xin + (size_t)(m0 + r) * KIN + OFFH + k0 + q * 4);
                    As[(q * 4 + 0) * 64 + r] = av.x;
                    As[(q * 4 + 1) * 64 + r] = av.y;
                    As[(q * 4 + 2) * 64 + r] = av.z;
                    As[(q * 4 + 3) * 64 + r] = av.w;
                    if (tid < 128) {
                        int kk = tid >> 3, qq = tid & 7;
                        *(float4*)(Bs + kk * 32 + qq * 4) =
                            *(const float4*)(d_WkT + (size_t)(k0 + kk) * KD + n0 + qq * 4);
                    }
                    __syncthreads();
#pragma unroll
                    for (int kk = 0; kk < 16; kk++) {
                        float a[4];
#pragma unroll
                        for (int i = 0; i < 4; i++) a[i] = As[kk * 64 + (tid >> 4) * 4 + i];
                        float bb0 = Bs[kk * 32 + (tid & 15) * 2];
                        float bb1 = Bs[kk * 32 + (tid & 15) * 2 + 1];
#pragma unroll
                        for (int i = 0; i < 4; i++) {
                            acc[i][0] = fmaf(a[i], bb0, acc[i][0]);
                            acc[i][1] = fmaf(a[i], bb1, acc[i][1]);
                        }
                    }
                    __syncthreads();
                }
                int tx = tid & 15, ty = tid >> 4;
#pragma unroll
                for (int i = 0; i < 4; i++)
#pragma unroll
                    for (int j = 0; j < 2; j++) {
                        int row = m0 + ty * 4 + i, col = n0 + tx * 2 + j;
                        float v = acc[i][j] + b_key[col];
                        d_Mk[((size_t)row * MD + t) * KD + col] = v > 0.f ? v : 0.f;
                    }
            } else {  // gate g + attention read -> key_r (xin[0:257))
                int bb = (bx - 64) * 8 + wid;
                const float* hb = d_xin + (size_t)bb * KIN + OFFH;
                float s = 0.f;
                for (int l = lane; l < HD; l += 32) s += hb[l] * W_g[l];
#pragma unroll
                for (int o = 16; o; o >>= 1) s += __shfl_xor_sync(0xffffffffu, s, o);
                float gv = sigm(s + b_g[0]);
                const float* wkb = d_wk + bb * MD;
                const float* ckb = d_ck + bb * MD;
                const float* mkb = d_Mk + (size_t)bb * MD * KD;
                for (int d = lane; d < 257; d += 32) {
                    float a = 0.f;
                    if (d < 256) { for (int m = 0; m < t; m++) a += wkb[m] * mkb[m * KD + d]; }
                    else         { for (int m = 0; m < t; m++) a += wkb[m] * ckb[m]; }
                    d_xin[bb * KIN + d] = gv * a;  // zero at t==0 (empty sum)
                }
            }
            gridBarrier();
        } else {  // t == 32: y_lin + argmax, write outputs
            if (bx >= 64) {
                int bb = (bx - 64) * 8 + wid;
                const float* hb = d_xin + (size_t)bb * KIN + OFFH;
                float yv[4];
#pragma unroll
                for (int yi = 0; yi < YD; yi++) {
                    float s = 0.f;
                    for (int l = lane; l < HD; l += 32) s += hb[l] * W_y[yi * HD + l];
#pragma unroll
                    for (int o = 16; o; o >>= 1) s += __shfl_xor_sync(0xffffffffu, s, o);
                    yv[yi] = s + b_y[yi];
                }
                if (lane == 0) {
                    int am = 0; float bst = yv[0];
#pragma unroll
                    for (int yi = 1; yi < YD; yi++)
                        if (yv[yi] > bst) { bst = yv[yi]; am = yi; }
                    if (out_size >= BD * YD) {
                        float* of = (float*)outp;
                        of[bb * 4 + 0] = yv[0];
                        of[bb * 4 + 1] = yv[1];
                        of[bb * 4 + 2] = yv[2];
                        of[bb * 4 + 3] = yv[3];
                        if (out_size >= BD * YD + BD) of[BD * YD + bb] = (float)am;
                    } else {
                        ((int*)outp)[bb] = am;  // argmax-only output variant
                    }
                }
            }
        }
    }
}

// ------------------------------- launcher ----------------------------------
extern "C" void kernel_launch(void* const* d_in, const int* in_sizes, int n_in,
                              void* d_out, int out_size)
{
    const float* x_seq  = (const float*)d_in[0];
    const float* W_enc  = (const float*)d_in[1];
    const float* gamma  = (const float*)d_in[2];
    const float* beta   = (const float*)d_in[3];
    const float* W_ih   = (const float*)d_in[4];
    const float* W_hh   = (const float*)d_in[5];
    const float* b_ih   = (const float*)d_in[6];
    const float* b_hh   = (const float*)d_in[7];
    const float* W_key  = (const float*)d_in[8];
    const float* b_key  = (const float*)d_in[9];
    const float* W_g    = (const float*)d_in[10];
    const float* b_g    = (const float*)d_in[11];
    const float* cgain  = (const float*)d_in[12];
    const float* cbias  = (const float*)d_in[13];
    const float* W_y    = (const float*)d_in[14];
    const float* b_y    = (const float*)d_in[15];

    prep_kernel<<<1024, NT>>>(W_ih, W_hh, b_ih, b_hh, W_key);
    enc_gemm<<<256, NT>>>(x_seq, W_enc);
    ctx_norm<<<BD, 128>>>(gamma, beta);
    recur<<<NB, NT>>>(b_key, W_g, b_g, cgain, cbias, W_y, b_y, d_out, out_size);
}

// round 3
// speedup vs baseline: 1.6194x; 1.6060x over previous
#include <cuda_runtime.h>
#include <cuda_bf16.h>
#include <math.h>

// ---------------------------------------------------------------------------
// Model_24730421690434: encoder GEMM -> context norm -> 33-step memory-LSTM
//   B=512, T=32, P*P=1024, Z=128, K=256, H=512, 4H=2048, Y=4, M=T+1=33
// R2: gate GEMM moved to tensor cores (mma.sync bf16, split hi/lo 3-MMA for
//     fp32-class accuracy). Everything else as R1 fp32 baseline.
// ---------------------------------------------------------------------------

#define NB 128
#define NT 256

#define BD 512      // batch
#define TD 32       // seq len
#define ZD 128      // z size
#define KD 256      // key size
#define HD 512      // hidden
#define YD 4
#define MD 33       // T+1
#define G4 2048     // 4*H
#define KIN 784     // inner dim: [0,257) key_r | [257,272) pad | [272,784) h
#define OFFH 272
#define KCH 49      // 784/16 k-chunks

// ------------------------------- device state ------------------------------
__device__ __align__(256) __nv_bfloat16 d_Bhi[(size_t)G4 * KIN]; // weights hi [n][k]
__device__ __align__(256) __nv_bfloat16 d_Blo[(size_t)G4 * KIN]; // weights lo [n][k]
__device__ __align__(256) __nv_bfloat16 d_Ahi[(size_t)BD * KIN]; // activ hi [b][k]
__device__ __align__(256) __nv_bfloat16 d_Alo[(size_t)BD * KIN]; // activ lo [b][k]
__device__ __align__(256) float d_biasg[G4];          // b_ih + b_hh
__device__ __align__(256) float d_WkT[HD * KD];       // W_key^T
__device__ __align__(256) float d_zbuf[BD * TD * ZD]; // normalized z (== M_v)
__device__ __align__(256) float d_xin[BD * KIN];      // fp32 h (and pad)
__device__ __align__(256) float d_cst[BD * HD];       // LSTM cell state
__device__ __align__(256) float d_gates[BD * G4];
__device__ __align__(256) float d_Mk[(size_t)BD * MD * KD];
__device__ __align__(256) float d_wk[BD * MD];
__device__ __align__(256) float d_ck[BD * MD];
__device__ unsigned g_cnt;
__device__ unsigned g_gen;

__device__ __forceinline__ float sigm(float x) { return 1.f / (1.f + expf(-x)); }

__device__ __forceinline__ void gridBarrier() {
    __syncthreads();
    if (threadIdx.x == 0) {
        unsigned gen = *(volatile unsigned*)&g_gen;
        __threadfence();
        unsigned t = atomicAdd(&g_cnt, 1u);
        if (t == NB - 1u) {
            g_cnt = 0u;
            __threadfence();
            atomicAdd(&g_gen, 1u);
        } else {
            while (*(volatile unsigned*)&g_gen == gen) { __nanosleep(64); }
        }
        __threadfence();
    }
    __syncthreads();
}

// ----------------------------- mma helpers ---------------------------------
__device__ __forceinline__ void cpasync16(void* dst, const void* src) {
    unsigned saddr = (unsigned)__cvta_generic_to_shared(dst);
    asm volatile("cp.async.cg.shared.global [%0], [%1], 16;\n" ::"r"(saddr), "l"(src));
}
#define CPCOMMIT() asm volatile("cp.async.commit_group;\n" ::)
#define CPWAIT(n)  asm volatile("cp.async.wait_group %0;\n" ::"n"(n))

__device__ __forceinline__ void mma16816(float* d, const unsigned* a, const unsigned* b) {
    asm volatile(
        "mma.sync.aligned.m16n8k16.row.col.f32.bf16.bf16.f32 "
        "{%0,%1,%2,%3},{%4,%5,%6,%7},{%8,%9},{%0,%1,%2,%3};"
        : "+f"(d[0]), "+f"(d[1]), "+f"(d[2]), "+f"(d[3])
        : "r"(a[0]), "r"(a[1]), "r"(a[2]), "r"(a[3]), "r"(b[0]), "r"(b[1]));
}

// ------------------- 64x128 fp32 tile GEMM (encoder only) ------------------
__device__ __forceinline__ void mm64x128(const float* __restrict__ A, int lda,
                                         const float* __restrict__ B, int ldb,
                                         int m0, int n0, int Kt,
                                         float (&acc)[4][8], float* As, float* Bs)
{
    const int tid = threadIdx.x;
    const int tx = tid & 15, ty = tid >> 4;
#pragma unroll
    for (int i = 0; i < 4; i++)
#pragma unroll
        for (int j = 0; j < 8; j++) acc[i][j] = 0.f;

    for (int k0 = 0; k0 < Kt; k0 += 16) {
        {
            int r = tid >> 2, q = tid & 3;
            float4 av = *(const float4*)(A + (size_t)(m0 + r) * lda + k0 + q * 4);
            As[(q * 4 + 0) * 64 + r] = av.x;
            As[(q * 4 + 1) * 64 + r] = av.y;
            As[(q * 4 + 2) * 64 + r] = av.z;
            As[(q * 4 + 3) * 64 + r] = av.w;
        }
#pragma unroll
        for (int jj = 0; jj < 2; jj++) {
            int idx = tid + jj * 256;
            int kk = idx >> 5, qq = idx & 31;
            *(float4*)(Bs + kk * 128 + qq * 4) =
                *(const float4*)(B + (size_t)(k0 + kk) * ldb + n0 + qq * 4);
        }
        __syncthreads();
#pragma unroll
        for (int kk = 0; kk < 16; kk++) {
            float a[4];
#pragma unroll
            for (int i = 0; i < 4; i++) a[i] = As[kk * 64 + ty * 4 + i];
            float4 b0 = *(const float4*)(Bs + kk * 128 + tx * 8);
            float4 b1 = *(const float4*)(Bs + kk * 128 + tx * 8 + 4);
            float bb[8] = {b0.x, b0.y, b0.z, b0.w, b1.x, b1.y, b1.z, b1.w};
#pragma unroll
            for (int i = 0; i < 4; i++)
#pragma unroll
                for (int j = 0; j < 8; j++) acc[i][j] = fmaf(a[i], bb[j], acc[i][j]);
        }
        __syncthreads();
    }
}

// ------------------------------- prep kernel -------------------------------
__global__ void __launch_bounds__(NT) prep_kernel(
    const float* __restrict__ W_ih, const float* __restrict__ W_hh,
    const float* __restrict__ b_ih, const float* __restrict__ b_hh,
    const float* __restrict__ W_key)
{
    for (int idx = blockIdx.x * blockDim.x + threadIdx.x; idx < G4 * KIN;
         idx += gridDim.x * blockDim.x) {
        int n = idx / KIN, k = idx - n * KIN;
        float v = 0.f;
        if (k < 257)                       v = W_ih[n * 257 + k];
        else if (k >= OFFH)                v = W_hh[n * HD + (k - OFFH)];
        __nv_bfloat16 hi = __float2bfloat16_rn(v);
        d_Bhi[idx] = hi;
        d_Blo[idx] = __float2bfloat16_rn(v - __bfloat162float(hi));
        if (idx < HD * KD) {
            int kk = idx >> 8, nn = idx & 255;
            d_WkT[idx] = W_key[nn * HD + kk];
        }
        if (idx < G4)        d_biasg[idx] = b_ih[idx] + b_hh[idx];
        if (idx < BD * KIN) {
            d_xin[idx] = 0.f;
            d_Ahi[idx] = __float2bfloat16_rn(0.f);
            d_Alo[idx] = __float2bfloat16_rn(0.f);
        }
        if (idx < BD * HD)   d_cst[idx] = 0.f;
    }
}

// ------------------------------ encoder GEMM -------------------------------
__global__ void __launch_bounds__(NT) enc_gemm(const float* __restrict__ X,
                                               const float* __restrict__ W)
{
    __shared__ float As[16 * 64];
    __shared__ float Bs[16 * 128];
    int m0 = blockIdx.x * 64;
    float acc[4][8];
    mm64x128(X, 1024, W, 128, m0, 0, 1024, acc, As, Bs);
    int tx = threadIdx.x & 15, ty = threadIdx.x >> 4;
#pragma unroll
    for (int i = 0; i < 4; i++)
#pragma unroll
        for (int j = 0; j < 8; j++)
            d_zbuf[(size_t)(m0 + ty * 4 + i) * ZD + tx * 8 + j] = acc[i][j];
}

// ------------------------------ context norm -------------------------------
__global__ void __launch_bounds__(128) ctx_norm(const float* __restrict__ gamma,
                                                const float* __restrict__ beta)
{
    int b = blockIdx.x, z = threadIdx.x;
    float v[TD];
    float s = 0.f;
#pragma unroll
    for (int t = 0; t < TD; t++) { v[t] = d_zbuf[((b * TD) + t) * ZD + z]; s += v[t]; }
    float mu = s * (1.f / TD);
    float q = 0.f;
#pragma unroll
    for (int t = 0; t < TD; t++) { float d = v[t] - mu; q += d * d; }
    float inv = rsqrtf(q * (1.f / TD) + 1e-8f);
    float ga = gamma[z], be = beta[z];
#pragma unroll
    for (int t = 0; t < TD; t++)
        d_zbuf[((b * TD) + t) * ZD + z] = (v[t] - mu) * inv * ga + be;
}

// ------------------------- persistent recurrence ---------------------------
__global__ void __launch_bounds__(NT) recur(
    const float* __restrict__ b_key, const float* __restrict__ W_g,
    const float* __restrict__ b_g,   const float* __restrict__ cgain,
    const float* __restrict__ cbias, const float* __restrict__ W_y,
    const float* __restrict__ b_y,   void* outp, int out_size)
{
    __shared__ float As[16 * 64];
    __shared__ float Bs[16 * 128];
    __shared__ float s_sc[256];
    __shared__ __align__(16) __nv_bfloat16 sA[2][2][64 * 16];   // [buf][hi/lo]
    __shared__ __align__(16) __nv_bfloat16 sB[2][2][128 * 16];  // [buf][hi/lo]

    const int tid = threadIdx.x;
    const int bx = blockIdx.x;
    const int lane = tid & 31, wid = tid >> 5;
    const int lr = lane >> 2, lc = lane & 3;

    const int m0 = (bx >> 4) * 64;
    const int n0 = (bx & 15) * 128;
    const int wm = wid & 1, wn = wid >> 1;

    // per-thread cp.async source/dest mapping (k0 added per chunk)
    const int a_part = tid & 1, a_row = (tid >> 1) & 63, a_half = tid >> 7;
    const __nv_bfloat16* a_srcbase =
        (a_half ? d_Alo : d_Ahi) + (size_t)(m0 + a_row) * KIN + a_part * 8;

    for (int t = 0; t < MD; t++) {
        // ---------------- Phase A: gate GEMM on tensor cores ---------------
        {
            float acc[2][4][4];
#pragma unroll
            for (int i = 0; i < 2; i++)
#pragma unroll
                for (int j = 0; j < 4; j++)
#pragma unroll
                    for (int r = 0; r < 4; r++) acc[i][j][r] = 0.f;

            // preload chunk 0 -> buf 0
            {
                cpasync16(&sA[0][a_half][a_row * 16 + a_part * 8], a_srcbase);
#pragma unroll
                for (int v = 0; v < 2; v++) {
                    int idx = tid + v * 256;
                    int part = idx & 1, row = (idx >> 1) & 127, half = idx >> 8;
                    cpasync16(&sB[0][half][row * 16 + part * 8],
                              (half ? d_Blo : d_Bhi) + (size_t)(n0 + row) * KIN + part * 8);
                }
                CPCOMMIT();
            }

            for (int c = 0; c < KCH; c++) {
                if (c < KCH - 1) {
                    int k0 = (c + 1) * 16;
                    int buf = (c + 1) & 1;
                    cpasync16(&sA[buf][a_half][a_row * 16 + a_part * 8], a_srcbase + k0);
#pragma unroll
                    for (int v = 0; v < 2; v++) {
                        int idx = tid + v * 256;
                        int part = idx & 1, row = (idx >> 1) & 127, half = idx >> 8;
                        cpasync16(&sB[buf][half][row * 16 + part * 8],
                                  (half ? d_Blo : d_Bhi) + (size_t)(n0 + row) * KIN + k0 + part * 8);
                    }
                    CPCOMMIT();
                    CPWAIT(1);
                } else {
                    CPWAIT(0);
                }
                __syncthreads();

                int buf = c & 1;
                const unsigned* pAh = (const unsigned*)sA[buf][0];
                const unsigned* pAl = (const unsigned*)sA[buf][1];
                const unsigned* pBh = (const unsigned*)sB[buf][0];
                const unsigned* pBl = (const unsigned*)sB[buf][1];

                unsigned aH[2][4], aL[2][4], bH[4][2], bL[4][2];
#pragma unroll
                for (int i = 0; i < 2; i++) {
                    int R = wm * 32 + i * 16 + lr;
                    aH[i][0] = pAh[R * 8 + lc];
                    aH[i][1] = pAh[(R + 8) * 8 + lc];
                    aH[i][2] = pAh[R * 8 + 4 + lc];
                    aH[i][3] = pAh[(R + 8) * 8 + 4 + lc];
                    aL[i][0] = pAl[R * 8 + lc];
                    aL[i][1] = pAl[(R + 8) * 8 + lc];
                    aL[i][2] = pAl[R * 8 + 4 + lc];
                    aL[i][3] = pAl[(R + 8) * 8 + 4 + lc];
                }
#pragma unroll
                for (int j = 0; j < 4; j++) {
                    int Nc = wn * 32 + j * 8 + lr;
                    bH[j][0] = pBh[Nc * 8 + lc];
                    bH[j][1] = pBh[Nc * 8 + 4 + lc];
                    bL[j][0] = pBl[Nc * 8 + lc];
                    bL[j][1] = pBl[Nc * 8 + 4 + lc];
                }
#pragma unroll
                for (int i = 0; i < 2; i++)
#pragma unroll
                    for (int j = 0; j < 4; j++) {
                        mma16816(acc[i][j], aH[i], bH[j]);
                        mma16816(acc[i][j], aH[i], bL[j]);
                        mma16816(acc[i][j], aL[i], bH[j]);
                    }
                __syncthreads();
            }
            // epilogue: add bias, write gates
#pragma unroll
            for (int i = 0; i < 2; i++) {
                int row0 = m0 + wm * 32 + i * 16 + lr;
#pragma unroll
                for (int j = 0; j < 4; j++) {
                    int col = n0 + wn * 32 + j * 8 + lc * 2;
                    float bz0 = d_biasg[col], bz1 = d_biasg[col + 1];
                    d_gates[(size_t)row0 * G4 + col]           = acc[i][j][0] + bz0;
                    d_gates[(size_t)row0 * G4 + col + 1]       = acc[i][j][1] + bz1;
                    d_gates[(size_t)(row0 + 8) * G4 + col]     = acc[i][j][2] + bz0;
                    d_gates[(size_t)(row0 + 8) * G4 + col + 1] = acc[i][j][3] + bz1;
                }
            }
        }
        if (t >= 1 && t < TD) {  // scores + softmax + confidence
            int bb = bx * 4 + (tid >> 6);
            int m = tid & 63;
            float s = 0.f;
            if (m < t) {
                const float* zt = d_zbuf + (size_t)(bb * TD + t) * ZD;
                const float* zm = d_zbuf + (size_t)(bb * TD + m) * ZD;
#pragma unroll 4
                for (int i = 0; i < ZD; i++) s += zt[i] * zm[i];
                d_ck[bb * MD + m] = sigm(s * cgain[0] + cbias[0]);
            }
            s_sc[tid] = s;
            __syncthreads();
            if (m == 0) {
                float mx = -3.4e38f;
                for (int mm = 0; mm < t; mm++) mx = fmaxf(mx, s_sc[tid + mm]);
                float sum = 0.f;
                for (int mm = 0; mm < t; mm++) {
                    float e = expf(s_sc[tid + mm] - mx);
                    d_wk[bb * MD + mm] = e;
                    sum += e;
                }
                float inv = 1.f / sum;
                for (int mm = 0; mm < t; mm++) d_wk[bb * MD + mm] *= inv;
            }
        }
        gridBarrier();

        // ---------------- Phase B: LSTM cell pointwise ----------------------
        {
            int base = bx * NT + tid;
#pragma unroll
            for (int u = 0; u < 8; u++) {
                int e = base + u * (NB * NT);
                int b = e >> 9, j = e & 511;
                const float* gr = d_gates + (size_t)b * G4;
                float gi = gr[j], gf = gr[512 + j], gg = gr[1024 + j], go = gr[1536 + j];
                float c = sigm(gf) * d_cst[e] + sigm(gi) * tanhf(gg);
                d_cst[e] = c;
                float hv = sigm(go) * tanhf(c);
                d_xin[b * KIN + OFFH + j] = hv;
                __nv_bfloat16 hh = __float2bfloat16_rn(hv);
                d_Ahi[(size_t)b * KIN + OFFH + j] = hh;
                d_Alo[(size_t)b * KIN + OFFH + j] =
                    __float2bfloat16_rn(hv - __bfloat162float(hh));
            }
        }
        gridBarrier();

        // ---------------- Phase C: key_w GEMM | attention | output ---------
        if (t < TD) {
            if (bx < 64) {  // key_w = relu(h @ W_key^T + b_key) -> M_k[:,t,:]
                int km0 = (bx >> 3) * 64, kn0 = (bx & 7) * 32;
                float acc[4][2];
#pragma unroll
                for (int i = 0; i < 4; i++) { acc[i][0] = 0.f; acc[i][1] = 0.f; }
                for (int k0 = 0; k0 < HD; k0 += 16) {
                    int r = tid >> 2, q = tid & 3;
                    float4 av = *(const float4*)(d_xin + (size_t)(km0 + r) * KIN + OFFH + k0 + q * 4);
                    As[(q * 4 + 0) * 64 + r] = av.x;
                    As[(q * 4 + 1) * 64 + r] = av.y;
                    As[(q * 4 + 2) * 64 + r] = av.z;
                    As[(q * 4 + 3) * 64 + r] = av.w;
                    if (tid < 128) {
                        int kk = tid >> 3, qq = tid & 7;
                        *(float4*)(Bs + kk * 32 + qq * 4) =
                            *(const float4*)(d_WkT + (size_t)(k0 + kk) * KD + kn0 + qq * 4);
                    }
                    __syncthreads();
#pragma unroll
                    for (int kk = 0; kk < 16; kk++) {
                        float a[4];
#pragma unroll
                        for (int i = 0; i < 4; i++) a[i] = As[kk * 64 + (tid >> 4) * 4 + i];
                        float bb0 = Bs[kk * 32 + (tid & 15) * 2];
                        float bb1 = Bs[kk * 32 + (tid & 15) * 2 + 1];
#pragma unroll
                        for (int i = 0; i < 4; i++) {
                            acc[i][0] = fmaf(a[i], bb0, acc[i][0]);
                            acc[i][1] = fmaf(a[i], bb1, acc[i][1]);
                        }
                    }
                    __syncthreads();
                }
                int tx = tid & 15, ty = tid >> 4;
#pragma unroll
                for (int i = 0; i < 4; i++)
#pragma unroll
                    for (int j = 0; j < 2; j++) {
                        int row = km0 + ty * 4 + i, col = kn0 + tx * 2 + j;
                        float v = acc[i][j] + b_key[col];
                        d_Mk[((size_t)row * MD + t) * KD + col] = v > 0.f ? v : 0.f;
                    }
            } else {  // gate g + attention read -> key_r (bf16 hi/lo)
                int bb = (bx - 64) * 8 + wid;
                const float* hb = d_xin + (size_t)bb * KIN + OFFH;
                float s = 0.f;
                for (int l = lane; l < HD; l += 32) s += hb[l] * W_g[l];
#pragma unroll
                for (int o = 16; o; o >>= 1) s += __shfl_xor_sync(0xffffffffu, s, o);
                float gv = sigm(s + b_g[0]);
                const float* wkb = d_wk + bb * MD;
                const float* ckb = d_ck + bb * MD;
                const float* mkb = d_Mk + (size_t)bb * MD * KD;
                for (int d = lane; d < 257; d += 32) {
                    float a = 0.f;
                    if (d < 256) { for (int m = 0; m < t; m++) a += wkb[m] * mkb[m * KD + d]; }
                    else         { for (int m = 0; m < t; m++) a += wkb[m] * ckb[m]; }
                    float v = gv * a;  // zero at t==0 (empty sum)
                    __nv_bfloat16 vh = __float2bfloat16_rn(v);
                    d_Ahi[(size_t)bb * KIN + d] = vh;
                    d_Alo[(size_t)bb * KIN + d] =
                        __float2bfloat16_rn(v - __bfloat162float(vh));
                }
            }
            gridBarrier();
        } else {  // t == 32: y_lin + argmax, write outputs
            if (bx >= 64) {
                int bb = (bx - 64) * 8 + wid;
                const float* hb = d_xin + (size_t)bb * KIN + OFFH;
                float yv[4];
#pragma unroll
                for (int yi = 0; yi < YD; yi++) {
                    float s = 0.f;
                    for (int l = lane; l < HD; l += 32) s += hb[l] * W_y[yi * HD + l];
#pragma unroll
                    for (int o = 16; o; o >>= 1) s += __shfl_xor_sync(0xffffffffu, s, o);
                    yv[yi] = s + b_y[yi];
                }
                if (lane == 0) {
                    int am = 0; float bst = yv[0];
#pragma unroll
                    for (int yi = 1; yi < YD; yi++)
                        if (yv[yi] > bst) { bst = yv[yi]; am = yi; }
                    if (out_size >= BD * YD) {
                        float* of = (float*)outp;
                        of[bb * 4 + 0] = yv[0];
                        of[bb * 4 + 1] = yv[1];
                        of[bb * 4 + 2] = yv[2];
                        of[bb * 4 + 3] = yv[3];
                        if (out_size >= BD * YD + BD) of[BD * YD + bb] = (float)am;
                    } else {
                        ((int*)outp)[bb] = am;
                    }
                }
            }
        }
    }
}

// ------------------------------- launcher ----------------------------------
extern "C" void kernel_launch(void* const* d_in, const int* in_sizes, int n_in,
                              void* d_out, int out_size)
{
    const float* x_seq  = (const float*)d_in[0];
    const float* W_enc  = (const float*)d_in[1];
    const float* gamma  = (const float*)d_in[2];
    const float* beta   = (const float*)d_in[3];
    const float* W_ih   = (const float*)d_in[4];
    const float* W_hh   = (const float*)d_in[5];
    const float* b_ih   = (const float*)d_in[6];
    const float* b_hh   = (const float*)d_in[7];
    const float* W_key  = (const float*)d_in[8];
    const float* b_key  = (const float*)d_in[9];
    const float* W_g    = (const float*)d_in[10];
    const float* b_g    = (const float*)d_in[11];
    const float* cgain  = (const float*)d_in[12];
    const float* cbias  = (const float*)d_in[13];
    const float* W_y    = (const float*)d_in[14];
    const float* b_y    = (const float*)d_in[15];

    prep_kernel<<<1024, NT>>>(W_ih, W_hh, b_ih, b_hh, W_key);
    enc_gemm<<<256, NT>>>(x_seq, W_enc);
    ctx_norm<<<BD, 128>>>(gamma, beta);
    recur<<<NB, NT>>>(b_key, W_g, b_g, cgain, cbias, W_y, b_y, d_out, out_size);
}

// round 4
// speedup vs baseline: 1.7489x; 1.0800x over previous
#include <cuda_runtime.h>
#include <cuda_bf16.h>
#include <math.h>

// ---------------------------------------------------------------------------
// Model_24730421690434: encoder GEMM -> context norm -> 33-step memory-LSTM
//   B=512, T=32, Z=128, K=256, H=512, 4H=2048, Y=4, M=33
// R3: fragment-direct tensor GEMM (no smem/syncs in mainloop), LSTM cell fused
//     into GEMM epilogue via gate-interleaved weight layout, 2 barriers/step.
// ---------------------------------------------------------------------------

#define NB 128
#define NT 256

#define BD 512
#define TD 32
#define ZD 128
#define KD 256
#define HD 512
#define YD 4
#define MD 33
#define G4 2048
#define KCH 49      // 784/16 total k-chunks
#define KC_K 17     // chunks 0..16  : key_r (k=0..256) + pad
#define KC_H 32     // chunks 17..48 : h (k=272..783)

// ------------------------------- device state ------------------------------
// Weight fragments, gate-interleaved col' = j*4 + gate, layout:
//   word[(n8*49 + c)*64 + lane*2 + w]  (n8 = col'>>3)
__device__ __align__(256) unsigned d_BfH[256 * 49 * 64];
__device__ __align__(256) unsigned d_BfL[256 * 49 * 64];
// Activation fragments: word[(m16*NCH + c)*128 + lane*4 + w]
__device__ __align__(256) unsigned d_AKh[32 * KC_K * 128];      // key_r, single buf
__device__ __align__(256) unsigned d_AKl[32 * KC_K * 128];
__device__ __align__(256) unsigned d_AHh[2][32 * KC_H * 128];   // h, double buf
__device__ __align__(256) unsigned d_AHl[2][32 * KC_H * 128];

__device__ __align__(256) float d_biasg[G4];           // gate-interleaved bias
__device__ __align__(256) float d_WkT[HD * KD];
__device__ __align__(256) float d_zbuf[BD * TD * ZD];  // normalized z (== M_v)
__device__ __align__(256) float d_h[BD * HD];          // fp32 h
__device__ __align__(256) float d_cst[BD * HD];        // LSTM cell state
__device__ __align__(256) float d_Mk[(size_t)BD * MD * KD];
__device__ __align__(256) float d_wk[BD * MD];
__device__ __align__(256) float d_ck[BD * MD];
__device__ unsigned g_cnt;
__device__ unsigned g_gen;

__device__ __forceinline__ float sigm(float x) {
    x = fminf(fmaxf(x, -30.f), 30.f);
    return __fdividef(1.f, 1.f + __expf(-x));
}
__device__ __forceinline__ float tanh_(float x) {
    float xc = fminf(fmaxf(x, -15.f), 15.f);
    float e = __expf(-2.f * xc);
    return __fdividef(1.f - e, 1.f + e);
}

__device__ __forceinline__ void gridBarrier() {
    __syncthreads();
    if (threadIdx.x == 0) {
        unsigned gen = *(volatile unsigned*)&g_gen;
        __threadfence();
        unsigned t = atomicAdd(&g_cnt, 1u);
        if (t == NB - 1u) {
            g_cnt = 0u;
            __threadfence();
            atomicAdd(&g_gen, 1u);
        } else {
            while (*(volatile unsigned*)&g_gen == gen) { __nanosleep(64); }
        }
        __threadfence();
    }
    __syncthreads();
}

__device__ __forceinline__ void mma16816(float* d, const unsigned* a, const unsigned* b) {
    asm volatile(
        "mma.sync.aligned.m16n8k16.row.col.f32.bf16.bf16.f32 "
        "{%0,%1,%2,%3},{%4,%5,%6,%7},{%8,%9},{%0,%1,%2,%3};"
        : "+f"(d[0]), "+f"(d[1]), "+f"(d[2]), "+f"(d[3])
        : "r"(a[0]), "r"(a[1]), "r"(a[2]), "r"(a[3]), "r"(b[0]), "r"(b[1]));
}

__device__ __forceinline__ unsigned packbf2(float v0, float v1) {
    unsigned short u0 = __bfloat16_as_ushort(__float2bfloat16_rn(v0));
    unsigned short u1 = __bfloat16_as_ushort(__float2bfloat16_rn(v1));
    return (unsigned)u1 << 16 | u0;
}

// ------------------- 64x128 fp32 tile GEMM (encoder only) ------------------
__device__ __forceinline__ void mm64x128(const float* __restrict__ A, int lda,
                                         const float* __restrict__ B, int ldb,
                                         int m0, int n0, int Kt,
                                         float (&acc)[4][8], float* As, float* Bs)
{
    const int tid = threadIdx.x;
    const int tx = tid & 15, ty = tid >> 4;
#pragma unroll
    for (int i = 0; i < 4; i++)
#pragma unroll
        for (int j = 0; j < 8; j++) acc[i][j] = 0.f;

    for (int k0 = 0; k0 < Kt; k0 += 16) {
        {
            int r = tid >> 2, q = tid & 3;
            float4 av = *(const float4*)(A + (size_t)(m0 + r) * lda + k0 + q * 4);
            As[(q * 4 + 0) * 64 + r] = av.x;
            As[(q * 4 + 1) * 64 + r] = av.y;
            As[(q * 4 + 2) * 64 + r] = av.z;
            As[(q * 4 + 3) * 64 + r] = av.w;
        }
#pragma unroll
        for (int jj = 0; jj < 2; jj++) {
            int idx = tid + jj * 256;
            int kk = idx >> 5, qq = idx & 31;
            *(float4*)(Bs + kk * 128 + qq * 4) =
                *(const float4*)(B + (size_t)(k0 + kk) * ldb + n0 + qq * 4);
        }
        __syncthreads();
#pragma unroll
        for (int kk = 0; kk < 16; kk++) {
            float a[4];
#pragma unroll
            for (int i = 0; i < 4; i++) a[i] = As[kk * 64 + ty * 4 + i];
            float4 b0 = *(const float4*)(Bs + kk * 128 + tx * 8);
            float4 b1 = *(const float4*)(Bs + kk * 128 + tx * 8 + 4);
            float bb[8] = {b0.x, b0.y, b0.z, b0.w, b1.x, b1.y, b1.z, b1.w};
#pragma unroll
            for (int i = 0; i < 4; i++)
#pragma unroll
                for (int j = 0; j < 8; j++) acc[i][j] = fmaf(a[i], bb[j], acc[i][j]);
        }
        __syncthreads();
    }
}

// ------------------------------- prep kernel -------------------------------
__device__ __forceinline__ float fetchW(const float* W_ih, const float* W_hh,
                                        int n, int k) {
    if (k < 257) return W_ih[n * 257 + k];
    if (k >= 272 && k < 784) return W_hh[n * HD + (k - 272)];
    return 0.f;
}

__global__ void __launch_bounds__(NT) prep_kernel(
    const float* __restrict__ W_ih, const float* __restrict__ W_hh,
    const float* __restrict__ b_ih, const float* __restrict__ b_hh,
    const float* __restrict__ W_key)
{
    const int stride = gridDim.x * blockDim.x;
    const int gtid = blockIdx.x * blockDim.x + threadIdx.x;

    // weight fragments (gate-interleaved columns)
    for (int idx = gtid; idx < 256 * 49 * 64; idx += stride) {
        int n8 = idx / (49 * 64);
        int rem = idx - n8 * (49 * 64);
        int c = rem >> 6;
        int lw = rem & 63;
        int lane = lw >> 1, w = lw & 1;
        int lr = lane >> 2, lc = lane & 3;
        int np = n8 * 8 + lr;            // col'
        int g = np & 3, j = np >> 2;
        int orig = g * 512 + j;
        int k = c * 16 + w * 8 + lc * 2;
        float v0 = fetchW(W_ih, W_hh, orig, k);
        float v1 = fetchW(W_ih, W_hh, orig, k + 1);
        __nv_bfloat16 h0 = __float2bfloat16_rn(v0);
        __nv_bfloat16 h1 = __float2bfloat16_rn(v1);
        d_BfH[idx] = (unsigned)__bfloat16_as_ushort(h1) << 16 | __bfloat16_as_ushort(h0);
        d_BfL[idx] = packbf2(v0 - __bfloat162float(h0), v1 - __bfloat162float(h1));
    }
    // W_key transpose
    for (int idx = gtid; idx < HD * KD; idx += stride) {
        int kk = idx >> 8, nn = idx & 255;
        d_WkT[idx] = W_key[nn * HD + kk];
    }
    // bias (gate-interleaved)
    for (int np = gtid; np < G4; np += stride) {
        int orig = (np & 3) * 512 + (np >> 2);
        d_biasg[np] = b_ih[orig] + b_hh[orig];
    }
    // zero activation fragments + cell state
    for (int idx = gtid; idx < 32 * KC_K * 128; idx += stride) {
        d_AKh[idx] = 0u; d_AKl[idx] = 0u;
    }
    for (int idx = gtid; idx < 32 * KC_H * 128; idx += stride) {
        d_AHh[0][idx] = 0u; d_AHl[0][idx] = 0u;
        d_AHh[1][idx] = 0u; d_AHl[1][idx] = 0u;
    }
    for (int idx = gtid; idx < BD * HD; idx += stride) d_cst[idx] = 0.f;
}

// ------------------------------ encoder GEMM -------------------------------
__global__ void __launch_bounds__(NT) enc_gemm(const float* __restrict__ X,
                                               const float* __restrict__ W)
{
    __shared__ float As[16 * 64];
    __shared__ float Bs[16 * 128];
    int m0 = blockIdx.x * 64;
    float acc[4][8];
    mm64x128(X, 1024, W, 128, m0, 0, 1024, acc, As, Bs);
    int tx = threadIdx.x & 15, ty = threadIdx.x >> 4;
#pragma unroll
    for (int i = 0; i < 4; i++)
#pragma unroll
        for (int j = 0; j < 8; j++)
            d_zbuf[(size_t)(m0 + ty * 4 + i) * ZD + tx * 8 + j] = acc[i][j];
}

// ------------------------------ context norm -------------------------------
__global__ void __launch_bounds__(128) ctx_norm(const float* __restrict__ gamma,
                                                const float* __restrict__ beta)
{
    int b = blockIdx.x, z = threadIdx.x;
    float v[TD];
    float s = 0.f;
#pragma unroll
    for (int t = 0; t < TD; t++) { v[t] = d_zbuf[((b * TD) + t) * ZD + z]; s += v[t]; }
    float mu = s * (1.f / TD);
    float q = 0.f;
#pragma unroll
    for (int t = 0; t < TD; t++) { float d = v[t] - mu; q += d * d; }
    float inv = rsqrtf(q * (1.f / TD) + 1e-8f);
    float ga = gamma[z], be = beta[z];
#pragma unroll
    for (int t = 0; t < TD; t++)
        d_zbuf[((b * TD) + t) * ZD + z] = (v[t] - mu) * inv * ga + be;
}

// ------------------------- persistent recurrence ---------------------------
__global__ void __launch_bounds__(NT) recur(
    const float* __restrict__ b_key, const float* __restrict__ W_g,
    const float* __restrict__ b_g,   const float* __restrict__ cgain,
    const float* __restrict__ cbias, const float* __restrict__ W_y,
    const float* __restrict__ b_y,   void* outp, int out_size)
{
    __shared__ float As[16 * 64];
    __shared__ float Bs[16 * 32];
    __shared__ float s_sc[256];

    const int tid = threadIdx.x;
    const int bx = blockIdx.x;
    const int lane = tid & 31, wid = tid >> 5;
    const int lr = lane >> 2, lc = lane & 3;
    const int wm = wid & 1, wn = wid >> 1;

    const int m16b = (bx >> 4) * 4 + wm * 2;   // i adds 0/1 -> m16 in [0,32)
    const int n8b  = (bx & 15) * 16 + wn * 4;  // j adds 0..3 -> n8 in [0,256)

    // fragment base pointers (lane folded in)
    const unsigned* pBH = d_BfH + (size_t)n8b * (49 * 64) + lane * 2;
    const unsigned* pBL = d_BfL + (size_t)n8b * (49 * 64) + lane * 2;
    const unsigned* pKH = d_AKh + (size_t)m16b * (KC_K * 128) + lane * 4;
    const unsigned* pKL = d_AKl + (size_t)m16b * (KC_K * 128) + lane * 4;

    // hoisted gate biases: per jj, cols 4*jq .. 4*jq+3
    float4 bias4[4];
#pragma unroll
    for (int jj = 0; jj < 4; jj++) {
        int jq = (n8b + jj) * 2 + (lc >> 1);
        bias4[jj] = *(const float4*)(d_biasg + jq * 4);
    }

    for (int t = 0; t < MD; t++) {
        // ============ Phase A: gate GEMM (frag-direct) + fused LSTM cell ====
        {
            const unsigned* pHH = d_AHh[t & 1] + (size_t)m16b * (KC_H * 128) + lane * 4;
            const unsigned* pHL = d_AHl[t & 1] + (size_t)m16b * (KC_H * 128) + lane * 4;

            float acc[2][4][4];
#pragma unroll
            for (int i = 0; i < 2; i++)
#pragma unroll
                for (int j = 0; j < 4; j++)
#pragma unroll
                    for (int r = 0; r < 4; r++) acc[i][j][r] = 0.f;

            // ---- key_r region: chunks 0..16 ----
#pragma unroll 1
            for (int c = 0; c < KC_K; c++) {
                unsigned aH0[4], aH1[4], aL0[4], aL1[4];
                *(uint4*)aH0 = *(const uint4*)(pKH + c * 128);
                *(uint4*)aH1 = *(const uint4*)(pKH + KC_K * 128 + c * 128);
                *(uint4*)aL0 = *(const uint4*)(pKL + c * 128);
                *(uint4*)aL1 = *(const uint4*)(pKL + KC_K * 128 + c * 128);
                unsigned bH[4][2], bL[4][2];
#pragma unroll
                for (int j = 0; j < 4; j++) {
                    *(uint2*)bH[j] = *(const uint2*)(pBH + j * (49 * 64) + c * 64);
                    *(uint2*)bL[j] = *(const uint2*)(pBL + j * (49 * 64) + c * 64);
                }
#pragma unroll
                for (int j = 0; j < 4; j++) {
                    mma16816(acc[0][j], aH0, bH[j]);
                    mma16816(acc[1][j], aH1, bH[j]);
                    mma16816(acc[0][j], aH0, bL[j]);
                    mma16816(acc[1][j], aH1, bL[j]);
                    mma16816(acc[0][j], aL0, bH[j]);
                    mma16816(acc[1][j], aL1, bH[j]);
                }
            }
            // ---- h region: chunks 17..48 ----
#pragma unroll 1
            for (int c = 0; c < KC_H; c++) {
                unsigned aH0[4], aH1[4], aL0[4], aL1[4];
                *(uint4*)aH0 = *(const uint4*)(pHH + c * 128);
                *(uint4*)aH1 = *(const uint4*)(pHH + KC_H * 128 + c * 128);
                *(uint4*)aL0 = *(const uint4*)(pHL + c * 128);
                *(uint4*)aL1 = *(const uint4*)(pHL + KC_H * 128 + c * 128);
                unsigned bH[4][2], bL[4][2];
#pragma unroll
                for (int j = 0; j < 4; j++) {
                    *(uint2*)bH[j] = *(const uint2*)(pBH + j * (49 * 64) + (KC_K + c) * 64);
                    *(uint2*)bL[j] = *(const uint2*)(pBL + j * (49 * 64) + (KC_K + c) * 64);
                }
#pragma unroll
                for (int j = 0; j < 4; j++) {
                    mma16816(acc[0][j], aH0, bH[j]);
                    mma16816(acc[1][j], aH1, bH[j]);
                    mma16816(acc[0][j], aH0, bL[j]);
                    mma16816(acc[1][j], aH1, bL[j]);
                    mma16816(acc[0][j], aL0, bH[j]);
                    mma16816(acc[1][j], aL1, bH[j]);
                }
            }

            // ---- fused epilogue: gate nonlinearity + cell update ----
            const bool odd = (lc & 1);
            const int pn = (t + 1) & 1;
            unsigned* hfH = (unsigned*)d_AHh[pn];
            unsigned* hfL = (unsigned*)d_AHl[pn];
#pragma unroll
            for (int i = 0; i < 2; i++)
#pragma unroll
                for (int jj = 0; jj < 4; jj++) {
                    float a0 = acc[i][jj][0], a1 = acc[i][jj][1];
                    float a2 = acc[i][jj][2], a3 = acc[i][jj][3];
                    float p0 = __shfl_xor_sync(0xffffffffu, odd ? a0 : a2, 1);
                    float p1 = __shfl_xor_sync(0xffffffffu, odd ? a1 : a3, 1);
                    float4 bb4 = bias4[jj];
                    float gi, gf, gg, go;
                    if (!odd) { gi = a0 + bb4.x; gf = a1 + bb4.y; gg = p0 + bb4.z; go = p1 + bb4.w; }
                    else      { gi = p0 + bb4.x; gf = p1 + bb4.y; gg = a2 + bb4.z; go = a3 + bb4.w; }
                    int jq = (n8b + jj) * 2 + (lc >> 1);
                    int row = (m16b + i) * 16 + lr + (odd ? 8 : 0);
                    int e = row * HD + jq;
                    float cold = d_cst[e];
                    float cn = sigm(gf) * cold + sigm(gi) * tanh_(gg);
                    d_cst[e] = cn;
                    float hv = sigm(go) * tanh_(cn);
                    d_h[e] = hv;
                    // fragment store (hi/lo bf16), double-buffered by parity
                    __nv_bfloat16 hh = __float2bfloat16_rn(hv);
                    __nv_bfloat16 hl = __float2bfloat16_rn(hv - __bfloat162float(hh));
                    int m16 = row >> 4, r = row & 15;
                    int ch = jq >> 4, kk = jq & 15;
                    int lane_a = (r & 7) * 4 + ((kk & 7) >> 1);
                    int w = (r >> 3) + ((kk >> 3) << 1);
                    size_t widx = ((size_t)(m16 * KC_H + ch)) * 128 + lane_a * 4 + w;
                    ((__nv_bfloat16*)hfH)[widx * 2 + (kk & 1)] = hh;
                    ((__nv_bfloat16*)hfL)[widx * 2 + (kk & 1)] = hl;
                }
        }

        // ---- attention scores + softmax + confidence (parallel side-task) ----
        if (t >= 1 && t < TD) {
            int bb = bx * 4 + (tid >> 6);
            int m = tid & 63;
            float s = 0.f;
            if (m < t) {
                const float* zt = d_zbuf + (size_t)(bb * TD + t) * ZD;
                const float* zm = d_zbuf + (size_t)(bb * TD + m) * ZD;
#pragma unroll 4
                for (int i = 0; i < ZD; i++) s += zt[i] * zm[i];
                d_ck[bb * MD + m] = sigm(s * cgain[0] + cbias[0]);
            }
            s_sc[tid] = s;
            __syncthreads();
            if (m == 0) {
                float mx = -3.4e38f;
                for (int mm = 0; mm < t; mm++) mx = fmaxf(mx, s_sc[tid + mm]);
                float sum = 0.f;
                for (int mm = 0; mm < t; mm++) {
                    float e = __expf(s_sc[tid + mm] - mx);
                    d_wk[bb * MD + mm] = e;
                    sum += e;
                }
                float inv = __fdividef(1.f, sum);
                for (int mm = 0; mm < t; mm++) d_wk[bb * MD + mm] *= inv;
            }
        }
        gridBarrier();  // barrier 1: h, wk, ck visible everywhere

        // ============ Phase C: key_w GEMM | attention read | output =========
        if (t < TD) {
            if (bx < 64) {  // key_w = relu(h @ W_key^T + b_key) -> M_k[:,t,:]
                int km0 = (bx >> 3) * 64, kn0 = (bx & 7) * 32;
                float acc[4][2];
#pragma unroll
                for (int i = 0; i < 4; i++) { acc[i][0] = 0.f; acc[i][1] = 0.f; }
                for (int k0 = 0; k0 < HD; k0 += 16) {
                    int r = tid >> 2, q = tid & 3;
                    float4 av = *(const float4*)(d_h + (size_t)(km0 + r) * HD + k0 + q * 4);
                    As[(q * 4 + 0) * 64 + r] = av.x;
                    As[(q * 4 + 1) * 64 + r] = av.y;
                    As[(q * 4 + 2) * 64 + r] = av.z;
                    As[(q * 4 + 3) * 64 + r] = av.w;
                    if (tid < 128) {
                        int kk = tid >> 3, qq = tid & 7;
                        *(float4*)(Bs + kk * 32 + qq * 4) =
                            *(const float4*)(d_WkT + (size_t)(k0 + kk) * KD + kn0 + qq * 4);
                    }
                    __syncthreads();
#pragma unroll
                    for (int kk = 0; kk < 16; kk++) {
                        float a[4];
#pragma unroll
                        for (int i = 0; i < 4; i++) a[i] = As[kk * 64 + (tid >> 4) * 4 + i];
                        float bb0 = Bs[kk * 32 + (tid & 15) * 2];
                        float bb1 = Bs[kk * 32 + (tid & 15) * 2 + 1];
#pragma unroll
                        for (int i = 0; i < 4; i++) {
                            acc[i][0] = fmaf(a[i], bb0, acc[i][0]);
                            acc[i][1] = fmaf(a[i], bb1, acc[i][1]);
                        }
                    }
                    __syncthreads();
                }
                int tx = tid & 15, ty = tid >> 4;
#pragma unroll
                for (int i = 0; i < 4; i++)
#pragma unroll
                    for (int j = 0; j < 2; j++) {
                        int row = km0 + ty * 4 + i, col = kn0 + tx * 2 + j;
                        float v = acc[i][j] + b_key[col];
                        d_Mk[((size_t)row * MD + t) * KD + col] = v > 0.f ? v : 0.f;
                    }
            } else {  // gate g + attention read -> key_r fragments
                int bb = (bx - 64) * 8 + wid;
                const float* hb = d_h + (size_t)bb * HD;
                float s = 0.f;
                for (int l = lane; l < HD; l += 32) s += hb[l] * W_g[l];
#pragma unroll
                for (int o = 16; o; o >>= 1) s += __shfl_xor_sync(0xffffffffu, s, o);
                float gv = sigm(s + b_g[0]);
                const float* wkb = d_wk + bb * MD;
                const float* ckb = d_ck + bb * MD;
                const float* mkb = d_Mk + (size_t)bb * MD * KD;
                int m16 = bb >> 4, r = bb & 15;
                for (int dp = lane; dp < 129; dp += 32) {
                    int d0 = dp * 2;
                    float v0 = 0.f, v1 = 0.f;
                    if (d0 < 256) {
                        for (int m = 0; m < t; m++) {
                            float w = wkb[m];
                            v0 += w * mkb[m * KD + d0];
                            v1 += w * mkb[m * KD + d0 + 1];
                        }
                    } else {
                        for (int m = 0; m < t; m++) v0 += wkb[m] * ckb[m];
                    }
                    v0 *= gv; v1 *= gv;
                    __nv_bfloat16 h0 = __float2bfloat16_rn(v0);
                    __nv_bfloat16 h1 = __float2bfloat16_rn(v1);
                    int ch = d0 >> 4, kk = d0 & 15;
                    int lane_a = (r & 7) * 4 + ((kk & 7) >> 1);
                    int w = (r >> 3) + ((kk >> 3) << 1);
                    size_t widx = ((size_t)(m16 * KC_K + ch)) * 128 + lane_a * 4 + w;
                    d_AKh[widx] = (unsigned)__bfloat16_as_ushort(h1) << 16 |
                                  __bfloat16_as_ushort(h0);
                    d_AKl[widx] = packbf2(v0 - __bfloat162float(h0),
                                          v1 - __bfloat162float(h1));
                }
            }
            gridBarrier();  // barrier 2: key_r, M_k visible for next step
        } else {  // t == 32: y_lin + argmax, write outputs
            if (bx >= 64) {
                int bb = (bx - 64) * 8 + wid;
                const float* hb = d_h + (size_t)bb * HD;
                float yv[4];
#pragma unroll
                for (int yi = 0; yi < YD; yi++) {
                    float s = 0.f;
                    for (int l = lane; l < HD; l += 32) s += hb[l] * W_y[yi * HD + l];
#pragma unroll
                    for (int o = 16; o; o >>= 1) s += __shfl_xor_sync(0xffffffffu, s, o);
                    yv[yi] = s + b_y[yi];
                }
                if (lane == 0) {
                    int am = 0; float bst = yv[0];
#pragma unroll
                    for (int yi = 1; yi < YD; yi++)
                        if (yv[yi] > bst) { bst = yv[yi]; am = yi; }
                    if (out_size >= BD * YD) {
                        float* of = (float*)outp;
                        of[bb * 4 + 0] = yv[0];
                        of[bb * 4 + 1] = yv[1];
                        of[bb * 4 + 2] = yv[2];
                        of[bb * 4 + 3] = yv[3];
                        if (out_size >= BD * YD + BD) of[BD * YD + bb] = (float)am;
                    } else {
                        ((int*)outp)[bb] = am;
                    }
                }
            }
        }
    }
}

// ------------------------------- launcher ----------------------------------
extern "C" void kernel_launch(void* const* d_in, const int* in_sizes, int n_in,
                              void* d_out, int out_size)
{
    const float* x_seq  = (const float*)d_in[0];
    const float* W_enc  = (const float*)d_in[1];
    const float* gamma  = (const float*)d_in[2];
    const float* beta   = (const float*)d_in[3];
    const float* W_ih   = (const float*)d_in[4];
    const float* W_hh   = (const float*)d_in[5];
    const float* b_ih   = (const float*)d_in[6];
    const float* b_hh   = (const float*)d_in[7];
    const float* W_key  = (const float*)d_in[8];
    const float* b_key  = (const float*)d_in[9];
    const float* W_g    = (const float*)d_in[10];
    const float* b_g    = (const float*)d_in[11];
    const float* cgain  = (const float*)d_in[12];
    const float* cbias  = (const float*)d_in[13];
    const float* W_y    = (const float*)d_in[14];
    const float* b_y    = (const float*)d_in[15];

    prep_kernel<<<1024, NT>>>(W_ih, W_hh, b_ih, b_hh, W_key);
    enc_gemm<<<256, NT>>>(x_seq, W_enc);
    ctx_norm<<<BD, 128>>>(gamma, beta);
    recur<<<NB, NT>>>(b_key, W_g, b_g, cgain, cbias, W_y, b_y, d_out, out_size);
}

// round 5
// speedup vs baseline: 2.4218x; 1.3847x over previous
#include <cuda_runtime.h>
#include <cuda_bf16.h>
#include <math.h>

// ---------------------------------------------------------------------------
// Model_24730421690434  (R4)
//   B=512, T=32, Z=128, K=256, H=512, 4H=2048, Y=4, M=33
// R4: smem-staged 3-stage cp.async gate GEMM (16 warps), cell state in regs,
//     tanh.approx transcendentals, tensor-core key_w GEMM, 2 barriers/step.
// ---------------------------------------------------------------------------

#define NB 128
#define NT 512

#define BD 512
#define TD 32
#define ZD 128
#define KD 256
#define HD 512
#define YD 4
#define MD 33
#define G4 2048
#define NCH 49      // 784/16 chunks: 0..16 key_r(+conf+pad), 17..48 h

// ------------------------------- device state ------------------------------
// Weight fragments (gate-interleaved col' = jcol*4+gate):
//   word[(n8*49 + c)*64 + lane*2 + w]
__device__ __align__(256) unsigned d_BfH[256 * 49 * 64];
__device__ __align__(256) unsigned d_BfL[256 * 49 * 64];
// W_key fragments: word[(n8*32 + c)*64 + lane*2 + w], n8<32, c<32
__device__ __align__(256) unsigned d_WKfH[32 * 32 * 64];
__device__ __align__(256) unsigned d_WKfL[32 * 32 * 64];
// Activation fragments (unified key_r+h), double-buffered by step parity:
//   word[(m16*49 + c)*128 + lane_a*4 + w]
__device__ __align__(256) unsigned d_AfH[2][32 * 49 * 128];
__device__ __align__(256) unsigned d_AfL[2][32 * 49 * 128];

__device__ __align__(256) float d_biasg[G4];           // gate-interleaved
__device__ __align__(256) float d_zbuf[BD * TD * ZD];  // normalized z (== M_v)
__device__ __align__(256) float d_h[BD * HD];          // fp32 h
__device__ __align__(256) float d_Mk[(size_t)BD * MD * KD];
__device__ __align__(256) float d_wk[BD * MD];
__device__ __align__(256) float d_ck[BD * MD];
__device__ unsigned g_cnt;
__device__ unsigned g_gen;

__device__ __forceinline__ float tanhap(float x) {
    float y; asm("tanh.approx.f32 %0, %1;" : "=f"(y) : "f"(x)); return y;
}
__device__ __forceinline__ float sigm(float x) {
    return fmaf(tanhap(x * 0.5f), 0.5f, 0.5f);
}

__device__ __forceinline__ void gridBarrier() {
    __syncthreads();
    if (threadIdx.x == 0) {
        unsigned gen = *(volatile unsigned*)&g_gen;
        __threadfence();
        unsigned t = atomicAdd(&g_cnt, 1u);
        if (t == NB - 1u) {
            g_cnt = 0u;
            __threadfence();
            atomicAdd(&g_gen, 1u);
        } else {
            while (*(volatile unsigned*)&g_gen == gen) { __nanosleep(32); }
        }
        __threadfence();
    }
    __syncthreads();
}

__device__ __forceinline__ void cpasync16(void* dst, const void* src) {
    unsigned saddr = (unsigned)__cvta_generic_to_shared(dst);
    asm volatile("cp.async.cg.shared.global [%0], [%1], 16;\n" ::"r"(saddr), "l"(src));
}
#define CPCOMMIT() asm volatile("cp.async.commit_group;\n" ::)
#define CPWAIT(n)  asm volatile("cp.async.wait_group %0;\n" ::"n"(n))

__device__ __forceinline__ void mma16816(float* d, const unsigned* a, const unsigned* b) {
    asm volatile(
        "mma.sync.aligned.m16n8k16.row.col.f32.bf16.bf16.f32 "
        "{%0,%1,%2,%3},{%4,%5,%6,%7},{%8,%9},{%0,%1,%2,%3};"
        : "+f"(d[0]), "+f"(d[1]), "+f"(d[2]), "+f"(d[3])
        : "r"(a[0]), "r"(a[1]), "r"(a[2]), "r"(a[3]), "r"(b[0]), "r"(b[1]));
}

__device__ __forceinline__ unsigned packbf2(float v0, float v1) {
    unsigned short u0 = __bfloat16_as_ushort(__float2bfloat16_rn(v0));
    unsigned short u1 = __bfloat16_as_ushort(__float2bfloat16_rn(v1));
    return (unsigned)u1 << 16 | u0;
}

// ------------------- 64x128 fp32 tile GEMM (encoder only) ------------------
__device__ __forceinline__ void mm64x128(const float* __restrict__ A, int lda,
                                         const float* __restrict__ B, int ldb,
                                         int m0, int n0, int Kt,
                                         float (&acc)[4][8], float* As, float* Bs)
{
    const int tid = threadIdx.x;
    const int tx = tid & 15, ty = tid >> 4;
#pragma unroll
    for (int i = 0; i < 4; i++)
#pragma unroll
        for (int j = 0; j < 8; j++) acc[i][j] = 0.f;

    for (int k0 = 0; k0 < Kt; k0 += 16) {
        {
            int r = tid >> 2, q = tid & 3;
            float4 av = *(const float4*)(A + (size_t)(m0 + r) * lda + k0 + q * 4);
            As[(q * 4 + 0) * 64 + r] = av.x;
            As[(q * 4 + 1) * 64 + r] = av.y;
            As[(q * 4 + 2) * 64 + r] = av.z;
            As[(q * 4 + 3) * 64 + r] = av.w;
        }
#pragma unroll
        for (int jj = 0; jj < 2; jj++) {
            int idx = tid + jj * 256;
            int kk = idx >> 5, qq = idx & 31;
            *(float4*)(Bs + kk * 128 + qq * 4) =
                *(const float4*)(B + (size_t)(k0 + kk) * ldb + n0 + qq * 4);
        }
        __syncthreads();
#pragma unroll
        for (int kk = 0; kk < 16; kk++) {
            float a[4];
#pragma unroll
            for (int i = 0; i < 4; i++) a[i] = As[kk * 64 + ty * 4 + i];
            float4 b0 = *(const float4*)(Bs + kk * 128 + tx * 8);
            float4 b1 = *(const float4*)(Bs + kk * 128 + tx * 8 + 4);
            float bb[8] = {b0.x, b0.y, b0.z, b0.w, b1.x, b1.y, b1.z, b1.w};
#pragma unroll
            for (int i = 0; i < 4; i++)
#pragma unroll
                for (int j = 0; j < 8; j++) acc[i][j] = fmaf(a[i], bb[j], acc[i][j]);
        }
        __syncthreads();
    }
}

// ------------------------------- prep kernel -------------------------------
__device__ __forceinline__ float fetchW(const float* W_ih, const float* W_hh,
                                        int n, int k) {
    if (k < 257) return W_ih[n * 257 + k];
    if (k >= 272 && k < 784) return W_hh[n * HD + (k - 272)];
    return 0.f;
}

__global__ void __launch_bounds__(256) prep_kernel(
    const float* __restrict__ W_ih, const float* __restrict__ W_hh,
    const float* __restrict__ b_ih, const float* __restrict__ b_hh,
    const float* __restrict__ W_key)
{
    const int stride = gridDim.x * blockDim.x;
    const int gtid = blockIdx.x * blockDim.x + threadIdx.x;

    // gate weight fragments (gate-interleaved columns)
    for (int idx = gtid; idx < 256 * 49 * 64; idx += stride) {
        int n8 = idx / (49 * 64);
        int rem = idx - n8 * (49 * 64);
        int c = rem >> 6;
        int lw = rem & 63;
        int lane = lw >> 1, w = lw & 1;
        int lr = lane >> 2, lc = lane & 3;
        int np = n8 * 8 + lr;            // col'
        int g = np & 3, j = np >> 2;
        int orig = g * 512 + j;
        int k = c * 16 + w * 8 + lc * 2;
        float v0 = fetchW(W_ih, W_hh, orig, k);
        float v1 = fetchW(W_ih, W_hh, orig, k + 1);
        __nv_bfloat16 h0 = __float2bfloat16_rn(v0);
        __nv_bfloat16 h1 = __float2bfloat16_rn(v1);
        d_BfH[idx] = (unsigned)__bfloat16_as_ushort(h1) << 16 | __bfloat16_as_ushort(h0);
        d_BfL[idx] = packbf2(v0 - __bfloat162float(h0), v1 - __bfloat162float(h1));
    }
    // W_key fragments
    for (int idx = gtid; idx < 32 * 32 * 64; idx += stride) {
        int n8 = idx / (32 * 64);
        int rem = idx - n8 * (32 * 64);
        int c = rem >> 6;
        int lw = rem & 63;
        int lane = lw >> 1, w = lw & 1;
        int lr = lane >> 2, lc = lane & 3;
        int n = n8 * 8 + lr;
        int k = c * 16 + w * 8 + lc * 2;
        float v0 = W_key[n * HD + k];
        float v1 = W_key[n * HD + k + 1];
        __nv_bfloat16 h0 = __float2bfloat16_rn(v0);
        __nv_bfloat16 h1 = __float2bfloat16_rn(v1);
        d_WKfH[idx] = (unsigned)__bfloat16_as_ushort(h1) << 16 | __bfloat16_as_ushort(h0);
        d_WKfL[idx] = packbf2(v0 - __bfloat162float(h0), v1 - __bfloat162float(h1));
    }
    // bias (gate-interleaved)
    for (int np = gtid; np < G4; np += stride) {
        int orig = (np & 3) * 512 + (np >> 2);
        d_biasg[np] = b_ih[orig] + b_hh[orig];
    }
    // zero activation fragments (both parities, both planes)
    for (int idx = gtid; idx < 32 * 49 * 128; idx += stride) {
        d_AfH[0][idx] = 0u; d_AfL[0][idx] = 0u;
        d_AfH[1][idx] = 0u; d_AfL[1][idx] = 0u;
    }
}

// ------------------------------ encoder GEMM -------------------------------
__global__ void __launch_bounds__(256) enc_gemm(const float* __restrict__ X,
                                                const float* __restrict__ W)
{
    __shared__ float As[16 * 64];
    __shared__ float Bs[16 * 128];
    int m0 = blockIdx.x * 64;
    float acc[4][8];
    mm64x128(X, 1024, W, 128, m0, 0, 1024, acc, As, Bs);
    int tx = threadIdx.x & 15, ty = threadIdx.x >> 4;
#pragma unroll
    for (int i = 0; i < 4; i++)
#pragma unroll
        for (int j = 0; j < 8; j++)
            d_zbuf[(size_t)(m0 + ty * 4 + i) * ZD + tx * 8 + j] = acc[i][j];
}

// ------------------------------ context norm -------------------------------
__global__ void __launch_bounds__(128) ctx_norm(const float* __restrict__ gamma,
                                                const float* __restrict__ beta)
{
    int b = blockIdx.x, z = threadIdx.x;
    float v[TD];
    float s = 0.f;
#pragma unroll
    for (int t = 0; t < TD; t++) { v[t] = d_zbuf[((b * TD) + t) * ZD + z]; s += v[t]; }
    float mu = s * (1.f / TD);
    float q = 0.f;
#pragma unroll
    for (int t = 0; t < TD; t++) { float d = v[t] - mu; q += d * d; }
    float inv = rsqrtf(q * (1.f / TD) + 1e-8f);
    float ga = gamma[z], be = beta[z];
#pragma unroll
    for (int t = 0; t < TD; t++)
        d_zbuf[((b * TD) + t) * ZD + z] = (v[t] - mu) * inv * ga + be;
}

// ------------------------- persistent recurrence ---------------------------
__global__ void __launch_bounds__(NT) recur(
    const float* __restrict__ b_key, const float* __restrict__ W_g,
    const float* __restrict__ b_g,   const float* __restrict__ cgain,
    const float* __restrict__ cbias, const float* __restrict__ W_y,
    const float* __restrict__ b_y,   void* outp, int out_size)
{
    // stage = [A: 1024 words][B: 2048 words] = 12 KB; 3 stages
    __shared__ __align__(16) unsigned sStage[3][3072];
    __shared__ float s_sc[256];

    const int tid = threadIdx.x;
    const int bx = blockIdx.x;
    const int lane = tid & 31, wid = tid >> 5;
    const int lr = lane >> 2, lc = lane & 3;

    // ---- Phase A mapping: 8 m-blocks x 16 n-blocks; warp = 1 m16 x 4 n8 ----
    const int mblk = bx >> 4, nblk = bx & 15;
    const int wmm = wid & 3;                 // m16 local
    const int wn  = wid >> 2;                // n8 group (x4)
    const int m16g = mblk * 4 + wmm;

    // cp.async per-thread mapping
    const int a_plane = tid >> 7;            // valid for tid<256
    const int a_m16A  = mblk * 4 + ((tid >> 5) & 3);
    const int a_widx  = (tid & 31) * 4;
    const int a_soff  = a_plane * 512 + ((tid >> 5) & 3) * 128 + a_widx;
    const int b_n8B   = nblk * 16 + (tid >> 5);
    const int b_plane = (tid >> 4) & 1;
    const int b_widx  = (tid & 15) * 4;
    const int b_soff  = 1024 + (tid >> 5) * 128 + b_plane * 64 + b_widx;
    const unsigned* bSrc = (b_plane ? d_BfL : d_BfH) + (size_t)b_n8B * (49 * 64) + b_widx;

    // hoisted gate biases per jj
    float4 bias4[4];
#pragma unroll
    for (int jj = 0; jj < 4; jj++) {
        int n8g = nblk * 16 + wn * 4 + jj;
        int jq = n8g * 2 + (lc >> 1);
        bias4[jj] = *(const float4*)(d_biasg + jq * 4);
    }

    const bool odd = (lc & 1);
    float cc[4] = {0.f, 0.f, 0.f, 0.f};      // cell state in registers

    for (int t = 0; t < MD; t++) {
        const int cur = t & 1, pn = (t + 1) & 1;
        // ============ Phase A: gate GEMM (smem pipeline) + fused cell =======
        {
            const unsigned* aSrc = (a_plane ? d_AfL[cur] : d_AfH[cur]) +
                                   (size_t)a_m16A * (49 * 128) + a_widx;
            // prologue: stages 0,1 <- chunks 0,1
#pragma unroll
            for (int p = 0; p < 2; p++) {
                if (tid < 256) cpasync16(&sStage[p][a_soff], aSrc + p * 128);
                cpasync16(&sStage[p][b_soff], bSrc + p * 64);
                CPCOMMIT();
            }
            float acc[4][4];
#pragma unroll
            for (int j = 0; j < 4; j++)
#pragma unroll
                for (int r = 0; r < 4; r++) acc[j][r] = 0.f;

#pragma unroll 1
            for (int c = 0; c < NCH; c++) {
                CPWAIT(1);
                __syncthreads();
                const unsigned* base = sStage[c % 3];
                unsigned aH[4], aL[4], bH[4][2], bL[4][2];
                *(uint4*)aH = *(const uint4*)(base + wmm * 128 + lane * 4);
                *(uint4*)aL = *(const uint4*)(base + 512 + wmm * 128 + lane * 4);
#pragma unroll
                for (int jj = 0; jj < 4; jj++) {
                    const unsigned* bb = base + 1024 + (wn * 4 + jj) * 128 + lane * 2;
                    *(uint2*)bH[jj] = *(const uint2*)(bb);
                    *(uint2*)bL[jj] = *(const uint2*)(bb + 64);
                }
#pragma unroll
                for (int jj = 0; jj < 4; jj++) mma16816(acc[jj], aH, bH[jj]);
#pragma unroll
                for (int jj = 0; jj < 4; jj++) mma16816(acc[jj], aH, bL[jj]);
#pragma unroll
                for (int jj = 0; jj < 4; jj++) mma16816(acc[jj], aL, bH[jj]);
                // issue chunk c+2 into stage (c+2)%3
                if (c + 2 < NCH) {
                    int st = (c + 2) % 3;
                    if (tid < 256) cpasync16(&sStage[st][a_soff], aSrc + (c + 2) * 128);
                    cpasync16(&sStage[st][b_soff], bSrc + (c + 2) * 64);
                }
                CPCOMMIT();
            }

            // ---- fused epilogue: gates + cell update + h frag stores ----
            unsigned* hOutH = d_AfH[pn];
            unsigned* hOutL = d_AfL[pn];
#pragma unroll
            for (int jj = 0; jj < 4; jj++) {
                float a0 = acc[jj][0], a1 = acc[jj][1];
                float a2 = acc[jj][2], a3 = acc[jj][3];
                float p0 = __shfl_xor_sync(0xffffffffu, odd ? a0 : a2, 1);
                float p1 = __shfl_xor_sync(0xffffffffu, odd ? a1 : a3, 1);
                float4 bb4 = bias4[jj];
                float gi, gf, gg, go;
                if (!odd) { gi = a0 + bb4.x; gf = a1 + bb4.y; gg = p0 + bb4.z; go = p1 + bb4.w; }
                else      { gi = p0 + bb4.x; gf = p1 + bb4.y; gg = a2 + bb4.z; go = a3 + bb4.w; }
                float cn = sigm(gf) * cc[jj] + sigm(gi) * tanhap(gg);
                cc[jj] = cn;
                float hv = sigm(go) * tanhap(cn);
                int n8g = nblk * 16 + wn * 4 + jj;
                int jq = n8g * 2 + (lc >> 1);
                int row = m16g * 16 + lr + (odd ? 8 : 0);
                d_h[row * HD + jq] = hv;
                // combine word pair with lane^2 partner, low-kk lane stores
                __nv_bfloat16 hh = __float2bfloat16_rn(hv);
                __nv_bfloat16 hl = __float2bfloat16_rn(hv - __bfloat162float(hh));
                unsigned uh = (unsigned)__bfloat16_as_ushort(hh);
                unsigned ul = (unsigned)__bfloat16_as_ushort(hl);
                unsigned ph = __shfl_xor_sync(0xffffffffu, uh, 2);
                unsigned pl = __shfl_xor_sync(0xffffffffu, ul, 2);
                if ((lc & 2) == 0) {
                    int kk = jq & 15;
                    int ch = 17 + (jq >> 4);
                    int lane_a = lr * 4 + ((kk & 7) >> 1);
                    int w = (odd ? 1 : 0) + ((kk >> 3) << 1);
                    size_t widx = ((size_t)(m16g * 49 + ch)) * 128 + lane_a * 4 + w;
                    hOutH[widx] = (ph << 16) | uh;
                    hOutL[widx] = (pl << 16) | ul;
                }
            }
        }

        // ---- attention scores + softmax + confidence ----
        if (t >= 1 && t < TD) {
            int bb = bx * 4 + ((tid >> 6) & 3);
            int m = tid & 63;
            if (tid < 256) {
                float s = 0.f;
                if (m < t) {
                    const float* zt = d_zbuf + (size_t)(bb * TD + t) * ZD;
                    const float* zm = d_zbuf + (size_t)(bb * TD + m) * ZD;
#pragma unroll 4
                    for (int i = 0; i < ZD; i++) s += zt[i] * zm[i];
                    d_ck[bb * MD + m] = sigm(s * cgain[0] + cbias[0]);
                }
                s_sc[tid] = s;
            }
            __syncthreads();
            if (tid < 256 && m == 0) {
                float mx = -3.4e38f;
                for (int mm = 0; mm < t; mm++) mx = fmaxf(mx, s_sc[tid + mm]);
                float sum = 0.f;
                for (int mm = 0; mm < t; mm++) {
                    float e = __expf(s_sc[tid + mm] - mx);
                    d_wk[bb * MD + mm] = e;
                    sum += e;
                }
                float inv = __fdividef(1.f, sum);
                for (int mm = 0; mm < t; mm++) d_wk[bb * MD + mm] *= inv;
            }
        }
        gridBarrier();  // h, wk, ck visible everywhere

        // ============ Phase C ==============================================
        if (t < TD) {
            if (bx < 64) {  // key_w = relu(h @ W_key^T + b_key), tensor cores
                const int m16 = (bx >> 3) * 4 + (wid & 3);
                const int n8  = (bx & 7) * 4 + (wid >> 2);
                const unsigned* pAH = d_AfH[pn] + ((size_t)m16 * 49 + 17) * 128 + lane * 4;
                const unsigned* pAL = d_AfL[pn] + ((size_t)m16 * 49 + 17) * 128 + lane * 4;
                const unsigned* pWH = d_WKfH + (size_t)n8 * (32 * 64) + lane * 2;
                const unsigned* pWL = d_WKfL + (size_t)n8 * (32 * 64) + lane * 2;
                float kacc[4] = {0.f, 0.f, 0.f, 0.f};
                unsigned nAH[4], nAL[4], nBH[2], nBL[2];
                *(uint4*)nAH = *(const uint4*)(pAH);
                *(uint4*)nAL = *(const uint4*)(pAL);
                *(uint2*)nBH = *(const uint2*)(pWH);
                *(uint2*)nBL = *(const uint2*)(pWL);
#pragma unroll 1
                for (int ch = 0; ch < 32; ch++) {
                    unsigned cAH[4], cAL[4], cBH[2], cBL[2];
                    *(uint4*)cAH = *(uint4*)nAH; *(uint4*)cAL = *(uint4*)nAL;
                    *(uint2*)cBH = *(uint2*)nBH; *(uint2*)cBL = *(uint2*)nBL;
                    if (ch < 31) {
                        *(uint4*)nAH = *(const uint4*)(pAH + (ch + 1) * 128);
                        *(uint4*)nAL = *(const uint4*)(pAL + (ch + 1) * 128);
                        *(uint2*)nBH = *(const uint2*)(pWH + (ch + 1) * 64);
                        *(uint2*)nBL = *(const uint2*)(pWL + (ch + 1) * 64);
                    }
                    mma16816(kacc, cAH, cBH);
                    mma16816(kacc, cAH, cBL);
                    mma16816(kacc, cAL, cBH);
                }
                int col = n8 * 8 + lc * 2;
                float bk0 = b_key[col], bk1 = b_key[col + 1];
                int row0 = m16 * 16 + lr;
                float2 v0 = {fmaxf(kacc[0] + bk0, 0.f), fmaxf(kacc[1] + bk1, 0.f)};
                float2 v1 = {fmaxf(kacc[2] + bk0, 0.f), fmaxf(kacc[3] + bk1, 0.f)};
                *(float2*)(d_Mk + ((size_t)row0 * MD + t) * KD + col) = v0;
                *(float2*)(d_Mk + ((size_t)(row0 + 8) * MD + t) * KD + col) = v1;
            } else {  // gate g + attention read -> key_r fragments (parity pn)
                int bb = (bx - 64) * 8 + (wid & 7);
                const float* hb = d_h + (size_t)bb * HD;
                float s = 0.f;
                for (int l = lane; l < HD; l += 32) s += hb[l] * W_g[l];
#pragma unroll
                for (int o = 16; o; o >>= 1) s += __shfl_xor_sync(0xffffffffu, s, o);
                float gv = sigm(s + b_g[0]);
                const float* wkb = d_wk + bb * MD;
                const float* ckb = d_ck + bb * MD;
                const float* mkb = d_Mk + (size_t)bb * MD * KD;
                int m16 = bb >> 4, r = bb & 15;
                unsigned* oH = d_AfH[pn];
                unsigned* oL = d_AfL[pn];
                for (int dp = lane + ((wid >> 3) << 5); dp < 129; dp += 64) {
                    int d0 = dp * 2;
                    float v0 = 0.f, v1 = 0.f;
                    if (d0 < 256) {
#pragma unroll 2
                        for (int m = 0; m < t; m++) {
                            float w = wkb[m];
                            v0 += w * mkb[m * KD + d0];
                            v1 += w * mkb[m * KD + d0 + 1];
                        }
                    } else {
                        for (int m = 0; m < t; m++) v0 += wkb[m] * ckb[m];
                    }
                    v0 *= gv; v1 *= gv;
                    __nv_bfloat16 h0 = __float2bfloat16_rn(v0);
                    __nv_bfloat16 h1 = __float2bfloat16_rn(v1);
                    int ch = d0 >> 4, kk = d0 & 15;
                    int lane_a = (r & 7) * 4 + ((kk & 7) >> 1);
                    int w = (r >> 3) + ((kk >> 3) << 1);
                    size_t widx = ((size_t)(m16 * 49 + ch)) * 128 + lane_a * 4 + w;
                    oH[widx] = (unsigned)__bfloat16_as_ushort(h1) << 16 |
                               __bfloat16_as_ushort(h0);
                    oL[widx] = packbf2(v0 - __bfloat162float(h0),
                                       v1 - __bfloat162float(h1));
                }
            }
            gridBarrier();  // key_r, M_k visible for next step
        } else {  // t == 32: y_lin + argmax
            if (bx >= 64 && bx < 128 && wid < 8) {
                int bb = (bx - 64) * 8 + wid;
                const float* hb = d_h + (size_t)bb * HD;
                float yv[4];
#pragma unroll
                for (int yi = 0; yi < YD; yi++) {
                    float s = 0.f;
                    for (int l = lane; l < HD; l += 32) s += hb[l] * W_y[yi * HD + l];
#pragma unroll
                    for (int o = 16; o; o >>= 1) s += __shfl_xor_sync(0xffffffffu, s, o);
                    yv[yi] = s + b_y[yi];
                }
                if (lane == 0) {
                    int am = 0; float bst = yv[0];
#pragma unroll
                    for (int yi = 1; yi < YD; yi++)
                        if (yv[yi] > bst) { bst = yv[yi]; am = yi; }
                    if (out_size >= BD * YD) {
                        float* of = (float*)outp;
                        of[bb * 4 + 0] = yv[0];
                        of[bb * 4 + 1] = yv[1];
                        of[bb * 4 + 2] = yv[2];
                        of[bb * 4 + 3] = yv[3];
                        if (out_size >= BD * YD + BD) of[BD * YD + bb] = (float)am;
                    } else {
                        ((int*)outp)[bb] = am;
                    }
                }
            }
        }
    }
}

// ------------------------------- launcher ----------------------------------
extern "C" void kernel_launch(void* const* d_in, const int* in_sizes, int n_in,
                              void* d_out, int out_size)
{
    const float* x_seq  = (const float*)d_in[0];
    const float* W_enc  = (const float*)d_in[1];
    const float* gamma  = (const float*)d_in[2];
    const float* beta   = (const float*)d_in[3];
    const float* W_ih   = (const float*)d_in[4];
    const float* W_hh   = (const float*)d_in[5];
    const float* b_ih   = (const float*)d_in[6];
    const float* b_hh   = (const float*)d_in[7];
    const float* W_key  = (const float*)d_in[8];
    const float* b_key  = (const float*)d_in[9];
    const float* W_g    = (const float*)d_in[10];
    const float* b_g    = (const float*)d_in[11];
    const float* cgain  = (const float*)d_in[12];
    const float* cbias  = (const float*)d_in[13];
    const float* W_y    = (const float*)d_in[14];
    const float* b_y    = (const float*)d_in[15];

    prep_kernel<<<1024, 256>>>(W_ih, W_hh, b_ih, b_hh, W_key);
    enc_gemm<<<256, 256>>>(x_seq, W_enc);
    ctx_norm<<<BD, 128>>>(gamma, beta);
    recur<<<NB, NT>>>(b_key, W_g, b_g, cgain, cbias, W_y, b_y, d_out, out_size);
}

// round 6
// speedup vs baseline: 2.4512x; 1.0122x over previous
#include <cuda_runtime.h>
#include <cuda_bf16.h>
#include <math.h>

// ---------------------------------------------------------------------------
// Model_24730421690434  (R5)
//   B=512, T=32, Z=128, K=256, H=512, 4H=2048, Y=4, M=33
// R5: B weights direct L2->reg (no smem staging), A via 3-stage cp.async smem,
//     register cell state, tanh.approx, tensor key_w GEMM, unrolled attention.
// ---------------------------------------------------------------------------

#define NB 128
#define NT 512

#define BD 512
#define TD 32
#define ZD 128
#define KD 256
#define HD 512
#define YD 4
#define MD 33
#define G4 2048
#define NCH 49      // 784/16 chunks: 0..16 key_r(+conf+pad), 17..48 h

// ------------------------------- device state ------------------------------
// Weight fragments (gate-interleaved col' = jcol*4+gate):
//   word[(n8*49 + c)*64 + lane*2 + w]
__device__ __align__(256) unsigned d_BfH[256 * 49 * 64];
__device__ __align__(256) unsigned d_BfL[256 * 49 * 64];
// W_key fragments: word[(n8*32 + c)*64 + lane*2 + w], n8<32, c<32
__device__ __align__(256) unsigned d_WKfH[32 * 32 * 64];
__device__ __align__(256) unsigned d_WKfL[32 * 32 * 64];
// Activation fragments (unified key_r+h), double-buffered by step parity:
//   word[(m16*49 + c)*128 + lane_a*4 + w]
__device__ __align__(256) unsigned d_AfH[2][32 * 49 * 128];
__device__ __align__(256) unsigned d_AfL[2][32 * 49 * 128];

__device__ __align__(256) float d_biasg[G4];           // gate-interleaved
__device__ __align__(256) float d_zbuf[BD * TD * ZD];  // normalized z (== M_v)
__device__ __align__(256) float d_h[BD * HD];          // fp32 h
__device__ __align__(256) float d_Mk[(size_t)BD * MD * KD];
__device__ __align__(256) float d_wk[BD * MD];
__device__ __align__(256) float d_ck[BD * MD];
__device__ unsigned g_cnt;
__device__ unsigned g_gen;

__device__ __forceinline__ float tanhap(float x) {
    float y; asm("tanh.approx.f32 %0, %1;" : "=f"(y) : "f"(x)); return y;
}
__device__ __forceinline__ float sigm(float x) {
    return fmaf(tanhap(x * 0.5f), 0.5f, 0.5f);
}

__device__ __forceinline__ void gridBarrier() {
    __syncthreads();
    if (threadIdx.x == 0) {
        unsigned gen = *(volatile unsigned*)&g_gen;
        __threadfence();
        unsigned t = atomicAdd(&g_cnt, 1u);
        if (t == NB - 1u) {
            g_cnt = 0u;
            __threadfence();
            atomicAdd(&g_gen, 1u);
        } else {
            while (*(volatile unsigned*)&g_gen == gen) { __nanosleep(32); }
        }
        __threadfence();
    }
    __syncthreads();
}

__device__ __forceinline__ void cpasync16(void* dst, const void* src) {
    unsigned saddr = (unsigned)__cvta_generic_to_shared(dst);
    asm volatile("cp.async.cg.shared.global [%0], [%1], 16;\n" ::"r"(saddr), "l"(src));
}
#define CPCOMMIT() asm volatile("cp.async.commit_group;\n" ::)
#define CPWAIT(n)  asm volatile("cp.async.wait_group %0;\n" ::"n"(n))

__device__ __forceinline__ void mma16816(float* d, const unsigned* a, const unsigned* b) {
    asm volatile(
        "mma.sync.aligned.m16n8k16.row.col.f32.bf16.bf16.f32 "
        "{%0,%1,%2,%3},{%4,%5,%6,%7},{%8,%9},{%0,%1,%2,%3};"
        : "+f"(d[0]), "+f"(d[1]), "+f"(d[2]), "+f"(d[3])
        : "r"(a[0]), "r"(a[1]), "r"(a[2]), "r"(a[3]), "r"(b[0]), "r"(b[1]));
}

__device__ __forceinline__ unsigned packbf2(float v0, float v1) {
    unsigned short u0 = __bfloat16_as_ushort(__float2bfloat16_rn(v0));
    unsigned short u1 = __bfloat16_as_ushort(__float2bfloat16_rn(v1));
    return (unsigned)u1 << 16 | u0;
}

// ------------------- 64x128 fp32 tile GEMM (encoder only) ------------------
__device__ __forceinline__ void mm64x128(const float* __restrict__ A, int lda,
                                         const float* __restrict__ B, int ldb,
                                         int m0, int n0, int Kt,
                                         float (&acc)[4][8], float* As, float* Bs)
{
    const int tid = threadIdx.x;
    const int tx = tid & 15, ty = tid >> 4;
#pragma unroll
    for (int i = 0; i < 4; i++)
#pragma unroll
        for (int j = 0; j < 8; j++) acc[i][j] = 0.f;

    for (int k0 = 0; k0 < Kt; k0 += 16) {
        {
            int r = tid >> 2, q = tid & 3;
            float4 av = *(const float4*)(A + (size_t)(m0 + r) * lda + k0 + q * 4);
            As[(q * 4 + 0) * 64 + r] = av.x;
            As[(q * 4 + 1) * 64 + r] = av.y;
            As[(q * 4 + 2) * 64 + r] = av.z;
            As[(q * 4 + 3) * 64 + r] = av.w;
        }
#pragma unroll
        for (int jj = 0; jj < 2; jj++) {
            int idx = tid + jj * 256;
            int kk = idx >> 5, qq = idx & 31;
            *(float4*)(Bs + kk * 128 + qq * 4) =
                *(const float4*)(B + (size_t)(k0 + kk) * ldb + n0 + qq * 4);
        }
        __syncthreads();
#pragma unroll
        for (int kk = 0; kk < 16; kk++) {
            float a[4];
#pragma unroll
            for (int i = 0; i < 4; i++) a[i] = As[kk * 64 + ty * 4 + i];
            float4 b0 = *(const float4*)(Bs + kk * 128 + tx * 8);
            float4 b1 = *(const float4*)(Bs + kk * 128 + tx * 8 + 4);
            float bb[8] = {b0.x, b0.y, b0.z, b0.w, b1.x, b1.y, b1.z, b1.w};
#pragma unroll
            for (int i = 0; i < 4; i++)
#pragma unroll
                for (int j = 0; j < 8; j++) acc[i][j] = fmaf(a[i], bb[j], acc[i][j]);
        }
        __syncthreads();
    }
}

// ------------------------------- prep kernel -------------------------------
__device__ __forceinline__ float fetchW(const float* W_ih, const float* W_hh,
                                        int n, int k) {
    if (k < 257) return W_ih[n * 257 + k];
    if (k >= 272 && k < 784) return W_hh[n * HD + (k - 272)];
    return 0.f;
}

__global__ void __launch_bounds__(256) prep_kernel(
    const float* __restrict__ W_ih, const float* __restrict__ W_hh,
    const float* __restrict__ b_ih, const float* __restrict__ b_hh,
    const float* __restrict__ W_key)
{
    const int stride = gridDim.x * blockDim.x;
    const int gtid = blockIdx.x * blockDim.x + threadIdx.x;

    // gate weight fragments (gate-interleaved columns)
    for (int idx = gtid; idx < 256 * 49 * 64; idx += stride) {
        int n8 = idx / (49 * 64);
        int rem = idx - n8 * (49 * 64);
        int c = rem >> 6;
        int lw = rem & 63;
        int lane = lw >> 1, w = lw & 1;
        int lr = lane >> 2, lc = lane & 3;
        int np = n8 * 8 + lr;            // col'
        int g = np & 3, j = np >> 2;
        int orig = g * 512 + j;
        int k = c * 16 + w * 8 + lc * 2;
        float v0 = fetchW(W_ih, W_hh, orig, k);
        float v1 = fetchW(W_ih, W_hh, orig, k + 1);
        __nv_bfloat16 h0 = __float2bfloat16_rn(v0);
        __nv_bfloat16 h1 = __float2bfloat16_rn(v1);
        d_BfH[idx] = (unsigned)__bfloat16_as_ushort(h1) << 16 | __bfloat16_as_ushort(h0);
        d_BfL[idx] = packbf2(v0 - __bfloat162float(h0), v1 - __bfloat162float(h1));
    }
    // W_key fragments
    for (int idx = gtid; idx < 32 * 32 * 64; idx += stride) {
        int n8 = idx / (32 * 64);
        int rem = idx - n8 * (32 * 64);
        int c = rem >> 6;
        int lw = rem & 63;
        int lane = lw >> 1, w = lw & 1;
        int lr = lane >> 2, lc = lane & 3;
        int n = n8 * 8 + lr;
        int k = c * 16 + w * 8 + lc * 2;
        float v0 = W_key[n * HD + k];
        float v1 = W_key[n * HD + k + 1];
        __nv_bfloat16 h0 = __float2bfloat16_rn(v0);
        __nv_bfloat16 h1 = __float2bfloat16_rn(v1);
        d_WKfH[idx] = (unsigned)__bfloat16_as_ushort(h1) << 16 | __bfloat16_as_ushort(h0);
        d_WKfL[idx] = packbf2(v0 - __bfloat162float(h0), v1 - __bfloat162float(h1));
    }
    // bias (gate-interleaved)
    for (int np = gtid; np < G4; np += stride) {
        int orig = (np & 3) * 512 + (np >> 2);
        d_biasg[np] = b_ih[orig] + b_hh[orig];
    }
    // zero activation fragments (both parities, both planes)
    for (int idx = gtid; idx < 32 * 49 * 128; idx += stride) {
        d_AfH[0][idx] = 0u; d_AfL[0][idx] = 0u;
        d_AfH[1][idx] = 0u; d_AfL[1][idx] = 0u;
    }
}

// ------------------------------ encoder GEMM -------------------------------
__global__ void __launch_bounds__(256) enc_gemm(const float* __restrict__ X,
                                                const float* __restrict__ W)
{
    __shared__ float As[16 * 64];
    __shared__ float Bs[16 * 128];
    int m0 = blockIdx.x * 64;
    float acc[4][8];
    mm64x128(X, 1024, W, 128, m0, 0, 1024, acc, As, Bs);
    int tx = threadIdx.x & 15, ty = threadIdx.x >> 4;
#pragma unroll
    for (int i = 0; i < 4; i++)
#pragma unroll
        for (int j = 0; j < 8; j++)
            d_zbuf[(size_t)(m0 + ty * 4 + i) * ZD + tx * 8 + j] = acc[i][j];
}

// ------------------------------ context norm -------------------------------
__global__ void __launch_bounds__(128) ctx_norm(const float* __restrict__ gamma,
                                                const float* __restrict__ beta)
{
    int b = blockIdx.x, z = threadIdx.x;
    float v[TD];
    float s = 0.f;
#pragma unroll
    for (int t = 0; t < TD; t++) { v[t] = d_zbuf[((b * TD) + t) * ZD + z]; s += v[t]; }
    float mu = s * (1.f / TD);
    float q = 0.f;
#pragma unroll
    for (int t = 0; t < TD; t++) { float d = v[t] - mu; q += d * d; }
    float inv = rsqrtf(q * (1.f / TD) + 1e-8f);
    float ga = gamma[z], be = beta[z];
#pragma unroll
    for (int t = 0; t < TD; t++)
        d_zbuf[((b * TD) + t) * ZD + z] = (v[t] - mu) * inv * ga + be;
}

// ------------------------- persistent recurrence ---------------------------
__global__ void __launch_bounds__(NT) recur(
    const float* __restrict__ b_key, const float* __restrict__ W_g,
    const float* __restrict__ b_g,   const float* __restrict__ cgain,
    const float* __restrict__ cbias, const float* __restrict__ W_y,
    const float* __restrict__ b_y,   void* outp, int out_size)
{
    // A-only staging: stage = 1024 words (hi 512 | lo 512) = 4 KB, 3 stages
    __shared__ __align__(16) unsigned sA[3][1024];
    __shared__ float s_sc[256];

    const int tid = threadIdx.x;
    const int bx = blockIdx.x;
    const int lane = tid & 31, wid = tid >> 5;
    const int lr = lane >> 2, lc = lane & 3;

    // ---- Phase A mapping: 8 m-blocks x 16 n-blocks; warp = 1 m16 x 4 n8 ----
    const int mblk = bx >> 4, nblk = bx & 15;
    const int wmm = wid & 3;                 // m16 local
    const int wn  = wid >> 2;                // n8 group (x4)
    const int m16g = mblk * 4 + wmm;

    // A cp.async mapping (tid < 256): plane | m16 | lane words
    const int a_plane = tid >> 7;
    const int a_m16A  = mblk * 4 + ((tid >> 5) & 3);
    const int a_widx  = (tid & 31) * 4;
    const int a_soff  = a_plane * 512 + ((tid >> 5) & 3) * 128 + a_widx;

    // B direct-load pointers: 4 n8 per warp, hi/lo planes
    const unsigned* pB[4][2];
#pragma unroll
    for (int jj = 0; jj < 4; jj++) {
        int n8g = nblk * 16 + wn * 4 + jj;
        pB[jj][0] = d_BfH + (size_t)n8g * (49 * 64) + lane * 2;
        pB[jj][1] = d_BfL + (size_t)n8g * (49 * 64) + lane * 2;
    }

    // hoisted gate biases per jj
    float4 bias4[4];
#pragma unroll
    for (int jj = 0; jj < 4; jj++) {
        int n8g = nblk * 16 + wn * 4 + jj;
        int jq = n8g * 2 + (lc >> 1);
        bias4[jj] = *(const float4*)(d_biasg + jq * 4);
    }

    const bool odd = (lc & 1);
    float cc[4] = {0.f, 0.f, 0.f, 0.f};      // cell state in registers

    for (int t = 0; t < MD; t++) {
        const int cur = t & 1, pn = (t + 1) & 1;
        // ============ Phase A: gate GEMM + fused cell =======================
        {
            const unsigned* aSrc = (a_plane ? d_AfL[cur] : d_AfH[cur]) +
                                   (size_t)a_m16A * (49 * 128) + a_widx;
            // prologue: A stages 0,1
#pragma unroll
            for (int p = 0; p < 2; p++) {
                if (tid < 256) cpasync16(&sA[p][a_soff], aSrc + p * 128);
                CPCOMMIT();
            }
            // prologue: B chunk 0 into regs
            unsigned cBH[4][2], cBL[4][2], nBH[4][2], nBL[4][2];
#pragma unroll
            for (int jj = 0; jj < 4; jj++) {
                *(uint2*)cBH[jj] = *(const uint2*)(pB[jj][0]);
                *(uint2*)cBL[jj] = *(const uint2*)(pB[jj][1]);
            }

            float acc[4][4];
#pragma unroll
            for (int j = 0; j < 4; j++)
#pragma unroll
                for (int r = 0; r < 4; r++) acc[j][r] = 0.f;

#pragma unroll 1
            for (int c = 0; c < NCH; c++) {
                // prefetch B chunk c+1
                if (c < NCH - 1) {
#pragma unroll
                    for (int jj = 0; jj < 4; jj++) {
                        *(uint2*)nBH[jj] = *(const uint2*)(pB[jj][0] + (c + 1) * 64);
                        *(uint2*)nBL[jj] = *(const uint2*)(pB[jj][1] + (c + 1) * 64);
                    }
                }
                CPWAIT(1);
                __syncthreads();
                const unsigned* base = sA[c % 3];
                unsigned aH[4], aL[4];
                *(uint4*)aH = *(const uint4*)(base + wmm * 128 + lane * 4);
                *(uint4*)aL = *(const uint4*)(base + 512 + wmm * 128 + lane * 4);
                // issue A chunk c+2
                if (c + 2 < NCH) {
                    if (tid < 256) cpasync16(&sA[(c + 2) % 3][a_soff], aSrc + (c + 2) * 128);
                }
                CPCOMMIT();
#pragma unroll
                for (int jj = 0; jj < 4; jj++) mma16816(acc[jj], aH, cBH[jj]);
#pragma unroll
                for (int jj = 0; jj < 4; jj++) mma16816(acc[jj], aH, cBL[jj]);
#pragma unroll
                for (int jj = 0; jj < 4; jj++) mma16816(acc[jj], aL, cBH[jj]);
#pragma unroll
                for (int jj = 0; jj < 4; jj++) {
                    *(uint2*)cBH[jj] = *(uint2*)nBH[jj];
                    *(uint2*)cBL[jj] = *(uint2*)nBL[jj];
                }
            }

            // ---- fused epilogue: gates + cell update + h frag stores ----
            unsigned* hOutH = d_AfH[pn];
            unsigned* hOutL = d_AfL[pn];
#pragma unroll
            for (int jj = 0; jj < 4; jj++) {
                float a0 = acc[jj][0], a1 = acc[jj][1];
                float a2 = acc[jj][2], a3 = acc[jj][3];
                float p0 = __shfl_xor_sync(0xffffffffu, odd ? a0 : a2, 1);
                float p1 = __shfl_xor_sync(0xffffffffu, odd ? a1 : a3, 1);
                float4 bb4 = bias4[jj];
                float gi, gf, gg, go;
                if (!odd) { gi = a0 + bb4.x; gf = a1 + bb4.y; gg = p0 + bb4.z; go = p1 + bb4.w; }
                else      { gi = p0 + bb4.x; gf = p1 + bb4.y; gg = a2 + bb4.z; go = a3 + bb4.w; }
                float cn = sigm(gf) * cc[jj] + sigm(gi) * tanhap(gg);
                cc[jj] = cn;
                float hv = sigm(go) * tanhap(cn);
                int n8g = nblk * 16 + wn * 4 + jj;
                int jq = n8g * 2 + (lc >> 1);
                int row = m16g * 16 + lr + (odd ? 8 : 0);
                d_h[row * HD + jq] = hv;
                // combine word pair with lane^2 partner, low-kk lane stores
                __nv_bfloat16 hh = __float2bfloat16_rn(hv);
                __nv_bfloat16 hl = __float2bfloat16_rn(hv - __bfloat162float(hh));
                unsigned uh = (unsigned)__bfloat16_as_ushort(hh);
                unsigned ul = (unsigned)__bfloat16_as_ushort(hl);
                unsigned ph = __shfl_xor_sync(0xffffffffu, uh, 2);
                unsigned pl = __shfl_xor_sync(0xffffffffu, ul, 2);
                if ((lc & 2) == 0) {
                    int kk = jq & 15;
                    int ch = 17 + (jq >> 4);
                    int lane_a = lr * 4 + ((kk & 7) >> 1);
                    int w = (odd ? 1 : 0) + ((kk >> 3) << 1);
                    size_t widx = ((size_t)(m16g * 49 + ch)) * 128 + lane_a * 4 + w;
                    hOutH[widx] = (ph << 16) | uh;
                    hOutL[widx] = (pl << 16) | ul;
                }
            }
        }

        // ---- attention scores + softmax + confidence ----
        if (t >= 1 && t < TD) {
            int bb = bx * 4 + ((tid >> 6) & 3);
            int m = tid & 63;
            if (tid < 256) {
                float s = 0.f;
                if (m < t) {
                    const float* zt = d_zbuf + (size_t)(bb * TD + t) * ZD;
                    const float* zm = d_zbuf + (size_t)(bb * TD + m) * ZD;
#pragma unroll 4
                    for (int i = 0; i < ZD; i++) s += zt[i] * zm[i];
                    d_ck[bb * MD + m] = sigm(s * cgain[0] + cbias[0]);
                }
                s_sc[tid] = s;
            }
            __syncthreads();
            if (tid < 256 && m == 0) {
                float mx = -3.4e38f;
                for (int mm = 0; mm < t; mm++) mx = fmaxf(mx, s_sc[tid + mm]);
                float sum = 0.f;
                for (int mm = 0; mm < t; mm++) {
                    float e = __expf(s_sc[tid + mm] - mx);
                    d_wk[bb * MD + mm] = e;
                    sum += e;
                }
                float inv = __fdividef(1.f, sum);
                for (int mm = 0; mm < t; mm++) d_wk[bb * MD + mm] *= inv;
            }
        }
        gridBarrier();  // h, wk, ck visible everywhere

        // ============ Phase C ==============================================
        if (t < TD) {
            if (bx < 64) {  // key_w = relu(h @ W_key^T + b_key), tensor cores
                const int m16 = (bx >> 3) * 4 + (wid & 3);
                const int n8  = (bx & 7) * 4 + (wid >> 2);
                const unsigned* pAH = d_AfH[pn] + ((size_t)m16 * 49 + 17) * 128 + lane * 4;
                const unsigned* pAL = d_AfL[pn] + ((size_t)m16 * 49 + 17) * 128 + lane * 4;
                const unsigned* pWH = d_WKfH + (size_t)n8 * (32 * 64) + lane * 2;
                const unsigned* pWL = d_WKfL + (size_t)n8 * (32 * 64) + lane * 2;
                float kacc[4] = {0.f, 0.f, 0.f, 0.f};
                unsigned nAH[4], nAL[4], nBH2[2], nBL2[2];
                *(uint4*)nAH = *(const uint4*)(pAH);
                *(uint4*)nAL = *(const uint4*)(pAL);
                *(uint2*)nBH2 = *(const uint2*)(pWH);
                *(uint2*)nBL2 = *(const uint2*)(pWL);
#pragma unroll 1
                for (int ch = 0; ch < 32; ch++) {
                    unsigned cAH[4], cAL[4], cBH2[2], cBL2[2];
                    *(uint4*)cAH = *(uint4*)nAH; *(uint4*)cAL = *(uint4*)nAL;
                    *(uint2*)cBH2 = *(uint2*)nBH2; *(uint2*)cBL2 = *(uint2*)nBL2;
                    if (ch < 31) {
                        *(uint4*)nAH = *(const uint4*)(pAH + (ch + 1) * 128);
                        *(uint4*)nAL = *(const uint4*)(pAL + (ch + 1) * 128);
                        *(uint2*)nBH2 = *(const uint2*)(pWH + (ch + 1) * 64);
                        *(uint2*)nBL2 = *(const uint2*)(pWL + (ch + 1) * 64);
                    }
                    mma16816(kacc, cAH, cBH2);
                    mma16816(kacc, cAH, cBL2);
                    mma16816(kacc, cAL, cBH2);
                }
                int col = n8 * 8 + lc * 2;
                float bk0 = b_key[col], bk1 = b_key[col + 1];
                int row0 = m16 * 16 + lr;
                float2 v0 = {fmaxf(kacc[0] + bk0, 0.f), fmaxf(kacc[1] + bk1, 0.f)};
                float2 v1 = {fmaxf(kacc[2] + bk0, 0.f), fmaxf(kacc[3] + bk1, 0.f)};
                *(float2*)(d_Mk + ((size_t)row0 * MD + t) * KD + col) = v0;
                *(float2*)(d_Mk + ((size_t)(row0 + 8) * MD + t) * KD + col) = v1;
            } else {  // gate g + attention read -> key_r fragments (parity pn)
                int bb = (bx - 64) * 8 + (wid & 7);
                const float* hb = d_h + (size_t)bb * HD;
                float s = 0.f;
                for (int l = lane; l < HD; l += 32) s += hb[l] * W_g[l];
#pragma unroll
                for (int o = 16; o; o >>= 1) s += __shfl_xor_sync(0xffffffffu, s, o);
                float gv = sigm(s + b_g[0]);
                const float* wkb = d_wk + bb * MD;
                const float* ckb = d_ck + bb * MD;
                const float* mkb = d_Mk + (size_t)bb * MD * KD;
                int m16 = bb >> 4, r = bb & 15;
                unsigned* oH = d_AfH[pn];
                unsigned* oL = d_AfL[pn];
                for (int dp = lane + ((wid >> 3) << 5); dp < 129; dp += 64) {
                    int d0 = dp * 2;
                    float v0 = 0.f, v1 = 0.f;
                    if (d0 < 256) {
                        int m = 0;
                        for (; m + 4 <= t; m += 4) {
                            float w0 = wkb[m], w1 = wkb[m + 1];
                            float w2 = wkb[m + 2], w3 = wkb[m + 3];
                            float x0 = mkb[(m) * KD + d0],     y0 = mkb[(m) * KD + d0 + 1];
                            float x1 = mkb[(m + 1) * KD + d0], y1 = mkb[(m + 1) * KD + d0 + 1];
                            float x2 = mkb[(m + 2) * KD + d0], y2 = mkb[(m + 2) * KD + d0 + 1];
                            float x3 = mkb[(m + 3) * KD + d0], y3 = mkb[(m + 3) * KD + d0 + 1];
                            v0 += w0 * x0 + w1 * x1 + w2 * x2 + w3 * x3;
                            v1 += w0 * y0 + w1 * y1 + w2 * y2 + w3 * y3;
                        }
                        for (; m < t; m++) {
                            float w = wkb[m];
                            v0 += w * mkb[m * KD + d0];
                            v1 += w * mkb[m * KD + d0 + 1];
                        }
                    } else {
                        for (int m = 0; m < t; m++) v0 += wkb[m] * ckb[m];
                    }
                    v0 *= gv; v1 *= gv;
                    __nv_bfloat16 h0 = __float2bfloat16_rn(v0);
                    __nv_bfloat16 h1 = __float2bfloat16_rn(v1);
                    int ch = d0 >> 4, kk = d0 & 15;
                    int lane_a = (r & 7) * 4 + ((kk & 7) >> 1);
                    int w = (r >> 3) + ((kk >> 3) << 1);
                    size_t widx = ((size_t)(m16 * 49 + ch)) * 128 + lane_a * 4 + w;
                    oH[widx] = (unsigned)__bfloat16_as_ushort(h1) << 16 |
                               __bfloat16_as_ushort(h0);
                    oL[widx] = packbf2(v0 - __bfloat162float(h0),
                                       v1 - __bfloat162float(h1));
                }
            }
            gridBarrier();  // key_r, M_k visible for next step
        } else {  // t == 32: y_lin + argmax
            if (bx >= 64 && bx < 128 && wid < 8) {
                int bb = (bx - 64) * 8 + wid;
                const float* hb = d_h + (size_t)bb * HD;
                float yv[4];
#pragma unroll
                for (int yi = 0; yi < YD; yi++) {
                    float s = 0.f;
                    for (int l = lane; l < HD; l += 32) s += hb[l] * W_y[yi * HD + l];
#pragma unroll
                    for (int o = 16; o; o >>= 1) s += __shfl_xor_sync(0xffffffffu, s, o);
                    yv[yi] = s + b_y[yi];
                }
                if (lane == 0) {
                    int am = 0; float bst = yv[0];
#pragma unroll
                    for (int yi = 1; yi < YD; yi++)
                        if (yv[yi] > bst) { bst = yv[yi]; am = yi; }
                    if (out_size >= BD * YD) {
                        float* of = (float*)outp;
                        of[bb * 4 + 0] = yv[0];
                        of[bb * 4 + 1] = yv[1];
                        of[bb * 4 + 2] = yv[2];
                        of[bb * 4 + 3] = yv[3];
                        if (out_size >= BD * YD + BD) of[BD * YD + bb] = (float)am;
                    } else {
                        ((int*)outp)[bb] = am;
                    }
                }
            }
        }
    }
}

// ------------------------------- launcher ----------------------------------
extern "C" void kernel_launch(void* const* d_in, const int* in_sizes, int n_in,
                              void* d_out, int out_size)
{
    const float* x_seq  = (const float*)d_in[0];
    const float* W_enc  = (const float*)d_in[1];
    const float* gamma  = (const float*)d_in[2];
    const float* beta   = (const float*)d_in[3];
    const float* W_ih   = (const float*)d_in[4];
    const float* W_hh   = (const float*)d_in[5];
    const float* b_ih   = (const float*)d_in[6];
    const float* b_hh   = (const float*)d_in[7];
    const float* W_key  = (const float*)d_in[8];
    const float* b_key  = (const float*)d_in[9];
    const float* W_g    = (const float*)d_in[10];
    const float* b_g    = (const float*)d_in[11];
    const float* cgain  = (const float*)d_in[12];
    const float* cbias  = (const float*)d_in[13];
    const float* W_y    = (const float*)d_in[14];
    const float* b_y    = (const float*)d_in[15];

    prep_kernel<<<1024, 256>>>(W_ih, W_hh, b_ih, b_hh, W_key);
    enc_gemm<<<256, 256>>>(x_seq, W_enc);
    ctx_norm<<<BD, 128>>>(gamma, beta);
    recur<<<NB, NT>>>(b_key, W_g, b_g, cgain, cbias, W_y, b_y, d_out, out_size);
}

// round 8
// speedup vs baseline: 2.7800x; 1.1341x over previous
#include <cuda_runtime.h>
#include <cuda_bf16.h>
#include <math.h>

// ---------------------------------------------------------------------------
// Model_24730421690434  (R7)
//   B=512, T=32, Z=128, K=256, H=512, 4H=2048, Y=4, M=33
// R7: R5 numerics restored (B hi+lo, 3-term split, 12 MMA/chunk) + R6 safe
//     wins: attention softmax precomputed, A group-staged (3 chunks/group,
//     triple buffer, 17 syncs/step), register cell state.
// ---------------------------------------------------------------------------

#define NB 128
#define NT 512

#define BD 512
#define TD 32
#define ZD 128
#define KD 256
#define HD 512
#define YD 4
#define MD 33
#define G4 2048
#define NCHP 51     // padded chunks (51 = 17*3): 0..16 key_r, 17..48 h, 49..50 zero
#define NGRP 17

// ------------------------------- device state ------------------------------
// Weight fragments (gate-interleaved col' = jcol*4+gate), hi and lo planes:
//   word[(n8*51 + c)*64 + lane*2 + w]
__device__ __align__(256) unsigned d_BfH[256 * NCHP * 64];
__device__ __align__(256) unsigned d_BfL[256 * NCHP * 64];
// W_key fragments: word[(n8*32 + c)*64 + lane*2 + w]
__device__ __align__(256) unsigned d_WKfH[32 * 32 * 64];
__device__ __align__(256) unsigned d_WKfL[32 * 32 * 64];
// Activation fragments, double-buffered by step parity:
//   word[(m16*51 + c)*128 + lane_a*4 + w]
__device__ __align__(256) unsigned d_AfH[2][32 * NCHP * 128];
__device__ __align__(256) unsigned d_AfL[2][32 * NCHP * 128];

__device__ __align__(256) float d_biasg[G4];           // gate-interleaved
__device__ __align__(256) float d_zbuf[BD * TD * ZD];  // normalized z (== M_v)
__device__ __align__(256) float d_h[BD * HD];          // fp32 h
__device__ __align__(256) float d_Mk[(size_t)BD * MD * KD];
__device__ __align__(256) float d_wk[(size_t)BD * MD * MD];  // [b][t][m]
__device__ __align__(256) float d_ck[(size_t)BD * MD * MD];  // [b][t][m]
__device__ unsigned g_cnt;
__device__ unsigned g_gen;

__device__ __forceinline__ float tanhap(float x) {
    float y; asm("tanh.approx.f32 %0, %1;" : "=f"(y) : "f"(x)); return y;
}
__device__ __forceinline__ float sigm(float x) {
    return fmaf(tanhap(x * 0.5f), 0.5f, 0.5f);
}

__device__ __forceinline__ void gridBarrier() {
    __syncthreads();
    if (threadIdx.x == 0) {
        unsigned gen = *(volatile unsigned*)&g_gen;
        __threadfence();
        unsigned t = atomicAdd(&g_cnt, 1u);
        if (t == NB - 1u) {
            g_cnt = 0u;
            __threadfence();
            atomicAdd(&g_gen, 1u);
        } else {
            while (*(volatile unsigned*)&g_gen == gen) { __nanosleep(32); }
        }
        __threadfence();
    }
    __syncthreads();
}

__device__ __forceinline__ void cpasync16(void* dst, const void* src) {
    unsigned saddr = (unsigned)__cvta_generic_to_shared(dst);
    asm volatile("cp.async.cg.shared.global [%0], [%1], 16;\n" ::"r"(saddr), "l"(src));
}
#define CPCOMMIT() asm volatile("cp.async.commit_group;\n" ::)
#define CPWAIT(n)  asm volatile("cp.async.wait_group %0;\n" ::"n"(n))

__device__ __forceinline__ void mma16816(float* d, const unsigned* a, const unsigned* b) {
    asm volatile(
        "mma.sync.aligned.m16n8k16.row.col.f32.bf16.bf16.f32 "
        "{%0,%1,%2,%3},{%4,%5,%6,%7},{%8,%9},{%0,%1,%2,%3};"
        : "+f"(d[0]), "+f"(d[1]), "+f"(d[2]), "+f"(d[3])
        : "r"(a[0]), "r"(a[1]), "r"(a[2]), "r"(a[3]), "r"(b[0]), "r"(b[1]));
}

__device__ __forceinline__ unsigned packbf2(float v0, float v1) {
    unsigned short u0 = __bfloat16_as_ushort(__float2bfloat16_rn(v0));
    unsigned short u1 = __bfloat16_as_ushort(__float2bfloat16_rn(v1));
    return (unsigned)u1 << 16 | u0;
}

// ------------------- 64x128 fp32 tile GEMM (encoder only) ------------------
__device__ __forceinline__ void mm64x128(const float* __restrict__ A, int lda,
                                         const float* __restrict__ B, int ldb,
                                         int m0, int n0, int Kt,
                                         float (&acc)[4][8], float* As, float* Bs)
{
    const int tid = threadIdx.x;
    const int tx = tid & 15, ty = tid >> 4;
#pragma unroll
    for (int i = 0; i < 4; i++)
#pragma unroll
        for (int j = 0; j < 8; j++) acc[i][j] = 0.f;

    for (int k0 = 0; k0 < Kt; k0 += 16) {
        {
            int r = tid >> 2, q = tid & 3;
            float4 av = *(const float4*)(A + (size_t)(m0 + r) * lda + k0 + q * 4);
            As[(q * 4 + 0) * 64 + r] = av.x;
            As[(q * 4 + 1) * 64 + r] = av.y;
            As[(q * 4 + 2) * 64 + r] = av.z;
            As[(q * 4 + 3) * 64 + r] = av.w;
        }
#pragma unroll
        for (int jj = 0; jj < 2; jj++) {
            int idx = tid + jj * 256;
            int kk = idx >> 5, qq = idx & 31;
            *(float4*)(Bs + kk * 128 + qq * 4) =
                *(const float4*)(B + (size_t)(k0 + kk) * ldb + n0 + qq * 4);
        }
        __syncthreads();
#pragma unroll
        for (int kk = 0; kk < 16; kk++) {
            float a[4];
#pragma unroll
            for (int i = 0; i < 4; i++) a[i] = As[kk * 64 + ty * 4 + i];
            float4 b0 = *(const float4*)(Bs + kk * 128 + tx * 8);
            float4 b1 = *(const float4*)(Bs + kk * 128 + tx * 8 + 4);
            float bb[8] = {b0.x, b0.y, b0.z, b0.w, b1.x, b1.y, b1.z, b1.w};
#pragma unroll
            for (int i = 0; i < 4; i++)
#pragma unroll
                for (int j = 0; j < 8; j++) acc[i][j] = fmaf(a[i], bb[j], acc[i][j]);
        }
        __syncthreads();
    }
}

// ------------------------------- prep kernel -------------------------------
__device__ __forceinline__ float fetchW(const float* W_ih, const float* W_hh,
                                        int n, int k) {
    if (k < 257) return W_ih[n * 257 + k];
    if (k >= 272 && k < 784) return W_hh[n * HD + (k - 272)];
    return 0.f;
}

__global__ void __launch_bounds__(256) prep_kernel(
    const float* __restrict__ W_ih, const float* __restrict__ W_hh,
    const float* __restrict__ b_ih, const float* __restrict__ b_hh,
    const float* __restrict__ W_key)
{
    const int stride = gridDim.x * blockDim.x;
    const int gtid = blockIdx.x * blockDim.x + threadIdx.x;

    // gate weight fragments (gate-interleaved columns), hi + lo planes
    for (int idx = gtid; idx < 256 * NCHP * 64; idx += stride) {
        int n8 = idx / (NCHP * 64);
        int rem = idx - n8 * (NCHP * 64);
        int c = rem >> 6;
        int lw = rem & 63;
        int lane = lw >> 1, w = lw & 1;
        int lr = lane >> 2, lc = lane & 3;
        int np = n8 * 8 + lr;            // col'
        int g = np & 3, j = np >> 2;
        int orig = g * 512 + j;
        int k = c * 16 + w * 8 + lc * 2;
        float v0 = (k < 784) ? fetchW(W_ih, W_hh, orig, k) : 0.f;
        float v1 = (k + 1 < 784) ? fetchW(W_ih, W_hh, orig, k + 1) : 0.f;
        __nv_bfloat16 h0 = __float2bfloat16_rn(v0);
        __nv_bfloat16 h1 = __float2bfloat16_rn(v1);
        d_BfH[idx] = (unsigned)__bfloat16_as_ushort(h1) << 16 | __bfloat16_as_ushort(h0);
        d_BfL[idx] = packbf2(v0 - __bfloat162float(h0), v1 - __bfloat162float(h1));
    }
    // W_key fragments (hi + lo)
    for (int idx = gtid; idx < 32 * 32 * 64; idx += stride) {
        int n8 = idx / (32 * 64);
        int rem = idx - n8 * (32 * 64);
        int c = rem >> 6;
        int lw = rem & 63;
        int lane = lw >> 1, w = lw & 1;
        int lr = lane >> 2, lc = lane & 3;
        int n = n8 * 8 + lr;
        int k = c * 16 + w * 8 + lc * 2;
        float v0 = W_key[n * HD + k];
        float v1 = W_key[n * HD + k + 1];
        __nv_bfloat16 h0 = __float2bfloat16_rn(v0);
        __nv_bfloat16 h1 = __float2bfloat16_rn(v1);
        d_WKfH[idx] = (unsigned)__bfloat16_as_ushort(h1) << 16 | __bfloat16_as_ushort(h0);
        d_WKfL[idx] = packbf2(v0 - __bfloat162float(h0), v1 - __bfloat162float(h1));
    }
    // bias (gate-interleaved)
    for (int np = gtid; np < G4; np += stride) {
        int orig = (np & 3) * 512 + (np >> 2);
        d_biasg[np] = b_ih[orig] + b_hh[orig];
    }
    // zero activation fragments (both parities, both planes)
    for (int idx = gtid; idx < 32 * NCHP * 128; idx += stride) {
        d_AfH[0][idx] = 0u; d_AfL[0][idx] = 0u;
        d_AfH[1][idx] = 0u; d_AfL[1][idx] = 0u;
    }
}

// ------------------------------ encoder GEMM -------------------------------
__global__ void __launch_bounds__(256) enc_gemm(const float* __restrict__ X,
                                                const float* __restrict__ W)
{
    __shared__ float As[16 * 64];
    __shared__ float Bs[16 * 128];
    int m0 = blockIdx.x * 64;
    float acc[4][8];
    mm64x128(X, 1024, W, 128, m0, 0, 1024, acc, As, Bs);
    int tx = threadIdx.x & 15, ty = threadIdx.x >> 4;
#pragma unroll
    for (int i = 0; i < 4; i++)
#pragma unroll
        for (int j = 0; j < 8; j++)
            d_zbuf[(size_t)(m0 + ty * 4 + i) * ZD + tx * 8 + j] = acc[i][j];
}

// ------------------------------ context norm -------------------------------
__global__ void __launch_bounds__(128) ctx_norm(const float* __restrict__ gamma,
                                                const float* __restrict__ beta)
{
    int b = blockIdx.x, z = threadIdx.x;
    float v[TD];
    float s = 0.f;
#pragma unroll
    for (int t = 0; t < TD; t++) { v[t] = d_zbuf[((b * TD) + t) * ZD + z]; s += v[t]; }
    float mu = s * (1.f / TD);
    float q = 0.f;
#pragma unroll
    for (int t = 0; t < TD; t++) { float d = v[t] - mu; q += d * d; }
    float inv = rsqrtf(q * (1.f / TD) + 1e-8f);
    float ga = gamma[z], be = beta[z];
#pragma unroll
    for (int t = 0; t < TD; t++)
        d_zbuf[((b * TD) + t) * ZD + z] = (v[t] - mu) * inv * ga + be;
}

// ----------------- precompute attention weights (static in z) --------------
__global__ void __launch_bounds__(256) attn_pre(const float* __restrict__ cgain,
                                                const float* __restrict__ cbias)
{
    __shared__ float zs[TD * ZD];   // 16 KB
    __shared__ float S[TD * TD];    // 4 KB
    const int b = blockIdx.x, tid = threadIdx.x;
    for (int i = tid; i < TD * ZD; i += 256) zs[i] = d_zbuf[(size_t)b * TD * ZD + i];
    __syncthreads();
    const float cg = cgain[0], cb = cbias[0];
    for (int p = tid; p < TD * TD; p += 256) {
        int t = p >> 5, m = p & 31;
        if (m < t) {
            const float* zt = zs + t * ZD;
            const float* zm = zs + m * ZD;
            float s = 0.f;
#pragma unroll 8
            for (int i = 0; i < ZD; i++) s += zt[i] * zm[i];
            S[p] = s;
        }
    }
    __syncthreads();
    if (tid >= 1 && tid < TD) {
        int t = tid;
        const float* row = S + t * TD;
        float mx = -3.4e38f;
        for (int m = 0; m < t; m++) mx = fmaxf(mx, row[m]);
        float sum = 0.f;
        float e[TD];
        for (int m = 0; m < t; m++) { e[m] = __expf(row[m] - mx); sum += e[m]; }
        float inv = __fdividef(1.f, sum);
        float* wkt = d_wk + ((size_t)b * MD + t) * MD;
        float* ckt = d_ck + ((size_t)b * MD + t) * MD;
        for (int m = 0; m < t; m++) {
            wkt[m] = e[m] * inv;
            ckt[m] = sigm(row[m] * cg + cb);
        }
    }
}

// ------------------------- persistent recurrence ---------------------------
__global__ void __launch_bounds__(NT) recur(
    const float* __restrict__ b_key, const float* __restrict__ W_g,
    const float* __restrict__ b_g,   const float* __restrict__ W_y,
    const float* __restrict__ b_y,   void* outp, int out_size)
{
    // A staging: 3 buffers x 3 chunks x 1024 words = 36 KB
    __shared__ __align__(16) unsigned sA[3][3][1024];

    const int tid = threadIdx.x;
    const int bx = blockIdx.x;
    const int lane = tid & 31, wid = tid >> 5;
    const int lr = lane >> 2, lc = lane & 3;

    // ---- Phase A mapping: 8 m-blocks x 16 n-blocks; warp = 1 m16 x 4 n8 ----
    const int mblk = bx >> 4, nblk = bx & 15;
    const int wmm = wid & 3;                 // m16 local
    const int wn  = wid >> 2;                // n8 group (x4)
    const int m16g = mblk * 4 + wmm;

    // A staging mapping: tid<256 stages chunks 0,2 of group; tid>=256 chunk 1
    const int t8      = tid & 255;
    const int a_plane = t8 >> 7;
    const int a_m16A  = mblk * 4 + ((t8 >> 5) & 3);
    const int a_widx  = (t8 & 31) * 4;
    const int a_soff  = a_plane * 512 + ((t8 >> 5) & 3) * 128 + a_widx;

    // B direct-load pointers: 4 n8 per warp, hi + lo planes
    const unsigned* pBH[4];
    const unsigned* pBL[4];
#pragma unroll
    for (int jj = 0; jj < 4; jj++) {
        int n8g = nblk * 16 + wn * 4 + jj;
        pBH[jj] = d_BfH + (size_t)n8g * (NCHP * 64) + lane * 2;
        pBL[jj] = d_BfL + (size_t)n8g * (NCHP * 64) + lane * 2;
    }

    // hoisted gate biases per jj
    float4 bias4[4];
#pragma unroll
    for (int jj = 0; jj < 4; jj++) {
        int n8g = nblk * 16 + wn * 4 + jj;
        int jq = n8g * 2 + (lc >> 1);
        bias4[jj] = *(const float4*)(d_biasg + jq * 4);
    }

    const bool odd = (lc & 1);
    float cc4[4] = {0.f, 0.f, 0.f, 0.f};      // cell state in registers

    for (int t = 0; t < MD; t++) {
        const int cur = t & 1, pn = (t + 1) & 1;
        // ============ Phase A: gate GEMM + fused cell =======================
        {
            const unsigned* aSrc = (a_plane ? d_AfL[cur] : d_AfH[cur]) +
                                   (size_t)a_m16A * (NCHP * 128) + a_widx;
            // prologue: stage groups 0,1
#pragma unroll
            for (int p = 0; p < 2; p++) {
                if (tid < 256) {
                    cpasync16(&sA[p][0][a_soff], aSrc + (p * 3 + 0) * 128);
                    cpasync16(&sA[p][2][a_soff], aSrc + (p * 3 + 2) * 128);
                } else {
                    cpasync16(&sA[p][1][a_soff], aSrc + (p * 3 + 1) * 128);
                }
                CPCOMMIT();
            }
            // B prologue: chunk 0 into regs (1-ahead pipeline)
            unsigned cBH[4][2], cBL[4][2], nBH[4][2], nBL[4][2];
#pragma unroll
            for (int jj = 0; jj < 4; jj++) {
                *(uint2*)cBH[jj] = *(const uint2*)(pBH[jj]);
                *(uint2*)cBL[jj] = *(const uint2*)(pBL[jj]);
            }

            float acc[4][4];
#pragma unroll
            for (int j = 0; j < 4; j++)
#pragma unroll
                for (int r = 0; r < 4; r++) acc[j][r] = 0.f;

            int bufIdx = 0;
#pragma unroll 1
            for (int g = 0; g < NGRP; g++) {
                CPWAIT(1);
                __syncthreads();
                // stage group g+2 into buffer (bufIdx+2)%3
                if (g + 2 < NGRP) {
                    int nbuf = bufIdx + 2; if (nbuf >= 3) nbuf -= 3;
                    int ch0 = (g + 2) * 3;
                    if (tid < 256) {
                        cpasync16(&sA[nbuf][0][a_soff], aSrc + (ch0 + 0) * 128);
                        cpasync16(&sA[nbuf][2][a_soff], aSrc + (ch0 + 2) * 128);
                    } else {
                        cpasync16(&sA[nbuf][1][a_soff], aSrc + (ch0 + 1) * 128);
                    }
                }
                CPCOMMIT();
                const unsigned* base = &sA[bufIdx][0][0];
#pragma unroll
                for (int ccq = 0; ccq < 3; ccq++) {
                    int ch = g * 3 + ccq;
                    // prefetch B chunk ch+1
                    if (ch + 1 < NCHP) {
#pragma unroll
                        for (int jj = 0; jj < 4; jj++) {
                            *(uint2*)nBH[jj] = *(const uint2*)(pBH[jj] + (ch + 1) * 64);
                            *(uint2*)nBL[jj] = *(const uint2*)(pBL[jj] + (ch + 1) * 64);
                        }
                    }
                    unsigned aH[4], aL[4];
                    *(uint4*)aH = *(const uint4*)(base + ccq * 1024 + wmm * 128 + lane * 4);
                    *(uint4*)aL = *(const uint4*)(base + ccq * 1024 + 512 + wmm * 128 + lane * 4);
#pragma unroll
                    for (int jj = 0; jj < 4; jj++) mma16816(acc[jj], aH, cBH[jj]);
#pragma unroll
                    for (int jj = 0; jj < 4; jj++) mma16816(acc[jj], aH, cBL[jj]);
#pragma unroll
                    for (int jj = 0; jj < 4; jj++) mma16816(acc[jj], aL, cBH[jj]);
#pragma unroll
                    for (int jj = 0; jj < 4; jj++) {
                        *(uint2*)cBH[jj] = *(uint2*)nBH[jj];
                        *(uint2*)cBL[jj] = *(uint2*)nBL[jj];
                    }
                }
                bufIdx++; if (bufIdx == 3) bufIdx = 0;
            }

            // ---- fused epilogue: gates + cell update + h frag stores ----
            unsigned* hOutH = d_AfH[pn];
            unsigned* hOutL = d_AfL[pn];
#pragma unroll
            for (int jj = 0; jj < 4; jj++) {
                float a0 = acc[jj][0], a1 = acc[jj][1];
                float a2 = acc[jj][2], a3 = acc[jj][3];
                float p0 = __shfl_xor_sync(0xffffffffu, odd ? a0 : a2, 1);
                float p1 = __shfl_xor_sync(0xffffffffu, odd ? a1 : a3, 1);
                float4 bb4 = bias4[jj];
                float gi, gf, gg, go;
                if (!odd) { gi = a0 + bb4.x; gf = a1 + bb4.y; gg = p0 + bb4.z; go = p1 + bb4.w; }
                else      { gi = p0 + bb4.x; gf = p1 + bb4.y; gg = a2 + bb4.z; go = a3 + bb4.w; }
                float cn = sigm(gf) * cc4[jj] + sigm(gi) * tanhap(gg);
                cc4[jj] = cn;
                float hv = sigm(go) * tanhap(cn);
                int n8g = nblk * 16 + wn * 4 + jj;
                int jq = n8g * 2 + (lc >> 1);
                int row = m16g * 16 + lr + (odd ? 8 : 0);
                d_h[row * HD + jq] = hv;
                __nv_bfloat16 hh = __float2bfloat16_rn(hv);
                __nv_bfloat16 hl = __float2bfloat16_rn(hv - __bfloat162float(hh));
                unsigned uh = (unsigned)__bfloat16_as_ushort(hh);
                unsigned ul = (unsigned)__bfloat16_as_ushort(hl);
                unsigned ph = __shfl_xor_sync(0xffffffffu, uh, 2);
                unsigned pl = __shfl_xor_sync(0xffffffffu, ul, 2);
                if ((lc & 2) == 0) {
                    int kk = jq & 15;
                    int ch = 17 + (jq >> 4);
                    int lane_a = lr * 4 + ((kk & 7) >> 1);
                    int w = (odd ? 1 : 0) + ((kk >> 3) << 1);
                    size_t widx = ((size_t)(m16g * NCHP + ch)) * 128 + lane_a * 4 + w;
                    hOutH[widx] = (ph << 16) | uh;
                    hOutL[widx] = (pl << 16) | ul;
                }
            }
        }
        gridBarrier();  // h visible everywhere

        // ============ Phase C ==============================================
        if (t < TD) {
            if (bx < 64) {  // key_w = relu(h @ W_key^T + b_key), tensor cores
                const int m16 = (bx >> 3) * 4 + (wid & 3);
                const int n8  = (bx & 7) * 4 + (wid >> 2);
                const unsigned* pAH = d_AfH[pn] + ((size_t)m16 * NCHP + 17) * 128 + lane * 4;
                const unsigned* pAL = d_AfL[pn] + ((size_t)m16 * NCHP + 17) * 128 + lane * 4;
                const unsigned* pWH = d_WKfH + (size_t)n8 * (32 * 64) + lane * 2;
                const unsigned* pWL = d_WKfL + (size_t)n8 * (32 * 64) + lane * 2;
                float kacc[4] = {0.f, 0.f, 0.f, 0.f};
                unsigned nAH[4], nAL[4], nBH2[2], nBL2[2];
                *(uint4*)nAH = *(const uint4*)(pAH);
                *(uint4*)nAL = *(const uint4*)(pAL);
                *(uint2*)nBH2 = *(const uint2*)(pWH);
                *(uint2*)nBL2 = *(const uint2*)(pWL);
#pragma unroll 1
                for (int ch = 0; ch < 32; ch++) {
                    unsigned cAH[4], cAL[4], cBH2[2], cBL2[2];
                    *(uint4*)cAH = *(uint4*)nAH; *(uint4*)cAL = *(uint4*)nAL;
                    *(uint2*)cBH2 = *(uint2*)nBH2; *(uint2*)cBL2 = *(uint2*)nBL2;
                    if (ch < 31) {
                        *(uint4*)nAH = *(const uint4*)(pAH + (ch + 1) * 128);
                        *(uint4*)nAL = *(const uint4*)(pAL + (ch + 1) * 128);
                        *(uint2*)nBH2 = *(const uint2*)(pWH + (ch + 1) * 64);
                        *(uint2*)nBL2 = *(const uint2*)(pWL + (ch + 1) * 64);
                    }
                    mma16816(kacc, cAH, cBH2);
                    mma16816(kacc, cAH, cBL2);
                    mma16816(kacc, cAL, cBH2);
                }
                int col = n8 * 8 + lc * 2;
                float bk0 = b_key[col], bk1 = b_key[col + 1];
                int row0 = m16 * 16 + lr;
                float2 v0 = {fmaxf(kacc[0] + bk0, 0.f), fmaxf(kacc[1] + bk1, 0.f)};
                float2 v1 = {fmaxf(kacc[2] + bk0, 0.f), fmaxf(kacc[3] + bk1, 0.f)};
                *(float2*)(d_Mk + ((size_t)row0 * MD + t) * KD + col) = v0;
                *(float2*)(d_Mk + ((size_t)(row0 + 8) * MD + t) * KD + col) = v1;
            } else {  // gate g + attention read -> key_r fragments (parity pn)
                int bb = (bx - 64) * 8 + (wid & 7);
                const float* hb = d_h + (size_t)bb * HD;
                float s = 0.f;
                for (int l = lane; l < HD; l += 32) s += hb[l] * W_g[l];
#pragma unroll
                for (int o = 16; o; o >>= 1) s += __shfl_xor_sync(0xffffffffu, s, o);
                float gv = sigm(s + b_g[0]);
                const float* wkb = d_wk + ((size_t)bb * MD + t) * MD;
                const float* ckb = d_ck + ((size_t)bb * MD + t) * MD;
                const float* mkb = d_Mk + (size_t)bb * MD * KD;
                int m16 = bb >> 4, r = bb & 15;
                unsigned* oH = d_AfH[pn];
                unsigned* oL = d_AfL[pn];
                for (int dp = lane + ((wid >> 3) << 5); dp < 129; dp += 64) {
                    int d0 = dp * 2;
                    float v0 = 0.f, v1 = 0.f;
                    if (d0 < 256) {
                        int m = 0;
                        for (; m + 4 <= t; m += 4) {
                            float w0 = wkb[m], w1 = wkb[m + 1];
                            float w2 = wkb[m + 2], w3 = wkb[m + 3];
                            float x0 = mkb[(m) * KD + d0],     y0 = mkb[(m) * KD + d0 + 1];
                            float x1 = mkb[(m + 1) * KD + d0], y1 = mkb[(m + 1) * KD + d0 + 1];
                            float x2 = mkb[(m + 2) * KD + d0], y2 = mkb[(m + 2) * KD + d0 + 1];
                            float x3 = mkb[(m + 3) * KD + d0], y3 = mkb[(m + 3) * KD + d0 + 1];
                            v0 += w0 * x0 + w1 * x1 + w2 * x2 + w3 * x3;
                            v1 += w0 * y0 + w1 * y1 + w2 * y2 + w3 * y3;
                        }
                        for (; m < t; m++) {
                            float w = wkb[m];
                            v0 += w * mkb[m * KD + d0];
                            v1 += w * mkb[m * KD + d0 + 1];
                        }
                    } else {
                        for (int m = 0; m < t; m++) v0 += wkb[m] * ckb[m];
                    }
                    v0 *= gv; v1 *= gv;
                    __nv_bfloat16 h0 = __float2bfloat16_rn(v0);
                    __nv_bfloat16 h1 = __float2bfloat16_rn(v1);
                    int ch = d0 >> 4, kk = d0 & 15;
                    int lane_a = (r & 7) * 4 + ((kk & 7) >> 1);
                    int w = (r >> 3) + ((kk >> 3) << 1);
                    size_t widx = ((size_t)(m16 * NCHP + ch)) * 128 + lane_a * 4 + w;
                    oH[widx] = (unsigned)__bfloat16_as_ushort(h1) << 16 |
                               __bfloat16_as_ushort(h0);
                    oL[widx] = packbf2(v0 - __bfloat162float(h0),
                                       v1 - __bfloat162float(h1));
                }
            }
            gridBarrier();  // key_r, M_k visible for next step
        } else {  // t == 32: y_lin + argmax
            if (bx >= 64 && bx < 128 && wid < 8) {
                int bb = (bx - 64) * 8 + wid;
                const float* hb = d_h + (size_t)bb * HD;
                float yv[4];
#pragma unroll
                for (int yi = 0; yi < YD; yi++) {
                    float s = 0.f;
                    for (int l = lane; l < HD; l += 32) s += hb[l] * W_y[yi * HD + l];
#pragma unroll
                    for (int o = 16; o; o >>= 1) s += __shfl_xor_sync(0xffffffffu, s, o);
                    yv[yi] = s + b_y[yi];
                }
                if (lane == 0) {
                    int am = 0; float bst = yv[0];
#pragma unroll
                    for (int yi = 1; yi < YD; yi++)
                        if (yv[yi] > bst) { bst = yv[yi]; am = yi; }
                    if (out_size >= BD * YD) {
                        float* of = (float*)outp;
                        of[bb * 4 + 0] = yv[0];
                        of[bb * 4 + 1] = yv[1];
                        of[bb * 4 + 2] = yv[2];
                        of[bb * 4 + 3] = yv[3];
                        if (out_size >= BD * YD + BD) of[BD * YD + bb] = (float)am;
                    } else {
                        ((int*)outp)[bb] = am;
                    }
                }
            }
        }
    }
}

// ------------------------------- launcher ----------------------------------
extern "C" void kernel_launch(void* const* d_in, const int* in_sizes, int n_in,
                              void* d_out, int out_size)
{
    const float* x_seq  = (const float*)d_in[0];
    const float* W_enc  = (const float*)d_in[1];
    const float* gamma  = (const float*)d_in[2];
    const float* beta   = (const float*)d_in[3];
    const float* W_ih   = (const float*)d_in[4];
    const float* W_hh   = (const float*)d_in[5];
    const float* b_ih   = (const float*)d_in[6];
    const float* b_hh   = (const float*)d_in[7];
    const float* W_key  = (const float*)d_in[8];
    const float* b_key  = (const float*)d_in[9];
    const float* W_g    = (const float*)d_in[10];
    const float* b_g    = (const float*)d_in[11];
    const float* cgain  = (const float*)d_in[12];
    const float* cbias  = (const float*)d_in[13];
    const float* W_y    = (const float*)d_in[14];
    const float* b_y    = (const float*)d_in[15];

    prep_kernel<<<1024, 256>>>(W_ih, W_hh, b_ih, b_hh, W_key);
    enc_gemm<<<256, 256>>>(x_seq, W_enc);
    ctx_norm<<<BD, 128>>>(gamma, beta);
    attn_pre<<<BD, 256>>>(cgain, cbias);
    recur<<<NB, NT>>>(b_key, W_g, b_g, W_y, b_y, d_out, out_size);
}

// round 9
// speedup vs baseline: 2.8580x; 1.0281x over previous
#include <cuda_runtime.h>
#include <cuda_bf16.h>
#include <math.h>

// ---------------------------------------------------------------------------
// Model_24730421690434  (R8)
//   B=512, T=32, Z=128, K=256, H=512, 4H=2048, Y=4, M=33
// R8: R7 recur unchanged (B hi+lo 3-term, group-staged A, precomputed attn).
//     NEW: attn_pre warp-parallel softmax (was 50us, serial+spills);
//          encoder GEMM on tensor cores (bf16 3-term split, X converted
//          on the fly).
// ---------------------------------------------------------------------------

#define NB 128
#define NT 512

#define BD 512
#define TD 32
#define ZD 128
#define KD 256
#define HD 512
#define YD 4
#define MD 33
#define G4 2048
#define NCHP 51     // padded chunks (51 = 17*3): 0..16 key_r, 17..48 h, 49..50 zero
#define NGRP 17

// ------------------------------- device state ------------------------------
// Gate weight fragments (gate-interleaved col' = jcol*4+gate), hi and lo:
//   word[(n8*51 + c)*64 + lane*2 + w]
__device__ __align__(256) unsigned d_BfH[256 * NCHP * 64];
__device__ __align__(256) unsigned d_BfL[256 * NCHP * 64];
// W_key fragments: word[(n8*32 + c)*64 + lane*2 + w]
__device__ __align__(256) unsigned d_WKfH[32 * 32 * 64];
__device__ __align__(256) unsigned d_WKfL[32 * 32 * 64];
// W_enc fragments: word[(n8*64 + c)*64 + lane*2 + w], n8<16, c<64
__device__ __align__(256) unsigned d_WEfH[16 * 64 * 64];
__device__ __align__(256) unsigned d_WEfL[16 * 64 * 64];
// Activation fragments, double-buffered by step parity:
//   word[(m16*51 + c)*128 + lane_a*4 + w]
__device__ __align__(256) unsigned d_AfH[2][32 * NCHP * 128];
__device__ __align__(256) unsigned d_AfL[2][32 * NCHP * 128];

__device__ __align__(256) float d_biasg[G4];           // gate-interleaved
__device__ __align__(256) float d_zbuf[BD * TD * ZD];  // normalized z (== M_v)
__device__ __align__(256) float d_h[BD * HD];          // fp32 h
__device__ __align__(256) float d_Mk[(size_t)BD * MD * KD];
__device__ __align__(256) float d_wk[(size_t)BD * MD * MD];  // [b][t][m]
__device__ __align__(256) float d_ck[(size_t)BD * MD * MD];  // [b][t][m]
__device__ unsigned g_cnt;
__device__ unsigned g_gen;

__device__ __forceinline__ float tanhap(float x) {
    float y; asm("tanh.approx.f32 %0, %1;" : "=f"(y) : "f"(x)); return y;
}
__device__ __forceinline__ float sigm(float x) {
    return fmaf(tanhap(x * 0.5f), 0.5f, 0.5f);
}

__device__ __forceinline__ void gridBarrier() {
    __syncthreads();
    if (threadIdx.x == 0) {
        unsigned gen = *(volatile unsigned*)&g_gen;
        __threadfence();
        unsigned t = atomicAdd(&g_cnt, 1u);
        if (t == NB - 1u) {
            g_cnt = 0u;
            __threadfence();
            atomicAdd(&g_gen, 1u);
        } else {
            while (*(volatile unsigned*)&g_gen == gen) { __nanosleep(32); }
        }
        __threadfence();
    }
    __syncthreads();
}

__device__ __forceinline__ void cpasync16(void* dst, const void* src) {
    unsigned saddr = (unsigned)__cvta_generic_to_shared(dst);
    asm volatile("cp.async.cg.shared.global [%0], [%1], 16;\n" ::"r"(saddr), "l"(src));
}
#define CPCOMMIT() asm volatile("cp.async.commit_group;\n" ::)
#define CPWAIT(n)  asm volatile("cp.async.wait_group %0;\n" ::"n"(n))

__device__ __forceinline__ void mma16816(float* d, const unsigned* a, const unsigned* b) {
    asm volatile(
        "mma.sync.aligned.m16n8k16.row.col.f32.bf16.bf16.f32 "
        "{%0,%1,%2,%3},{%4,%5,%6,%7},{%8,%9},{%0,%1,%2,%3};"
        : "+f"(d[0]), "+f"(d[1]), "+f"(d[2]), "+f"(d[3])
        : "r"(a[0]), "r"(a[1]), "r"(a[2]), "r"(a[3]), "r"(b[0]), "r"(b[1]));
}

__device__ __forceinline__ unsigned packbf2(float v0, float v1) {
    unsigned short u0 = __bfloat16_as_ushort(__float2bfloat16_rn(v0));
    unsigned short u1 = __bfloat16_as_ushort(__float2bfloat16_rn(v1));
    return (unsigned)u1 << 16 | u0;
}
// split fp32 pair into bf16 hi word + lo word
__device__ __forceinline__ void splitbf2(float v0, float v1, unsigned& hi, unsigned& lo) {
    __nv_bfloat16 h0 = __float2bfloat16_rn(v0);
    __nv_bfloat16 h1 = __float2bfloat16_rn(v1);
    hi = (unsigned)__bfloat16_as_ushort(h1) << 16 | __bfloat16_as_ushort(h0);
    lo = packbf2(v0 - __bfloat162float(h0), v1 - __bfloat162float(h1));
}

// ------------------------------- prep kernel -------------------------------
__device__ __forceinline__ float fetchW(const float* W_ih, const float* W_hh,
                                        int n, int k) {
    if (k < 257) return W_ih[n * 257 + k];
    if (k >= 272 && k < 784) return W_hh[n * HD + (k - 272)];
    return 0.f;
}

__global__ void __launch_bounds__(256) prep_kernel(
    const float* __restrict__ W_ih, const float* __restrict__ W_hh,
    const float* __restrict__ b_ih, const float* __restrict__ b_hh,
    const float* __restrict__ W_key, const float* __restrict__ W_enc)
{
    const int stride = gridDim.x * blockDim.x;
    const int gtid = blockIdx.x * blockDim.x + threadIdx.x;

    // gate weight fragments (gate-interleaved columns), hi + lo planes
    for (int idx = gtid; idx < 256 * NCHP * 64; idx += stride) {
        int n8 = idx / (NCHP * 64);
        int rem = idx - n8 * (NCHP * 64);
        int c = rem >> 6;
        int lw = rem & 63;
        int lane = lw >> 1, w = lw & 1;
        int lr = lane >> 2, lc = lane & 3;
        int np = n8 * 8 + lr;            // col'
        int g = np & 3, j = np >> 2;
        int orig = g * 512 + j;
        int k = c * 16 + w * 8 + lc * 2;
        float v0 = (k < 784) ? fetchW(W_ih, W_hh, orig, k) : 0.f;
        float v1 = (k + 1 < 784) ? fetchW(W_ih, W_hh, orig, k + 1) : 0.f;
        splitbf2(v0, v1, d_BfH[idx], d_BfL[idx]);
    }
    // W_key fragments (hi + lo)
    for (int idx = gtid; idx < 32 * 32 * 64; idx += stride) {
        int n8 = idx / (32 * 64);
        int rem = idx - n8 * (32 * 64);
        int c = rem >> 6;
        int lw = rem & 63;
        int lane = lw >> 1, w = lw & 1;
        int lr = lane >> 2, lc = lane & 3;
        int n = n8 * 8 + lr;
        int k = c * 16 + w * 8 + lc * 2;
        splitbf2(W_key[n * HD + k], W_key[n * HD + k + 1],
                 d_WKfH[idx], d_WKfL[idx]);
    }
    // W_enc fragments (hi + lo): B[k][n] = W_enc[k*128 + n]
    for (int idx = gtid; idx < 16 * 64 * 64; idx += stride) {
        int n8 = idx / (64 * 64);
        int rem = idx - n8 * (64 * 64);
        int c = rem >> 6;
        int lw = rem & 63;
        int lane = lw >> 1, w = lw & 1;
        int lr = lane >> 2, lc = lane & 3;
        int n = n8 * 8 + lr;
        int k = c * 16 + w * 8 + lc * 2;
        splitbf2(W_enc[k * ZD + n], W_enc[(k + 1) * ZD + n],
                 d_WEfH[idx], d_WEfL[idx]);
    }
    // bias (gate-interleaved)
    for (int np = gtid; np < G4; np += stride) {
        int orig = (np & 3) * 512 + (np >> 2);
        d_biasg[np] = b_ih[orig] + b_hh[orig];
    }
    // zero activation fragments (both parities, both planes)
    for (int idx = gtid; idx < 32 * NCHP * 128; idx += stride) {
        d_AfH[0][idx] = 0u; d_AfL[0][idx] = 0u;
        d_AfH[1][idx] = 0u; d_AfL[1][idx] = 0u;
    }
}

// ------------------- encoder GEMM on tensor cores --------------------------
// z[16384,128] = X[16384,1024] @ W_enc[1024,128]; fp32 X converted on the fly.
__global__ void __launch_bounds__(256) enc_gemm2(const float* __restrict__ X)
{
    const int tid = threadIdx.x;
    const int lane = tid & 31, wid = tid >> 5;
    const int lr = lane >> 2, lc = lane & 3;
    const int m16 = blockIdx.x * 8 + wid;       // 128 blocks x 8 warps = 1024

    const float* xr0 = X + (size_t)(m16 * 16 + lr) * 1024;
    const float* xr1 = xr0 + 8 * 1024;

    float acc[16][4];
#pragma unroll
    for (int n8 = 0; n8 < 16; n8++)
#pragma unroll
        for (int r = 0; r < 4; r++) acc[n8][r] = 0.f;

#pragma unroll 1
    for (int c = 0; c < 64; c++) {
        int k = c * 16 + lc * 2;
        float2 x00 = *(const float2*)(xr0 + k);
        float2 x10 = *(const float2*)(xr1 + k);
        float2 x01 = *(const float2*)(xr0 + k + 8);
        float2 x11 = *(const float2*)(xr1 + k + 8);
        unsigned aH[4], aL[4];
        splitbf2(x00.x, x00.y, aH[0], aL[0]);
        splitbf2(x10.x, x10.y, aH[1], aL[1]);
        splitbf2(x01.x, x01.y, aH[2], aL[2]);
        splitbf2(x11.x, x11.y, aH[3], aL[3]);
#pragma unroll
        for (int n8 = 0; n8 < 16; n8++) {
            const unsigned* pH = d_WEfH + (size_t)(n8 * 64 + c) * 64 + lane * 2;
            const unsigned* pL = d_WEfL + (size_t)(n8 * 64 + c) * 64 + lane * 2;
            unsigned bH[2], bL[2];
            *(uint2*)bH = *(const uint2*)pH;
            *(uint2*)bL = *(const uint2*)pL;
            mma16816(acc[n8], aH, bH);
            mma16816(acc[n8], aH, bL);
            mma16816(acc[n8], aL, bH);
        }
    }
    int row0 = m16 * 16 + lr;
#pragma unroll
    for (int n8 = 0; n8 < 16; n8++) {
        int col = n8 * 8 + lc * 2;
        *(float2*)(d_zbuf + (size_t)row0 * ZD + col)       = make_float2(acc[n8][0], acc[n8][1]);
        *(float2*)(d_zbuf + (size_t)(row0 + 8) * ZD + col) = make_float2(acc[n8][2], acc[n8][3]);
    }
}

// ------------------------------ context norm -------------------------------
__global__ void __launch_bounds__(128) ctx_norm(const float* __restrict__ gamma,
                                                const float* __restrict__ beta)
{
    int b = blockIdx.x, z = threadIdx.x;
    float v[TD];
    float s = 0.f;
#pragma unroll
    for (int t = 0; t < TD; t++) { v[t] = d_zbuf[((b * TD) + t) * ZD + z]; s += v[t]; }
    float mu = s * (1.f / TD);
    float q = 0.f;
#pragma unroll
    for (int t = 0; t < TD; t++) { float d = v[t] - mu; q += d * d; }
    float inv = rsqrtf(q * (1.f / TD) + 1e-8f);
    float ga = gamma[z], be = beta[z];
#pragma unroll
    for (int t = 0; t < TD; t++)
        d_zbuf[((b * TD) + t) * ZD + z] = (v[t] - mu) * inv * ga + be;
}

// ----------------- precompute attention weights (static in z) --------------
// Warp-parallel softmax: warp w handles t = 1 + w + 8*it; lanes cover m.
__global__ void __launch_bounds__(256) attn_pre(const float* __restrict__ cgain,
                                                const float* __restrict__ cbias)
{
    __shared__ float zs[TD * ZD];   // 16 KB
    __shared__ float S[TD * TD];    // 4 KB
    const int b = blockIdx.x, tid = threadIdx.x;
    const int lane = tid & 31, w = tid >> 5;
    for (int i = tid; i < TD * ZD; i += 256) zs[i] = d_zbuf[(size_t)b * TD * ZD + i];
    __syncthreads();
    const float cg = cgain[0], cb = cbias[0];
    for (int p = tid; p < TD * TD; p += 256) {
        int t = p >> 5, m = p & 31;
        if (m < t) {
            const float4* zt = (const float4*)(zs + t * ZD);
            const float4* zm = (const float4*)(zs + m * ZD);
            float s = 0.f;
#pragma unroll
            for (int i = 0; i < ZD / 4; i++) {
                float4 a = zt[i], bq = zm[i];
                s += a.x * bq.x + a.y * bq.y + a.z * bq.z + a.w * bq.w;
            }
            S[p] = s;
        }
    }
    __syncthreads();
#pragma unroll
    for (int it = 0; it < 4; it++) {
        int t = 1 + w + it * 8;
        if (t > 31) break;                      // t=32 never used by Phase C
        float sv = (lane < t) ? S[t * TD + lane] : -3.4e38f;
        float mx = sv;
#pragma unroll
        for (int o = 16; o; o >>= 1) mx = fmaxf(mx, __shfl_xor_sync(0xffffffffu, mx, o));
        float e = (lane < t) ? __expf(sv - mx) : 0.f;
        float sum = e;
#pragma unroll
        for (int o = 16; o; o >>= 1) sum += __shfl_xor_sync(0xffffffffu, sum, o);
        float inv = __fdividef(1.f, sum);
        if (lane < t) {
            d_wk[((size_t)b * MD + t) * MD + lane] = e * inv;
            d_ck[((size_t)b * MD + t) * MD + lane] = sigm(sv * cg + cb);
        }
    }
}

// ------------------------- persistent recurrence ---------------------------
__global__ void __launch_bounds__(NT) recur(
    const float* __restrict__ b_key, const float* __restrict__ W_g,
    const float* __restrict__ b_g,   const float* __restrict__ W_y,
    const float* __restrict__ b_y,   void* outp, int out_size)
{
    // A staging: 3 buffers x 3 chunks x 1024 words = 36 KB
    __shared__ __align__(16) unsigned sA[3][3][1024];

    const int tid = threadIdx.x;
    const int bx = blockIdx.x;
    const int lane = tid & 31, wid = tid >> 5;
    const int lr = lane >> 2, lc = lane & 3;

    // ---- Phase A mapping: 8 m-blocks x 16 n-blocks; warp = 1 m16 x 4 n8 ----
    const int mblk = bx >> 4, nblk = bx & 15;
    const int wmm = wid & 3;                 // m16 local
    const int wn  = wid >> 2;                // n8 group (x4)
    const int m16g = mblk * 4 + wmm;

    // A staging mapping: tid<256 stages chunks 0,2 of group; tid>=256 chunk 1
    const int t8      = tid & 255;
    const int a_plane = t8 >> 7;
    const int a_m16A  = mblk * 4 + ((t8 >> 5) & 3);
    const int a_widx  = (t8 & 31) * 4;
    const int a_soff  = a_plane * 512 + ((t8 >> 5) & 3) * 128 + a_widx;

    // B direct-load pointers: 4 n8 per warp, hi + lo planes
    const unsigned* pBH[4];
    const unsigned* pBL[4];
#pragma unroll
    for (int jj = 0; jj < 4; jj++) {
        int n8g = nblk * 16 + wn * 4 + jj;
        pBH[jj] = d_BfH + (size_t)n8g * (NCHP * 64) + lane * 2;
        pBL[jj] = d_BfL + (size_t)n8g * (NCHP * 64) + lane * 2;
    }

    // hoisted gate biases per jj
    float4 bias4[4];
#pragma unroll
    for (int jj = 0; jj < 4; jj++) {
        int n8g = nblk * 16 + wn * 4 + jj;
        int jq = n8g * 2 + (lc >> 1);
        bias4[jj] = *(const float4*)(d_biasg + jq * 4);
    }

    const bool odd = (lc & 1);
    float cc4[4] = {0.f, 0.f, 0.f, 0.f};      // cell state in registers

    for (int t = 0; t < MD; t++) {
        const int cur = t & 1, pn = (t + 1) & 1;
        // ============ Phase A: gate GEMM + fused cell =======================
        {
            const unsigned* aSrc = (a_plane ? d_AfL[cur] : d_AfH[cur]) +
                                   (size_t)a_m16A * (NCHP * 128) + a_widx;
            // prologue: stage groups 0,1
#pragma unroll
            for (int p = 0; p < 2; p++) {
                if (tid < 256) {
                    cpasync16(&sA[p][0][a_soff], aSrc + (p * 3 + 0) * 128);
                    cpasync16(&sA[p][2][a_soff], aSrc + (p * 3 + 2) * 128);
                } else {
                    cpasync16(&sA[p][1][a_soff], aSrc + (p * 3 + 1) * 128);
                }
                CPCOMMIT();
            }
            // B prologue: chunk 0 into regs (1-ahead pipeline)
            unsigned cBH[4][2], cBL[4][2], nBH[4][2], nBL[4][2];
#pragma unroll
            for (int jj = 0; jj < 4; jj++) {
                *(uint2*)cBH[jj] = *(const uint2*)(pBH[jj]);
                *(uint2*)cBL[jj] = *(const uint2*)(pBL[jj]);
            }

            float acc[4][4];
#pragma unroll
            for (int j = 0; j < 4; j++)
#pragma unroll
                for (int r = 0; r < 4; r++) acc[j][r] = 0.f;

            int bufIdx = 0;
#pragma unroll 1
            for (int g = 0; g < NGRP; g++) {
                CPWAIT(1);
                __syncthreads();
                // stage group g+2 into buffer (bufIdx+2)%3
                if (g + 2 < NGRP) {
                    int nbuf = bufIdx + 2; if (nbuf >= 3) nbuf -= 3;
                    int ch0 = (g + 2) * 3;
                    if (tid < 256) {
                        cpasync16(&sA[nbuf][0][a_soff], aSrc + (ch0 + 0) * 128);
                        cpasync16(&sA[nbuf][2][a_soff], aSrc + (ch0 + 2) * 128);
                    } else {
                        cpasync16(&sA[nbuf][1][a_soff], aSrc + (ch0 + 1) * 128);
                    }
                }
                CPCOMMIT();
                const unsigned* base = &sA[bufIdx][0][0];
#pragma unroll
                for (int ccq = 0; ccq < 3; ccq++) {
                    int ch = g * 3 + ccq;
                    // prefetch B chunk ch+1
                    if (ch + 1 < NCHP) {
#pragma unroll
                        for (int jj = 0; jj < 4; jj++) {
                            *(uint2*)nBH[jj] = *(const uint2*)(pBH[jj] + (ch + 1) * 64);
                            *(uint2*)nBL[jj] = *(const uint2*)(pBL[jj] + (ch + 1) * 64);
                        }
                    }
                    unsigned aH[4], aL[4];
                    *(uint4*)aH = *(const uint4*)(base + ccq * 1024 + wmm * 128 + lane * 4);
                    *(uint4*)aL = *(const uint4*)(base + ccq * 1024 + 512 + wmm * 128 + lane * 4);
#pragma unroll
                    for (int jj = 0; jj < 4; jj++) mma16816(acc[jj], aH, cBH[jj]);
#pragma unroll
                    for (int jj = 0; jj < 4; jj++) mma16816(acc[jj], aH, cBL[jj]);
#pragma unroll
                    for (int jj = 0; jj < 4; jj++) mma16816(acc[jj], aL, cBH[jj]);
#pragma unroll
                    for (int jj = 0; jj < 4; jj++) {
                        *(uint2*)cBH[jj] = *(uint2*)nBH[jj];
                        *(uint2*)cBL[jj] = *(uint2*)nBL[jj];
                    }
                }
                bufIdx++; if (bufIdx == 3) bufIdx = 0;
            }

            // ---- fused epilogue: gates + cell update + h frag stores ----
            unsigned* hOutH = d_AfH[pn];
            unsigned* hOutL = d_AfL[pn];
#pragma unroll
            for (int jj = 0; jj < 4; jj++) {
                float a0 = acc[jj][0], a1 = acc[jj][1];
                float a2 = acc[jj][2], a3 = acc[jj][3];
                float p0 = __shfl_xor_sync(0xffffffffu, odd ? a0 : a2, 1);
                float p1 = __shfl_xor_sync(0xffffffffu, odd ? a1 : a3, 1);
                float4 bb4 = bias4[jj];
                float gi, gf, gg, go;
                if (!odd) { gi = a0 + bb4.x; gf = a1 + bb4.y; gg = p0 + bb4.z; go = p1 + bb4.w; }
                else      { gi = p0 + bb4.x; gf = p1 + bb4.y; gg = a2 + bb4.z; go = a3 + bb4.w; }
                float cn = sigm(gf) * cc4[jj] + sigm(gi) * tanhap(gg);
                cc4[jj] = cn;
                float hv = sigm(go) * tanhap(cn);
                int n8g = nblk * 16 + wn * 4 + jj;
                int jq = n8g * 2 + (lc >> 1);
                int row = m16g * 16 + lr + (odd ? 8 : 0);
                d_h[row * HD + jq] = hv;
                __nv_bfloat16 hh = __float2bfloat16_rn(hv);
                __nv_bfloat16 hl = __float2bfloat16_rn(hv - __bfloat162float(hh));
                unsigned uh = (unsigned)__bfloat16_as_ushort(hh);
                unsigned ul = (unsigned)__bfloat16_as_ushort(hl);
                unsigned ph = __shfl_xor_sync(0xffffffffu, uh, 2);
                unsigned pl = __shfl_xor_sync(0xffffffffu, ul, 2);
                if ((lc & 2) == 0) {
                    int kk = jq & 15;
                    int ch = 17 + (jq >> 4);
                    int lane_a = lr * 4 + ((kk & 7) >> 1);
                    int w = (odd ? 1 : 0) + ((kk >> 3) << 1);
                    size_t widx = ((size_t)(m16g * NCHP + ch)) * 128 + lane_a * 4 + w;
                    hOutH[widx] = (ph << 16) | uh;
                    hOutL[widx] = (pl << 16) | ul;
                }
            }
        }
        gridBarrier();  // h visible everywhere

        // ============ Phase C ==============================================
        if (t < TD) {
            if (bx < 64) {  // key_w = relu(h @ W_key^T + b_key), tensor cores
                const int m16 = (bx >> 3) * 4 + (wid & 3);
                const int n8  = (bx & 7) * 4 + (wid >> 2);
                const unsigned* pAH = d_AfH[pn] + ((size_t)m16 * NCHP + 17) * 128 + lane * 4;
                const unsigned* pAL = d_AfL[pn] + ((size_t)m16 * NCHP + 17) * 128 + lane * 4;
                const unsigned* pWH = d_WKfH + (size_t)n8 * (32 * 64) + lane * 2;
                const unsigned* pWL = d_WKfL + (size_t)n8 * (32 * 64) + lane * 2;
                float kacc[4] = {0.f, 0.f, 0.f, 0.f};
                unsigned nAH[4], nAL[4], nBH2[2], nBL2[2];
                *(uint4*)nAH = *(const uint4*)(pAH);
                *(uint4*)nAL = *(const uint4*)(pAL);
                *(uint2*)nBH2 = *(const uint2*)(pWH);
                *(uint2*)nBL2 = *(const uint2*)(pWL);
#pragma unroll 1
                for (int ch = 0; ch < 32; ch++) {
                    unsigned cAH[4], cAL[4], cBH2[2], cBL2[2];
                    *(uint4*)cAH = *(uint4*)nAH; *(uint4*)cAL = *(uint4*)nAL;
                    *(uint2*)cBH2 = *(uint2*)nBH2; *(uint2*)cBL2 = *(uint2*)nBL2;
                    if (ch < 31) {
                        *(uint4*)nAH = *(const uint4*)(pAH + (ch + 1) * 128);
                        *(uint4*)nAL = *(const uint4*)(pAL + (ch + 1) * 128);
                        *(uint2*)nBH2 = *(const uint2*)(pWH + (ch + 1) * 64);
                        *(uint2*)nBL2 = *(const uint2*)(pWL + (ch + 1) * 64);
                    }
                    mma16816(kacc, cAH, cBH2);
                    mma16816(kacc, cAH, cBL2);
                    mma16816(kacc, cAL, cBH2);
                }
                int col = n8 * 8 + lc * 2;
                float bk0 = b_key[col], bk1 = b_key[col + 1];
                int row0 = m16 * 16 + lr;
                float2 v0 = {fmaxf(kacc[0] + bk0, 0.f), fmaxf(kacc[1] + bk1, 0.f)};
                float2 v1 = {fmaxf(kacc[2] + bk0, 0.f), fmaxf(kacc[3] + bk1, 0.f)};
                *(float2*)(d_Mk + ((size_t)row0 * MD + t) * KD + col) = v0;
                *(float2*)(d_Mk + ((size_t)(row0 + 8) * MD + t) * KD + col) = v1;
            } else {  // gate g + attention read -> key_r fragments (parity pn)
                int bb = (bx - 64) * 8 + (wid & 7);
                const float* hb = d_h + (size_t)bb * HD;
                float s = 0.f;
                for (int l = lane; l < HD; l += 32) s += hb[l] * W_g[l];
#pragma unroll
                for (int o = 16; o; o >>= 1) s += __shfl_xor_sync(0xffffffffu, s, o);
                float gv = sigm(s + b_g[0]);
                const float* wkb = d_wk + ((size_t)bb * MD + t) * MD;
                const float* ckb = d_ck + ((size_t)bb * MD + t) * MD;
                const float* mkb = d_Mk + (size_t)bb * MD * KD;
                int m16 = bb >> 4, r = bb & 15;
                unsigned* oH = d_AfH[pn];
                unsigned* oL = d_AfL[pn];
                for (int dp = lane + ((wid >> 3) << 5); dp < 129; dp += 64) {
                    int d0 = dp * 2;
                    float v0 = 0.f, v1 = 0.f;
                    if (d0 < 256) {
                        int m = 0;
                        for (; m + 4 <= t; m += 4) {
                            float w0 = wkb[m], w1 = wkb[m + 1];
                            float w2 = wkb[m + 2], w3 = wkb[m + 3];
                            float x0 = mkb[(m) * KD + d0],     y0 = mkb[(m) * KD + d0 + 1];
                            float x1 = mkb[(m + 1) * KD + d0], y1 = mkb[(m + 1) * KD + d0 + 1];
                            float x2 = mkb[(m + 2) * KD + d0], y2 = mkb[(m + 2) * KD + d0 + 1];
                            float x3 = mkb[(m + 3) * KD + d0], y3 = mkb[(m + 3) * KD + d0 + 1];
                            v0 += w0 * x0 + w1 * x1 + w2 * x2 + w3 * x3;
                            v1 += w0 * y0 + w1 * y1 + w2 * y2 + w3 * y3;
                        }
                        for (; m < t; m++) {
                            float w = wkb[m];
                            v0 += w * mkb[m * KD + d0];
                            v1 += w * mkb[m * KD + d0 + 1];
                        }
                    } else {
                        for (int m = 0; m < t; m++) v0 += wkb[m] * ckb[m];
                    }
                    v0 *= gv; v1 *= gv;
                    __nv_bfloat16 h0 = __float2bfloat16_rn(v0);
                    __nv_bfloat16 h1 = __float2bfloat16_rn(v1);
                    int ch = d0 >> 4, kk = d0 & 15;
                    int lane_a = (r & 7) * 4 + ((kk & 7) >> 1);
                    int w = (r >> 3) + ((kk >> 3) << 1);
                    size_t widx = ((size_t)(m16 * NCHP + ch)) * 128 + lane_a * 4 + w;
                    oH[widx] = (unsigned)__bfloat16_as_ushort(h1) << 16 |
                               __bfloat16_as_ushort(h0);
                    oL[widx] = packbf2(v0 - __bfloat162float(h0),
                                       v1 - __bfloat162float(h1));
                }
            }
            gridBarrier();  // key_r, M_k visible for next step
        } else {  // t == 32: y_lin + argmax
            if (bx >= 64 && bx < 128 && wid < 8) {
                int bb = (bx - 64) * 8 + wid;
                const float* hb = d_h + (size_t)bb * HD;
                float yv[4];
#pragma unroll
                for (int yi = 0; yi < YD; yi++) {
                    float s = 0.f;
                    for (int l = lane; l < HD; l += 32) s += hb[l] * W_y[yi * HD + l];
#pragma unroll
                    for (int o = 16; o; o >>= 1) s += __shfl_xor_sync(0xffffffffu, s, o);
                    yv[yi] = s + b_y[yi];
                }
                if (lane == 0) {
                    int am = 0; float bst = yv[0];
#pragma unroll
                    for (int yi = 1; yi < YD; yi++)
                        if (yv[yi] > bst) { bst = yv[yi]; am = yi; }
                    if (out_size >= BD * YD) {
                        float* of = (float*)outp;
                        of[bb * 4 + 0] = yv[0];
                        of[bb * 4 + 1] = yv[1];
                        of[bb * 4 + 2] = yv[2];
                        of[bb * 4 + 3] = yv[3];
                        if (out_size >= BD * YD + BD) of[BD * YD + bb] = (float)am;
                    } else {
                        ((int*)outp)[bb] = am;
                    }
                }
            }
        }
    }
}

// ------------------------------- launcher ----------------------------------
extern "C" void kernel_launch(void* const* d_in, const int* in_sizes, int n_in,
                              void* d_out, int out_size)
{
    const float* x_seq  = (const float*)d_in[0];
    const float* W_enc  = (const float*)d_in[1];
    const float* gamma  = (const float*)d_in[2];
    const float* beta   = (const float*)d_in[3];
    const float* W_ih   = (const float*)d_in[4];
    const float* W_hh   = (const float*)d_in[5];
    const float* b_ih   = (const float*)d_in[6];
    const float* b_hh   = (const float*)d_in[7];
    const float* W_key  = (const float*)d_in[8];
    const float* b_key  = (const float*)d_in[9];
    const float* W_g    = (const float*)d_in[10];
    const float* b_g    = (const float*)d_in[11];
    const float* cgain  = (const float*)d_in[12];
    const float* cbias  = (const float*)d_in[13];
    const float* W_y    = (const float*)d_in[14];
    const float* b_y    = (const float*)d_in[15];

    prep_kernel<<<1024, 256>>>(W_ih, W_hh, b_ih, b_hh, W_key, W_enc);
    enc_gemm2<<<128, 256>>>(x_seq);
    ctx_norm<<<BD, 128>>>(gamma, beta);
    attn_pre<<<BD, 256>>>(cgain, cbias);
    recur<<<NB, NT>>>(b_key, W_g, b_g, W_y, b_y, d_out, out_size);
}

// round 10
// speedup vs baseline: 3.0908x; 1.0815x over previous
#include <cuda_runtime.h>
#include <cuda_bf16.h>
#include <math.h>

// ---------------------------------------------------------------------------
// Model_24730421690434  (R9)
//   B=512, T=32, Z=128, K=256, H=512, 4H=2048, Y=4, M=33
// R9: latency fixes — padded-stride attn_pre (kills 32-way bank conflicts),
//     hierarchical 2-level grid barrier (kills single-address atomic funnel),
//     dual-chain key_w GEMM (halves exposed L2 latency). Phase A unchanged.
// ---------------------------------------------------------------------------

#define NB 128
#define NT 512

#define BD 512
#define TD 32
#define ZD 128
#define KD 256
#define HD 512
#define YD 4
#define MD 33
#define G4 2048
#define NCHP 51     // padded chunks (51 = 17*3): 0..16 key_r, 17..48 h, 49..50 zero
#define NGRP 17
#define ZP 129      // padded z row stride (bank-conflict-free)

// ------------------------------- device state ------------------------------
// Gate weight fragments (gate-interleaved col' = jcol*4+gate), hi and lo:
//   word[(n8*51 + c)*64 + lane*2 + w]
__device__ __align__(256) unsigned d_BfH[256 * NCHP * 64];
__device__ __align__(256) unsigned d_BfL[256 * NCHP * 64];
// W_key fragments: word[(n8*32 + c)*64 + lane*2 + w]
__device__ __align__(256) unsigned d_WKfH[32 * 32 * 64];
__device__ __align__(256) unsigned d_WKfL[32 * 32 * 64];
// W_enc fragments: word[(n8*64 + c)*64 + lane*2 + w], n8<16, c<64
__device__ __align__(256) unsigned d_WEfH[16 * 64 * 64];
__device__ __align__(256) unsigned d_WEfL[16 * 64 * 64];
// Activation fragments, double-buffered by step parity:
//   word[(m16*51 + c)*128 + lane_a*4 + w]
__device__ __align__(256) unsigned d_AfH[2][32 * NCHP * 128];
__device__ __align__(256) unsigned d_AfL[2][32 * NCHP * 128];

__device__ __align__(256) float d_biasg[G4];           // gate-interleaved
__device__ __align__(256) float d_zbuf[BD * TD * ZD];  // normalized z (== M_v)
__device__ __align__(256) float d_h[BD * HD];          // fp32 h
__device__ __align__(256) float d_Mk[(size_t)BD * MD * KD];
__device__ __align__(256) float d_wk[(size_t)BD * MD * MD];  // [b][t][m]
__device__ __align__(256) float d_ck[(size_t)BD * MD * MD];  // [b][t][m]
// hierarchical barrier state (one counter per 128B line)
__device__ unsigned g_cnt1[8 * 32];
__device__ unsigned g_cnt2;
__device__ unsigned g_gen;

__device__ __forceinline__ float tanhap(float x) {
    float y; asm("tanh.approx.f32 %0, %1;" : "=f"(y) : "f"(x)); return y;
}
__device__ __forceinline__ float sigm(float x) {
    return fmaf(tanhap(x * 0.5f), 0.5f, 0.5f);
}

// 2-level sense-reversal grid barrier: 8 group counters (16 arrivals each)
// feed 1 master counter; avoids 128-deep single-address atomic serialization.
__device__ __forceinline__ void gridBarrier() {
    __syncthreads();
    if (threadIdx.x == 0) {
        const int grp = (blockIdx.x & 7) * 32;
        unsigned gen = *(volatile unsigned*)&g_gen;
        __threadfence();
        if (atomicAdd(&g_cnt1[grp], 1u) == 15u) {
            g_cnt1[grp] = 0u;
            __threadfence();
            if (atomicAdd(&g_cnt2, 1u) == 7u) {
                g_cnt2 = 0u;
                __threadfence();
                atomicAdd(&g_gen, 1u);
            }
        }
        while (*(volatile unsigned*)&g_gen == gen) { __nanosleep(64); }
        __threadfence();
    }
    __syncthreads();
}

__device__ __forceinline__ void cpasync16(void* dst, const void* src) {
    unsigned saddr = (unsigned)__cvta_generic_to_shared(dst);
    asm volatile("cp.async.cg.shared.global [%0], [%1], 16;\n" ::"r"(saddr), "l"(src));
}
#define CPCOMMIT() asm volatile("cp.async.commit_group;\n" ::)
#define CPWAIT(n)  asm volatile("cp.async.wait_group %0;\n" ::"n"(n))

__device__ __forceinline__ void mma16816(float* d, const unsigned* a, const unsigned* b) {
    asm volatile(
        "mma.sync.aligned.m16n8k16.row.col.f32.bf16.bf16.f32 "
        "{%0,%1,%2,%3},{%4,%5,%6,%7},{%8,%9},{%0,%1,%2,%3};"
        : "+f"(d[0]), "+f"(d[1]), "+f"(d[2]), "+f"(d[3])
        : "r"(a[0]), "r"(a[1]), "r"(a[2]), "r"(a[3]), "r"(b[0]), "r"(b[1]));
}

__device__ __forceinline__ unsigned packbf2(float v0, float v1) {
    unsigned short u0 = __bfloat16_as_ushort(__float2bfloat16_rn(v0));
    unsigned short u1 = __bfloat16_as_ushort(__float2bfloat16_rn(v1));
    return (unsigned)u1 << 16 | u0;
}
__device__ __forceinline__ void splitbf2(float v0, float v1, unsigned& hi, unsigned& lo) {
    __nv_bfloat16 h0 = __float2bfloat16_rn(v0);
    __nv_bfloat16 h1 = __float2bfloat16_rn(v1);
    hi = (unsigned)__bfloat16_as_ushort(h1) << 16 | __bfloat16_as_ushort(h0);
    lo = packbf2(v0 - __bfloat162float(h0), v1 - __bfloat162float(h1));
}

// ------------------------------- prep kernel -------------------------------
__device__ __forceinline__ float fetchW(const float* W_ih, const float* W_hh,
                                        int n, int k) {
    if (k < 257) return W_ih[n * 257 + k];
    if (k >= 272 && k < 784) return W_hh[n * HD + (k - 272)];
    return 0.f;
}

__global__ void __launch_bounds__(256) prep_kernel(
    const float* __restrict__ W_ih, const float* __restrict__ W_hh,
    const float* __restrict__ b_ih, const float* __restrict__ b_hh,
    const float* __restrict__ W_key, const float* __restrict__ W_enc)
{
    const int stride = gridDim.x * blockDim.x;
    const int gtid = blockIdx.x * blockDim.x + threadIdx.x;

    for (int idx = gtid; idx < 256 * NCHP * 64; idx += stride) {
        int n8 = idx / (NCHP * 64);
        int rem = idx - n8 * (NCHP * 64);
        int c = rem >> 6;
        int lw = rem & 63;
        int lane = lw >> 1, w = lw & 1;
        int lr = lane >> 2, lc = lane & 3;
        int np = n8 * 8 + lr;
        int g = np & 3, j = np >> 2;
        int orig = g * 512 + j;
        int k = c * 16 + w * 8 + lc * 2;
        float v0 = (k < 784) ? fetchW(W_ih, W_hh, orig, k) : 0.f;
        float v1 = (k + 1 < 784) ? fetchW(W_ih, W_hh, orig, k + 1) : 0.f;
        splitbf2(v0, v1, d_BfH[idx], d_BfL[idx]);
    }
    for (int idx = gtid; idx < 32 * 32 * 64; idx += stride) {
        int n8 = idx / (32 * 64);
        int rem = idx - n8 * (32 * 64);
        int c = rem >> 6;
        int lw = rem & 63;
        int lane = lw >> 1, w = lw & 1;
        int lr = lane >> 2, lc = lane & 3;
        int n = n8 * 8 + lr;
        int k = c * 16 + w * 8 + lc * 2;
        splitbf2(W_key[n * HD + k], W_key[n * HD + k + 1],
                 d_WKfH[idx], d_WKfL[idx]);
    }
    for (int idx = gtid; idx < 16 * 64 * 64; idx += stride) {
        int n8 = idx / (64 * 64);
        int rem = idx - n8 * (64 * 64);
        int c = rem >> 6;
        int lw = rem & 63;
        int lane = lw >> 1, w = lw & 1;
        int lr = lane >> 2, lc = lane & 3;
        int n = n8 * 8 + lr;
        int k = c * 16 + w * 8 + lc * 2;
        splitbf2(W_enc[k * ZD + n], W_enc[(k + 1) * ZD + n],
                 d_WEfH[idx], d_WEfL[idx]);
    }
    for (int np = gtid; np < G4; np += stride) {
        int orig = (np & 3) * 512 + (np >> 2);
        d_biasg[np] = b_ih[orig] + b_hh[orig];
    }
    for (int idx = gtid; idx < 32 * NCHP * 128; idx += stride) {
        d_AfH[0][idx] = 0u; d_AfL[0][idx] = 0u;
        d_AfH[1][idx] = 0u; d_AfL[1][idx] = 0u;
    }
}

// ------------------- encoder GEMM on tensor cores --------------------------
__global__ void __launch_bounds__(256) enc_gemm2(const float* __restrict__ X)
{
    const int tid = threadIdx.x;
    const int lane = tid & 31, wid = tid >> 5;
    const int lr = lane >> 2, lc = lane & 3;
    const int m16 = blockIdx.x * 8 + wid;

    const float* xr0 = X + (size_t)(m16 * 16 + lr) * 1024;
    const float* xr1 = xr0 + 8 * 1024;

    float acc[16][4];
#pragma unroll
    for (int n8 = 0; n8 < 16; n8++)
#pragma unroll
        for (int r = 0; r < 4; r++) acc[n8][r] = 0.f;

#pragma unroll 1
    for (int c = 0; c < 64; c++) {
        int k = c * 16 + lc * 2;
        float2 x00 = *(const float2*)(xr0 + k);
        float2 x10 = *(const float2*)(xr1 + k);
        float2 x01 = *(const float2*)(xr0 + k + 8);
        float2 x11 = *(const float2*)(xr1 + k + 8);
        unsigned aH[4], aL[4];
        splitbf2(x00.x, x00.y, aH[0], aL[0]);
        splitbf2(x10.x, x10.y, aH[1], aL[1]);
        splitbf2(x01.x, x01.y, aH[2], aL[2]);
        splitbf2(x11.x, x11.y, aH[3], aL[3]);
#pragma unroll
        for (int n8 = 0; n8 < 16; n8++) {
            const unsigned* pH = d_WEfH + (size_t)(n8 * 64 + c) * 64 + lane * 2;
            const unsigned* pL = d_WEfL + (size_t)(n8 * 64 + c) * 64 + lane * 2;
            unsigned bH[2], bL[2];
            *(uint2*)bH = *(const uint2*)pH;
            *(uint2*)bL = *(const uint2*)pL;
            mma16816(acc[n8], aH, bH);
            mma16816(acc[n8], aH, bL);
            mma16816(acc[n8], aL, bH);
        }
    }
    int row0 = m16 * 16 + lr;
#pragma unroll
    for (int n8 = 0; n8 < 16; n8++) {
        int col = n8 * 8 + lc * 2;
        *(float2*)(d_zbuf + (size_t)row0 * ZD + col)       = make_float2(acc[n8][0], acc[n8][1]);
        *(float2*)(d_zbuf + (size_t)(row0 + 8) * ZD + col) = make_float2(acc[n8][2], acc[n8][3]);
    }
}

// ------------------------------ context norm -------------------------------
__global__ void __launch_bounds__(128) ctx_norm(const float* __restrict__ gamma,
                                                const float* __restrict__ beta)
{
    int b = blockIdx.x, z = threadIdx.x;
    float v[TD];
    float s = 0.f;
#pragma unroll
    for (int t = 0; t < TD; t++) { v[t] = d_zbuf[((b * TD) + t) * ZD + z]; s += v[t]; }
    float mu = s * (1.f / TD);
    float q = 0.f;
#pragma unroll
    for (int t = 0; t < TD; t++) { float d = v[t] - mu; q += d * d; }
    float inv = rsqrtf(q * (1.f / TD) + 1e-8f);
    float ga = gamma[z], be = beta[z];
#pragma unroll
    for (int t = 0; t < TD; t++)
        d_zbuf[((b * TD) + t) * ZD + z] = (v[t] - mu) * inv * ga + be;
}

// ----------------- precompute attention weights (static in z) --------------
// z rows padded to stride ZP=129 floats: cross-row reads hit distinct banks.
__global__ void __launch_bounds__(256) attn_pre(const float* __restrict__ cgain,
                                                const float* __restrict__ cbias)
{
    __shared__ float zs[TD * ZP];   // ~16.5 KB, padded stride
    __shared__ float S[TD * TD];    // 4 KB
    const int b = blockIdx.x, tid = threadIdx.x;
    const int lane = tid & 31, w = tid >> 5;
    for (int i = tid; i < TD * ZD; i += 256) {
        int t = i >> 7, z = i & 127;
        zs[t * ZP + z] = d_zbuf[(size_t)b * TD * ZD + i];
    }
    __syncthreads();
    const float cg = cgain[0], cb = cbias[0];
    for (int p = tid; p < TD * TD; p += 256) {
        int t = p >> 5, m = p & 31;   // warp-uniform t, lane-varying m
        if (m < t) {
            const float* zt = zs + t * ZP;   // broadcast
            const float* zm = zs + m * ZP;   // conflict-free (odd stride)
            float s = 0.f;
#pragma unroll 8
            for (int i = 0; i < ZD; i++) s += zt[i] * zm[i];
            S[p] = s;
        }
    }
    __syncthreads();
#pragma unroll
    for (int it = 0; it < 4; it++) {
        int t = 1 + w + it * 8;
        if (t > 31) break;
        float sv = (lane < t) ? S[t * TD + lane] : -3.4e38f;
        float mx = sv;
#pragma unroll
        for (int o = 16; o; o >>= 1) mx = fmaxf(mx, __shfl_xor_sync(0xffffffffu, mx, o));
        float e = (lane < t) ? __expf(sv - mx) : 0.f;
        float sum = e;
#pragma unroll
        for (int o = 16; o; o >>= 1) sum += __shfl_xor_sync(0xffffffffu, sum, o);
        float inv = __fdividef(1.f, sum);
        if (lane < t) {
            d_wk[((size_t)b * MD + t) * MD + lane] = e * inv;
            d_ck[((size_t)b * MD + t) * MD + lane] = sigm(sv * cg + cb);
        }
    }
}

// ------------------------- persistent recurrence ---------------------------
__global__ void __launch_bounds__(NT) recur(
    const float* __restrict__ b_key, const float* __restrict__ W_g,
    const float* __restrict__ b_g,   const float* __restrict__ W_y,
    const float* __restrict__ b_y,   void* outp, int out_size)
{
    // A staging: 3 buffers x 3 chunks x 1024 words = 36 KB
    __shared__ __align__(16) unsigned sA[3][3][1024];

    const int tid = threadIdx.x;
    const int bx = blockIdx.x;
    const int lane = tid & 31, wid = tid >> 5;
    const int lr = lane >> 2, lc = lane & 3;

    const int mblk = bx >> 4, nblk = bx & 15;
    const int wmm = wid & 3;
    const int wn  = wid >> 2;
    const int m16g = mblk * 4 + wmm;

    const int t8      = tid & 255;
    const int a_plane = t8 >> 7;
    const int a_m16A  = mblk * 4 + ((t8 >> 5) & 3);
    const int a_widx  = (t8 & 31) * 4;
    const int a_soff  = a_plane * 512 + ((t8 >> 5) & 3) * 128 + a_widx;

    const unsigned* pBH[4];
    const unsigned* pBL[4];
#pragma unroll
    for (int jj = 0; jj < 4; jj++) {
        int n8g = nblk * 16 + wn * 4 + jj;
        pBH[jj] = d_BfH + (size_t)n8g * (NCHP * 64) + lane * 2;
        pBL[jj] = d_BfL + (size_t)n8g * (NCHP * 64) + lane * 2;
    }

    float4 bias4[4];
#pragma unroll
    for (int jj = 0; jj < 4; jj++) {
        int n8g = nblk * 16 + wn * 4 + jj;
        int jq = n8g * 2 + (lc >> 1);
        bias4[jj] = *(const float4*)(d_biasg + jq * 4);
    }

    const bool odd = (lc & 1);
    float cc4[4] = {0.f, 0.f, 0.f, 0.f};

    for (int t = 0; t < MD; t++) {
        const int cur = t & 1, pn = (t + 1) & 1;
        // ============ Phase A: gate GEMM + fused cell =======================
        {
            const unsigned* aSrc = (a_plane ? d_AfL[cur] : d_AfH[cur]) +
                                   (size_t)a_m16A * (NCHP * 128) + a_widx;
#pragma unroll
            for (int p = 0; p < 2; p++) {
                if (tid < 256) {
                    cpasync16(&sA[p][0][a_soff], aSrc + (p * 3 + 0) * 128);
                    cpasync16(&sA[p][2][a_soff], aSrc + (p * 3 + 2) * 128);
                } else {
                    cpasync16(&sA[p][1][a_soff], aSrc + (p * 3 + 1) * 128);
                }
                CPCOMMIT();
            }
            unsigned cBH[4][2], cBL[4][2], nBH[4][2], nBL[4][2];
#pragma unroll
            for (int jj = 0; jj < 4; jj++) {
                *(uint2*)cBH[jj] = *(const uint2*)(pBH[jj]);
                *(uint2*)cBL[jj] = *(const uint2*)(pBL[jj]);
            }

            float acc[4][4];
#pragma unroll
            for (int j = 0; j < 4; j++)
#pragma unroll
                for (int r = 0; r < 4; r++) acc[j][r] = 0.f;

            int bufIdx = 0;
#pragma unroll 1
            for (int g = 0; g < NGRP; g++) {
                CPWAIT(1);
                __syncthreads();
                if (g + 2 < NGRP) {
                    int nbuf = bufIdx + 2; if (nbuf >= 3) nbuf -= 3;
                    int ch0 = (g + 2) * 3;
                    if (tid < 256) {
                        cpasync16(&sA[nbuf][0][a_soff], aSrc + (ch0 + 0) * 128);
                        cpasync16(&sA[nbuf][2][a_soff], aSrc + (ch0 + 2) * 128);
                    } else {
                        cpasync16(&sA[nbuf][1][a_soff], aSrc + (ch0 + 1) * 128);
                    }
                }
                CPCOMMIT();
                const unsigned* base = &sA[bufIdx][0][0];
#pragma unroll
                for (int ccq = 0; ccq < 3; ccq++) {
                    int ch = g * 3 + ccq;
                    if (ch + 1 < NCHP) {
#pragma unroll
                        for (int jj = 0; jj < 4; jj++) {
                            *(uint2*)nBH[jj] = *(const uint2*)(pBH[jj] + (ch + 1) * 64);
                            *(uint2*)nBL[jj] = *(const uint2*)(pBL[jj] + (ch + 1) * 64);
                        }
                    }
                    unsigned aH[4], aL[4];
                    *(uint4*)aH = *(const uint4*)(base + ccq * 1024 + wmm * 128 + lane * 4);
                    *(uint4*)aL = *(const uint4*)(base + ccq * 1024 + 512 + wmm * 128 + lane * 4);
#pragma unroll
                    for (int jj = 0; jj < 4; jj++) mma16816(acc[jj], aH, cBH[jj]);
#pragma unroll
                    for (int jj = 0; jj < 4; jj++) mma16816(acc[jj], aH, cBL[jj]);
#pragma unroll
                    for (int jj = 0; jj < 4; jj++) mma16816(acc[jj], aL, cBH[jj]);
#pragma unroll
                    for (int jj = 0; jj < 4; jj++) {
                        *(uint2*)cBH[jj] = *(uint2*)nBH[jj];
                        *(uint2*)cBL[jj] = *(uint2*)nBL[jj];
                    }
                }
                bufIdx++; if (bufIdx == 3) bufIdx = 0;
            }

            // ---- fused epilogue: gates + cell update + h frag stores ----
            unsigned* hOutH = d_AfH[pn];
            unsigned* hOutL = d_AfL[pn];
#pragma unroll
            for (int jj = 0; jj < 4; jj++) {
                float a0 = acc[jj][0], a1 = acc[jj][1];
                float a2 = acc[jj][2], a3 = acc[jj][3];
                float p0 = __shfl_xor_sync(0xffffffffu, odd ? a0 : a2, 1);
                float p1 = __shfl_xor_sync(0xffffffffu, odd ? a1 : a3, 1);
                float4 bb4 = bias4[jj];
                float gi, gf, gg, go;
                if (!odd) { gi = a0 + bb4.x; gf = a1 + bb4.y; gg = p0 + bb4.z; go = p1 + bb4.w; }
                else      { gi = p0 + bb4.x; gf = p1 + bb4.y; gg = a2 + bb4.z; go = a3 + bb4.w; }
                float cn = sigm(gf) * cc4[jj] + sigm(gi) * tanhap(gg);
                cc4[jj] = cn;
                float hv = sigm(go) * tanhap(cn);
                int n8g = nblk * 16 + wn * 4 + jj;
                int jq = n8g * 2 + (lc >> 1);
                int row = m16g * 16 + lr + (odd ? 8 : 0);
                d_h[row * HD + jq] = hv;
                __nv_bfloat16 hh = __float2bfloat16_rn(hv);
                __nv_bfloat16 hl = __float2bfloat16_rn(hv - __bfloat162float(hh));
                unsigned uh = (unsigned)__bfloat16_as_ushort(hh);
                unsigned ul = (unsigned)__bfloat16_as_ushort(hl);
                unsigned ph = __shfl_xor_sync(0xffffffffu, uh, 2);
                unsigned pl = __shfl_xor_sync(0xffffffffu, ul, 2);
                if ((lc & 2) == 0) {
                    int kk = jq & 15;
                    int ch = 17 + (jq >> 4);
                    int lane_a = lr * 4 + ((kk & 7) >> 1);
                    int w = (odd ? 1 : 0) + ((kk >> 3) << 1);
                    size_t widx = ((size_t)(m16g * NCHP + ch)) * 128 + lane_a * 4 + w;
                    hOutH[widx] = (ph << 16) | uh;
                    hOutL[widx] = (pl << 16) | ul;
                }
            }
        }
        gridBarrier();  // h visible everywhere

        // ============ Phase C ==============================================
        if (t < TD) {
            if (bx < 64) {  // key_w = relu(h @ W_key^T + b_key), dual-chain
                const int m16 = (bx >> 3) * 4 + (wid & 3);
                const int n8  = (bx & 7) * 4 + (wid >> 2);
                const unsigned* pAH = d_AfH[pn] + ((size_t)m16 * NCHP + 17) * 128 + lane * 4;
                const unsigned* pAL = d_AfL[pn] + ((size_t)m16 * NCHP + 17) * 128 + lane * 4;
                const unsigned* pWH = d_WKfH + (size_t)n8 * (32 * 64) + lane * 2;
                const unsigned* pWL = d_WKfL + (size_t)n8 * (32 * 64) + lane * 2;
                float ka[4] = {0.f, 0.f, 0.f, 0.f};
                float kb[4] = {0.f, 0.f, 0.f, 0.f};
                unsigned cAH0[4], cAL0[4], cW0H[2], cW0L[2];
                unsigned cAH1[4], cAL1[4], cW1H[2], cW1L[2];
                *(uint4*)cAH0 = *(const uint4*)(pAH);
                *(uint4*)cAL0 = *(const uint4*)(pAL);
                *(uint2*)cW0H = *(const uint2*)(pWH);
                *(uint2*)cW0L = *(const uint2*)(pWL);
                *(uint4*)cAH1 = *(const uint4*)(pAH + 16 * 128);
                *(uint4*)cAL1 = *(const uint4*)(pAL + 16 * 128);
                *(uint2*)cW1H = *(const uint2*)(pWH + 16 * 64);
                *(uint2*)cW1L = *(const uint2*)(pWL + 16 * 64);
#pragma unroll 1
                for (int ch = 0; ch < 16; ch++) {
                    unsigned nAH0[4], nAL0[4], nW0H[2], nW0L[2];
                    unsigned nAH1[4], nAL1[4], nW1H[2], nW1L[2];
                    if (ch < 15) {
                        *(uint4*)nAH0 = *(const uint4*)(pAH + (ch + 1) * 128);
                        *(uint4*)nAL0 = *(const uint4*)(pAL + (ch + 1) * 128);
                        *(uint2*)nW0H = *(const uint2*)(pWH + (ch + 1) * 64);
                        *(uint2*)nW0L = *(const uint2*)(pWL + (ch + 1) * 64);
                        *(uint4*)nAH1 = *(const uint4*)(pAH + (ch + 17) * 128);
                        *(uint4*)nAL1 = *(const uint4*)(pAL + (ch + 17) * 128);
                        *(uint2*)nW1H = *(const uint2*)(pWH + (ch + 17) * 64);
                        *(uint2*)nW1L = *(const uint2*)(pWL + (ch + 17) * 64);
                    }
                    mma16816(ka, cAH0, cW0H);
                    mma16816(kb, cAH1, cW1H);
                    mma16816(ka, cAH0, cW0L);
                    mma16816(kb, cAH1, cW1L);
                    mma16816(ka, cAL0, cW0H);
                    mma16816(kb, cAL1, cW1H);
                    if (ch < 15) {
                        *(uint4*)cAH0 = *(uint4*)nAH0; *(uint4*)cAL0 = *(uint4*)nAL0;
                        *(uint2*)cW0H = *(uint2*)nW0H; *(uint2*)cW0L = *(uint2*)nW0L;
                        *(uint4*)cAH1 = *(uint4*)nAH1; *(uint4*)cAL1 = *(uint4*)nAL1;
                        *(uint2*)cW1H = *(uint2*)nW1H; *(uint2*)cW1L = *(uint2*)nW1L;
                    }
                }
#pragma unroll
                for (int r = 0; r < 4; r++) ka[r] += kb[r];
                int col = n8 * 8 + lc * 2;
                float bk0 = b_key[col], bk1 = b_key[col + 1];
                int row0 = m16 * 16 + lr;
                float2 v0 = {fmaxf(ka[0] + bk0, 0.f), fmaxf(ka[1] + bk1, 0.f)};
                float2 v1 = {fmaxf(ka[2] + bk0, 0.f), fmaxf(ka[3] + bk1, 0.f)};
                *(float2*)(d_Mk + ((size_t)row0 * MD + t) * KD + col) = v0;
                *(float2*)(d_Mk + ((size_t)(row0 + 8) * MD + t) * KD + col) = v1;
            } else {  // gate g + attention read -> key_r fragments (parity pn)
                int bb = (bx - 64) * 8 + (wid & 7);
                const float* hb = d_h + (size_t)bb * HD;
                float s = 0.f;
                for (int l = lane; l < HD; l += 32) s += hb[l] * W_g[l];
#pragma unroll
                for (int o = 16; o; o >>= 1) s += __shfl_xor_sync(0xffffffffu, s, o);
                float gv = sigm(s + b_g[0]);
                const float* wkb = d_wk + ((size_t)bb * MD + t) * MD;
                const float* ckb = d_ck + ((size_t)bb * MD + t) * MD;
                const float* mkb = d_Mk + (size_t)bb * MD * KD;
                int m16 = bb >> 4, r = bb & 15;
                unsigned* oH = d_AfH[pn];
                unsigned* oL = d_AfL[pn];
                for (int dp = lane + ((wid >> 3) << 5); dp < 129; dp += 64) {
                    int d0 = dp * 2;
                    float v0 = 0.f, v1 = 0.f;
                    if (d0 < 256) {
                        int m = 0;
                        for (; m + 4 <= t; m += 4) {
                            float w0 = wkb[m], w1 = wkb[m + 1];
                            float w2 = wkb[m + 2], w3 = wkb[m + 3];
                            float x0 = mkb[(m) * KD + d0],     y0 = mkb[(m) * KD + d0 + 1];
                            float x1 = mkb[(m + 1) * KD + d0], y1 = mkb[(m + 1) * KD + d0 + 1];
                            float x2 = mkb[(m + 2) * KD + d0], y2 = mkb[(m + 2) * KD + d0 + 1];
                            float x3 = mkb[(m + 3) * KD + d0], y3 = mkb[(m + 3) * KD + d0 + 1];
                            v0 += w0 * x0 + w1 * x1 + w2 * x2 + w3 * x3;
                            v1 += w0 * y0 + w1 * y1 + w2 * y2 + w3 * y3;
                        }
                        for (; m < t; m++) {
                            float w = wkb[m];
                            v0 += w * mkb[m * KD + d0];
                            v1 += w * mkb[m * KD + d0 + 1];
                        }
                    } else {
                        for (int m = 0; m < t; m++) v0 += wkb[m] * ckb[m];
                    }
                    v0 *= gv; v1 *= gv;
                    __nv_bfloat16 h0 = __float2bfloat16_rn(v0);
                    __nv_bfloat16 h1 = __float2bfloat16_rn(v1);
                    int ch = d0 >> 4, kk = d0 & 15;
                    int lane_a = (r & 7) * 4 + ((kk & 7) >> 1);
                    int w = (r >> 3) + ((kk >> 3) << 1);
                    size_t widx = ((size_t)(m16 * NCHP + ch)) * 128 + lane_a * 4 + w;
                    oH[widx] = (unsigned)__bfloat16_as_ushort(h1) << 16 |
                               __bfloat16_as_ushort(h0);
                    oL[widx] = packbf2(v0 - __bfloat162float(h0),
                                       v1 - __bfloat162float(h1));
                }
            }
            gridBarrier();  // key_r, M_k visible for next step
        } else {  // t == 32: y_lin + argmax
            if (bx >= 64 && bx < 128 && wid < 8) {
                int bb = (bx - 64) * 8 + wid;
                const float* hb = d_h + (size_t)bb * HD;
                float yv[4];
#pragma unroll
                for (int yi = 0; yi < YD; yi++) {
                    float s = 0.f;
                    for (int l = lane; l < HD; l += 32) s += hb[l] * W_y[yi * HD + l];
#pragma unroll
                    for (int o = 16; o; o >>= 1) s += __shfl_xor_sync(0xffffffffu, s, o);
                    yv[yi] = s + b_y[yi];
                }
                if (lane == 0) {
                    int am = 0; float bst = yv[0];
#pragma unroll
                    for (int yi = 1; yi < YD; yi++)
                        if (yv[yi] > bst) { bst = yv[yi]; am = yi; }
                    if (out_size >= BD * YD) {
                        float* of = (float*)outp;
                        of[bb * 4 + 0] = yv[0];
                        of[bb * 4 + 1] = yv[1];
                        of[bb * 4 + 2] = yv[2];
                        of[bb * 4 + 3] = yv[3];
                        if (out_size >= BD * YD + BD) of[BD * YD + bb] = (float)am;
                    } else {
                        ((int*)outp)[bb] = am;
                    }
                }
            }
        }
    }
}

// ------------------------------- launcher ----------------------------------
extern "C" void kernel_launch(void* const* d_in, const int* in_sizes, int n_in,
                              void* d_out, int out_size)
{
    const float* x_seq  = (const float*)d_in[0];
    const float* W_enc  = (const float*)d_in[1];
    const float* gamma  = (const float*)d_in[2];
    const float* beta   = (const float*)d_in[3];
    const float* W_ih   = (const float*)d_in[4];
    const float* W_hh   = (const float*)d_in[5];
    const float* b_ih   = (const float*)d_in[6];
    const float* b_hh   = (const float*)d_in[7];
    const float* W_key  = (const float*)d_in[8];
    const float* b_key  = (const float*)d_in[9];
    const float* W_g    = (const float*)d_in[10];
    const float* b_g    = (const float*)d_in[11];
    const float* cgain  = (const float*)d_in[12];
    const float* cbias  = (const float*)d_in[13];
    const float* W_y    = (const float*)d_in[14];
    const float* b_y    = (const float*)d_in[15];

    prep_kernel<<<1024, 256>>>(W_ih, W_hh, b_ih, b_hh, W_key, W_enc);
    enc_gemm2<<<128, 256>>>(x_seq);
    ctx_norm<<<BD, 128>>>(gamma, beta);
    attn_pre<<<BD, 256>>>(cgain, cbias);
    recur<<<NB, NT>>>(b_key, W_g, b_g, W_y, b_y, d_out, out_size);
}

// round 11
// speedup vs baseline: 3.3461x; 1.0826x over previous
#include <cuda_runtime.h>
#include <cuda_bf16.h>
#include <math.h>

// ---------------------------------------------------------------------------
// Model_24730421690434  (R10)
//   B=512, T=32, Z=128, K=256, H=512, 4H=2048, Y=4, M=33
// R10: Phase A B-operand joins the cp.async pipeline (3 groups x 3 chunks,
//      108 KB dynamic smem, zero LDG in mainloop); ctx_norm fused into
//      attn precompute (normalized z never leaves smem).
// ---------------------------------------------------------------------------

#define NB 128
#define NT 512

#define BD 512
#define TD 32
#define ZD 128
#define KD 256
#define HD 512
#define YD 4
#define MD 33
#define G4 2048
#define NCHP 51     // padded chunks (51 = 17*3): 0..16 key_r, 17..48 h, 49..50 zero
#define NGRP 17
#define ZP 129      // padded z row stride (bank-conflict-free)
#define CHW 3072    // words per staged chunk: A[0,1024) | Bhi[1024,2048) | Blo[2048,3072)
#define SMEM_RECUR (9 * CHW * 4)   // 3 groups x 3 chunks

// ------------------------------- device state ------------------------------
__device__ __align__(256) unsigned d_BfH[256 * NCHP * 64];
__device__ __align__(256) unsigned d_BfL[256 * NCHP * 64];
__device__ __align__(256) unsigned d_WKfH[32 * 32 * 64];
__device__ __align__(256) unsigned d_WKfL[32 * 32 * 64];
__device__ __align__(256) unsigned d_WEfH[16 * 64 * 64];
__device__ __align__(256) unsigned d_WEfL[16 * 64 * 64];
__device__ __align__(256) unsigned d_AfH[2][32 * NCHP * 128];
__device__ __align__(256) unsigned d_AfL[2][32 * NCHP * 128];

__device__ __align__(256) float d_biasg[G4];
__device__ __align__(256) float d_zbuf[BD * TD * ZD];  // RAW encoder output
__device__ __align__(256) float d_h[BD * HD];
__device__ __align__(256) float d_Mk[(size_t)BD * MD * KD];
__device__ __align__(256) float d_wk[(size_t)BD * MD * MD];
__device__ __align__(256) float d_ck[(size_t)BD * MD * MD];
__device__ unsigned g_cnt1[8 * 32];
__device__ unsigned g_cnt2;
__device__ unsigned g_gen;

__device__ __forceinline__ float tanhap(float x) {
    float y; asm("tanh.approx.f32 %0, %1;" : "=f"(y) : "f"(x)); return y;
}
__device__ __forceinline__ float sigm(float x) {
    return fmaf(tanhap(x * 0.5f), 0.5f, 0.5f);
}

__device__ __forceinline__ void gridBarrier() {
    __syncthreads();
    if (threadIdx.x == 0) {
        const int grp = (blockIdx.x & 7) * 32;
        unsigned gen = *(volatile unsigned*)&g_gen;
        __threadfence();
        if (atomicAdd(&g_cnt1[grp], 1u) == 15u) {
            g_cnt1[grp] = 0u;
            __threadfence();
            if (atomicAdd(&g_cnt2, 1u) == 7u) {
                g_cnt2 = 0u;
                __threadfence();
                atomicAdd(&g_gen, 1u);
            }
        }
        while (*(volatile unsigned*)&g_gen == gen) { __nanosleep(64); }
        __threadfence();
    }
    __syncthreads();
}

__device__ __forceinline__ void cpasync16(void* dst, const void* src) {
    unsigned saddr = (unsigned)__cvta_generic_to_shared(dst);
    asm volatile("cp.async.cg.shared.global [%0], [%1], 16;\n" ::"r"(saddr), "l"(src));
}
#define CPCOMMIT() asm volatile("cp.async.commit_group;\n" ::)
#define CPWAIT(n)  asm volatile("cp.async.wait_group %0;\n" ::"n"(n))

__device__ __forceinline__ void mma16816(float* d, const unsigned* a, const unsigned* b) {
    asm volatile(
        "mma.sync.aligned.m16n8k16.row.col.f32.bf16.bf16.f32 "
        "{%0,%1,%2,%3},{%4,%5,%6,%7},{%8,%9},{%0,%1,%2,%3};"
        : "+f"(d[0]), "+f"(d[1]), "+f"(d[2]), "+f"(d[3])
        : "r"(a[0]), "r"(a[1]), "r"(a[2]), "r"(a[3]), "r"(b[0]), "r"(b[1]));
}

__device__ __forceinline__ unsigned packbf2(float v0, float v1) {
    unsigned short u0 = __bfloat16_as_ushort(__float2bfloat16_rn(v0));
    unsigned short u1 = __bfloat16_as_ushort(__float2bfloat16_rn(v1));
    return (unsigned)u1 << 16 | u0;
}
__device__ __forceinline__ void splitbf2(float v0, float v1, unsigned& hi, unsigned& lo) {
    __nv_bfloat16 h0 = __float2bfloat16_rn(v0);
    __nv_bfloat16 h1 = __float2bfloat16_rn(v1);
    hi = (unsigned)__bfloat16_as_ushort(h1) << 16 | __bfloat16_as_ushort(h0);
    lo = packbf2(v0 - __bfloat162float(h0), v1 - __bfloat162float(h1));
}

// ------------------------------- prep kernel -------------------------------
__device__ __forceinline__ float fetchW(const float* W_ih, const float* W_hh,
                                        int n, int k) {
    if (k < 257) return W_ih[n * 257 + k];
    if (k >= 272 && k < 784) return W_hh[n * HD + (k - 272)];
    return 0.f;
}

__global__ void __launch_bounds__(256) prep_kernel(
    const float* __restrict__ W_ih, const float* __restrict__ W_hh,
    const float* __restrict__ b_ih, const float* __restrict__ b_hh,
    const float* __restrict__ W_key, const float* __restrict__ W_enc)
{
    const int stride = gridDim.x * blockDim.x;
    const int gtid = blockIdx.x * blockDim.x + threadIdx.x;

    for (int idx = gtid; idx < 256 * NCHP * 64; idx += stride) {
        int n8 = idx / (NCHP * 64);
        int rem = idx - n8 * (NCHP * 64);
        int c = rem >> 6;
        int lw = rem & 63;
        int lane = lw >> 1, w = lw & 1;
        int lr = lane >> 2, lc = lane & 3;
        int np = n8 * 8 + lr;
        int g = np & 3, j = np >> 2;
        int orig = g * 512 + j;
        int k = c * 16 + w * 8 + lc * 2;
        float v0 = (k < 784) ? fetchW(W_ih, W_hh, orig, k) : 0.f;
        float v1 = (k + 1 < 784) ? fetchW(W_ih, W_hh, orig, k + 1) : 0.f;
        splitbf2(v0, v1, d_BfH[idx], d_BfL[idx]);
    }
    for (int idx = gtid; idx < 32 * 32 * 64; idx += stride) {
        int n8 = idx / (32 * 64);
        int rem = idx - n8 * (32 * 64);
        int c = rem >> 6;
        int lw = rem & 63;
        int lane = lw >> 1, w = lw & 1;
        int lr = lane >> 2, lc = lane & 3;
        int n = n8 * 8 + lr;
        int k = c * 16 + w * 8 + lc * 2;
        splitbf2(W_key[n * HD + k], W_key[n * HD + k + 1],
                 d_WKfH[idx], d_WKfL[idx]);
    }
    for (int idx = gtid; idx < 16 * 64 * 64; idx += stride) {
        int n8 = idx / (64 * 64);
        int rem = idx - n8 * (64 * 64);
        int c = rem >> 6;
        int lw = rem & 63;
        int lane = lw >> 1, w = lw & 1;
        int lr = lane >> 2, lc = lane & 3;
        int n = n8 * 8 + lr;
        int k = c * 16 + w * 8 + lc * 2;
        splitbf2(W_enc[k * ZD + n], W_enc[(k + 1) * ZD + n],
                 d_WEfH[idx], d_WEfL[idx]);
    }
    for (int np = gtid; np < G4; np += stride) {
        int orig = (np & 3) * 512 + (np >> 2);
        d_biasg[np] = b_ih[orig] + b_hh[orig];
    }
    for (int idx = gtid; idx < 32 * NCHP * 128; idx += stride) {
        d_AfH[0][idx] = 0u; d_AfL[0][idx] = 0u;
        d_AfH[1][idx] = 0u; d_AfL[1][idx] = 0u;
    }
}

// ------------------- encoder GEMM on tensor cores --------------------------
__global__ void __launch_bounds__(256) enc_gemm2(const float* __restrict__ X)
{
    const int tid = threadIdx.x;
    const int lane = tid & 31, wid = tid >> 5;
    const int lr = lane >> 2, lc = lane & 3;
    const int m16 = blockIdx.x * 8 + wid;

    const float* xr0 = X + (size_t)(m16 * 16 + lr) * 1024;
    const float* xr1 = xr0 + 8 * 1024;

    float acc[16][4];
#pragma unroll
    for (int n8 = 0; n8 < 16; n8++)
#pragma unroll
        for (int r = 0; r < 4; r++) acc[n8][r] = 0.f;

#pragma unroll 1
    for (int c = 0; c < 64; c++) {
        int k = c * 16 + lc * 2;
        float2 x00 = *(const float2*)(xr0 + k);
        float2 x10 = *(const float2*)(xr1 + k);
        float2 x01 = *(const float2*)(xr0 + k + 8);
        float2 x11 = *(const float2*)(xr1 + k + 8);
        unsigned aH[4], aL[4];
        splitbf2(x00.x, x00.y, aH[0], aL[0]);
        splitbf2(x10.x, x10.y, aH[1], aL[1]);
        splitbf2(x01.x, x01.y, aH[2], aL[2]);
        splitbf2(x11.x, x11.y, aH[3], aL[3]);
#pragma unroll
        for (int n8 = 0; n8 < 16; n8++) {
            const unsigned* pH = d_WEfH + (size_t)(n8 * 64 + c) * 64 + lane * 2;
            const unsigned* pL = d_WEfL + (size_t)(n8 * 64 + c) * 64 + lane * 2;
            unsigned bH[2], bL[2];
            *(uint2*)bH = *(const uint2*)pH;
            *(uint2*)bL = *(const uint2*)pL;
            mma16816(acc[n8], aH, bH);
            mma16816(acc[n8], aH, bL);
            mma16816(acc[n8], aL, bH);
        }
    }
    int row0 = m16 * 16 + lr;
#pragma unroll
    for (int n8 = 0; n8 < 16; n8++) {
        int col = n8 * 8 + lc * 2;
        *(float2*)(d_zbuf + (size_t)row0 * ZD + col)       = make_float2(acc[n8][0], acc[n8][1]);
        *(float2*)(d_zbuf + (size_t)(row0 + 8) * ZD + col) = make_float2(acc[n8][2], acc[n8][3]);
    }
}

// ------- fused context norm + attention precompute (per batch block) -------
__global__ void __launch_bounds__(256) norm_attn(
    const float* __restrict__ gamma, const float* __restrict__ beta,
    const float* __restrict__ cgain, const float* __restrict__ cbias)
{
    __shared__ float zs[TD * ZP];   // normalized z, padded stride
    __shared__ float S[TD * TD];
    const int b = blockIdx.x, tid = threadIdx.x;
    const int lane = tid & 31, w = tid >> 5;

    // normalize: thread z (tid<128) holds the T-column
    if (tid < 128) {
        float v[TD];
        float s = 0.f;
#pragma unroll
        for (int t = 0; t < TD; t++) {
            v[t] = d_zbuf[((size_t)(b * TD) + t) * ZD + tid];
            s += v[t];
        }
        float mu = s * (1.f / TD);
        float q = 0.f;
#pragma unroll
        for (int t = 0; t < TD; t++) { float d = v[t] - mu; q += d * d; }
        float inv = rsqrtf(q * (1.f / TD) + 1e-8f);
        float ga = gamma[tid], be = beta[tid];
#pragma unroll
        for (int t = 0; t < TD; t++)
            zs[t * ZP + tid] = (v[t] - mu) * inv * ga + be;
    }
    __syncthreads();

    const float cg = cgain[0], cb = cbias[0];
    for (int p = tid; p < TD * TD; p += 256) {
        int t = p >> 5, m = p & 31;
        if (m < t) {
            const float* zt = zs + t * ZP;   // broadcast (warp-uniform t)
            const float* zm = zs + m * ZP;   // conflict-free (odd stride)
            float s = 0.f;
#pragma unroll 8
            for (int i = 0; i < ZD; i++) s += zt[i] * zm[i];
            S[p] = s;
        }
    }
    __syncthreads();
#pragma unroll
    for (int it = 0; it < 4; it++) {
        int t = 1 + w + it * 8;
        if (t > 31) break;
        float sv = (lane < t) ? S[t * TD + lane] : -3.4e38f;
        float mx = sv;
#pragma unroll
        for (int o = 16; o; o >>= 1) mx = fmaxf(mx, __shfl_xor_sync(0xffffffffu, mx, o));
        float e = (lane < t) ? __expf(sv - mx) : 0.f;
        float sum = e;
#pragma unroll
        for (int o = 16; o; o >>= 1) sum += __shfl_xor_sync(0xffffffffu, sum, o);
        float inv = __fdividef(1.f, sum);
        if (lane < t) {
            d_wk[((size_t)b * MD + t) * MD + lane] = e * inv;
            d_ck[((size_t)b * MD + t) * MD + lane] = sigm(sv * cg + cb);
        }
    }
}

// ------------------------- persistent recurrence ---------------------------
__global__ void __launch_bounds__(NT) recur(
    const float* __restrict__ b_key, const float* __restrict__ W_g,
    const float* __restrict__ b_g,   const float* __restrict__ W_y,
    const float* __restrict__ b_y,   void* outp, int out_size)
{
    extern __shared__ unsigned sS[];   // 3 groups x 3 chunks x 3072 words

    const int tid = threadIdx.x;
    const int bx = blockIdx.x;
    const int lane = tid & 31, wid = tid >> 5;
    const int lr = lane >> 2, lc = lane & 3;

    const int mblk = bx >> 4, nblk = bx & 15;
    const int wmm = wid & 3;
    const int wn  = wid >> 2;
    const int m16g = mblk * 4 + wmm;

    // A staging (tid<256): covers 2 planes x 4 m16 x 128 words
    const int t8      = tid & 255;
    const int a_plane = t8 >> 7;
    const int a_m16A  = mblk * 4 + ((t8 >> 5) & 3);
    const int a_widx  = (t8 & 31) * 4;
    const int a_soff  = a_plane * 512 + ((t8 >> 5) & 3) * 128 + a_widx;

    // B staging (all 512 threads): 2 planes x 16 n8 x 64 words
    const int b_plane = tid >> 8;
    const int b_n8l   = (tid >> 4) & 15;
    const int b_w4    = (tid & 15) * 4;
    const int b_soff  = 1024 + b_plane * 1024 + b_n8l * 64 + b_w4;
    const unsigned* bSrc = (b_plane ? d_BfL : d_BfH) +
                           (size_t)(nblk * 16 + b_n8l) * (NCHP * 64) + b_w4;

    float4 bias4[4];
#pragma unroll
    for (int jj = 0; jj < 4; jj++) {
        int n8g = nblk * 16 + wn * 4 + jj;
        int jq = n8g * 2 + (lc >> 1);
        bias4[jj] = *(const float4*)(d_biasg + jq * 4);
    }

    const bool odd = (lc & 1);
    float cc4[4] = {0.f, 0.f, 0.f, 0.f};

    for (int t = 0; t < MD; t++) {
        const int cur = t & 1, pn = (t + 1) & 1;
        // ============ Phase A: gate GEMM + fused cell =======================
        {
            const unsigned* aSrc = (a_plane ? d_AfL[cur] : d_AfH[cur]) +
                                   (size_t)a_m16A * (NCHP * 128) + a_widx;
            // prologue: stage groups 0,1
#pragma unroll
            for (int p = 0; p < 2; p++) {
#pragma unroll
                for (int ccq = 0; ccq < 3; ccq++) {
                    int ch = p * 3 + ccq;
                    unsigned* dst = sS + (p * 3 + ccq) * CHW;
                    if (tid < 256) cpasync16(dst + a_soff, aSrc + ch * 128);
                    cpasync16(dst + b_soff, bSrc + ch * 64);
                }
                CPCOMMIT();
            }

            float acc[4][4];
#pragma unroll
            for (int j = 0; j < 4; j++)
#pragma unroll
                for (int r = 0; r < 4; r++) acc[j][r] = 0.f;

            int bufIdx = 0;
#pragma unroll 1
            for (int g = 0; g < NGRP; g++) {
                CPWAIT(1);
                __syncthreads();
                {
                    int sg = g + 2;
                    int nbuf = bufIdx + 2; if (nbuf >= 3) nbuf -= 3;
                    if (sg < NGRP) {
#pragma unroll
                        for (int ccq = 0; ccq < 3; ccq++) {
                            int ch = sg * 3 + ccq;
                            unsigned* dst = sS + (nbuf * 3 + ccq) * CHW;
                            if (tid < 256) cpasync16(dst + a_soff, aSrc + ch * 128);
                            cpasync16(dst + b_soff, bSrc + ch * 64);
                        }
                    }
                    CPCOMMIT();
                }
                const unsigned* gb = sS + bufIdx * 3 * CHW;
#pragma unroll
                for (int ccq = 0; ccq < 3; ccq++) {
                    const unsigned* base = gb + ccq * CHW;
                    unsigned aH[4], aL[4];
                    *(uint4*)aH = *(const uint4*)(base + wmm * 128 + lane * 4);
                    *(uint4*)aL = *(const uint4*)(base + 512 + wmm * 128 + lane * 4);
                    unsigned bH[4][2], bL[4][2];
#pragma unroll
                    for (int jj = 0; jj < 4; jj++) {
                        *(uint2*)bH[jj] = *(const uint2*)(base + 1024 + (wn * 4 + jj) * 64 + lane * 2);
                        *(uint2*)bL[jj] = *(const uint2*)(base + 2048 + (wn * 4 + jj) * 64 + lane * 2);
                    }
#pragma unroll
                    for (int jj = 0; jj < 4; jj++) mma16816(acc[jj], aH, bH[jj]);
#pragma unroll
                    for (int jj = 0; jj < 4; jj++) mma16816(acc[jj], aH, bL[jj]);
#pragma unroll
                    for (int jj = 0; jj < 4; jj++) mma16816(acc[jj], aL, bH[jj]);
                }
                bufIdx++; if (bufIdx == 3) bufIdx = 0;
            }

            // ---- fused epilogue: gates + cell update + h frag stores ----
            unsigned* hOutH = d_AfH[pn];
            unsigned* hOutL = d_AfL[pn];
#pragma unroll
            for (int jj = 0; jj < 4; jj++) {
                float a0 = acc[jj][0], a1 = acc[jj][1];
                float a2 = acc[jj][2], a3 = acc[jj][3];
                float p0 = __shfl_xor_sync(0xffffffffu, odd ? a0 : a2, 1);
                float p1 = __shfl_xor_sync(0xffffffffu, odd ? a1 : a3, 1);
                float4 bb4 = bias4[jj];
                float gi, gf, gg, go;
                if (!odd) { gi = a0 + bb4.x; gf = a1 + bb4.y; gg = p0 + bb4.z; go = p1 + bb4.w; }
                else      { gi = p0 + bb4.x; gf = p1 + bb4.y; gg = a2 + bb4.z; go = a3 + bb4.w; }
                float cn = sigm(gf) * cc4[jj] + sigm(gi) * tanhap(gg);
                cc4[jj] = cn;
                float hv = sigm(go) * tanhap(cn);
                int n8g = nblk * 16 + wn * 4 + jj;
                int jq = n8g * 2 + (lc >> 1);
                int row = m16g * 16 + lr + (odd ? 8 : 0);
                d_h[row * HD + jq] = hv;
                __nv_bfloat16 hh = __float2bfloat16_rn(hv);
                __nv_bfloat16 hl = __float2bfloat16_rn(hv - __bfloat162float(hh));
                unsigned uh = (unsigned)__bfloat16_as_ushort(hh);
                unsigned ul = (unsigned)__bfloat16_as_ushort(hl);
                unsigned ph = __shfl_xor_sync(0xffffffffu, uh, 2);
                unsigned pl = __shfl_xor_sync(0xffffffffu, ul, 2);
                if ((lc & 2) == 0) {
                    int kk = jq & 15;
                    int ch = 17 + (jq >> 4);
                    int lane_a = lr * 4 + ((kk & 7) >> 1);
                    int w = (odd ? 1 : 0) + ((kk >> 3) << 1);
                    size_t widx = ((size_t)(m16g * NCHP + ch)) * 128 + lane_a * 4 + w;
                    hOutH[widx] = (ph << 16) | uh;
                    hOutL[widx] = (pl << 16) | ul;
                }
            }
        }
        gridBarrier();  // h visible everywhere

        // ============ Phase C ==============================================
        if (t < TD) {
            if (bx < 64) {  // key_w = relu(h @ W_key^T + b_key), dual-chain
                const int m16 = (bx >> 3) * 4 + (wid & 3);
                const int n8  = (bx & 7) * 4 + (wid >> 2);
                const unsigned* pAH = d_AfH[pn] + ((size_t)m16 * NCHP + 17) * 128 + lane * 4;
                const unsigned* pAL = d_AfL[pn] + ((size_t)m16 * NCHP + 17) * 128 + lane * 4;
                const unsigned* pWH = d_WKfH + (size_t)n8 * (32 * 64) + lane * 2;
                const unsigned* pWL = d_WKfL + (size_t)n8 * (32 * 64) + lane * 2;
                float ka[4] = {0.f, 0.f, 0.f, 0.f};
                float kb[4] = {0.f, 0.f, 0.f, 0.f};
                unsigned cAH0[4], cAL0[4], cW0H[2], cW0L[2];
                unsigned cAH1[4], cAL1[4], cW1H[2], cW1L[2];
                *(uint4*)cAH0 = *(const uint4*)(pAH);
                *(uint4*)cAL0 = *(const uint4*)(pAL);
                *(uint2*)cW0H = *(const uint2*)(pWH);
                *(uint2*)cW0L = *(const uint2*)(pWL);
                *(uint4*)cAH1 = *(const uint4*)(pAH + 16 * 128);
                *(uint4*)cAL1 = *(const uint4*)(pAL + 16 * 128);
                *(uint2*)cW1H = *(const uint2*)(pWH + 16 * 64);
                *(uint2*)cW1L = *(const uint2*)(pWL + 16 * 64);
#pragma unroll 1
                for (int ch = 0; ch < 16; ch++) {
                    unsigned nAH0[4], nAL0[4], nW0H[2], nW0L[2];
                    unsigned nAH1[4], nAL1[4], nW1H[2], nW1L[2];
                    if (ch < 15) {
                        *(uint4*)nAH0 = *(const uint4*)(pAH + (ch + 1) * 128);
                        *(uint4*)nAL0 = *(const uint4*)(pAL + (ch + 1) * 128);
                        *(uint2*)nW0H = *(const uint2*)(pWH + (ch + 1) * 64);
                        *(uint2*)nW0L = *(const uint2*)(pWL + (ch + 1) * 64);
                        *(uint4*)nAH1 = *(const uint4*)(pAH + (ch + 17) * 128);
                        *(uint4*)nAL1 = *(const uint4*)(pAL + (ch + 17) * 128);
                        *(uint2*)nW1H = *(const uint2*)(pWH + (ch + 17) * 64);
                        *(uint2*)nW1L = *(const uint2*)(pWL + (ch + 17) * 64);
                    }
                    mma16816(ka, cAH0, cW0H);
                    mma16816(kb, cAH1, cW1H);
                    mma16816(ka, cAH0, cW0L);
                    mma16816(kb, cAH1, cW1L);
                    mma16816(ka, cAL0, cW0H);
                    mma16816(kb, cAL1, cW1H);
                    if (ch < 15) {
                        *(uint4*)cAH0 = *(uint4*)nAH0; *(uint4*)cAL0 = *(uint4*)nAL0;
                        *(uint2*)cW0H = *(uint2*)nW0H; *(uint2*)cW0L = *(uint2*)nW0L;
                        *(uint4*)cAH1 = *(uint4*)nAH1; *(uint4*)cAL1 = *(uint4*)nAL1;
                        *(uint2*)cW1H = *(uint2*)nW1H; *(uint2*)cW1L = *(uint2*)nW1L;
                    }
                }
#pragma unroll
                for (int r = 0; r < 4; r++) ka[r] += kb[r];
                int col = n8 * 8 + lc * 2;
                float bk0 = b_key[col], bk1 = b_key[col + 1];
                int row0 = m16 * 16 + lr;
                float2 v0 = {fmaxf(ka[0] + bk0, 0.f), fmaxf(ka[1] + bk1, 0.f)};
                float2 v1 = {fmaxf(ka[2] + bk0, 0.f), fmaxf(ka[3] + bk1, 0.f)};
                *(float2*)(d_Mk + ((size_t)row0 * MD + t) * KD + col) = v0;
                *(float2*)(d_Mk + ((size_t)(row0 + 8) * MD + t) * KD + col) = v1;
            } else {  // gate g + attention read -> key_r fragments (parity pn)
                int bb = (bx - 64) * 8 + (wid & 7);
                const float* hb = d_h + (size_t)bb * HD;
                float s = 0.f;
                for (int l = lane; l < HD; l += 32) s += hb[l] * W_g[l];
#pragma unroll
                for (int o = 16; o; o >>= 1) s += __shfl_xor_sync(0xffffffffu, s, o);
                float gv = sigm(s + b_g[0]);
                const float* wkb = d_wk + ((size_t)bb * MD + t) * MD;
                const float* ckb = d_ck + ((size_t)bb * MD + t) * MD;
                const float* mkb = d_Mk + (size_t)bb * MD * KD;
                int m16 = bb >> 4, r = bb & 15;
                unsigned* oH = d_AfH[pn];
                unsigned* oL = d_AfL[pn];
                for (int dp = lane + ((wid >> 3) << 5); dp < 129; dp += 64) {
                    int d0 = dp * 2;
                    float v0 = 0.f, v1 = 0.f;
                    if (d0 < 256) {
                        int m = 0;
                        for (; m + 4 <= t; m += 4) {
                            float w0 = wkb[m], w1 = wkb[m + 1];
                            float w2 = wkb[m + 2], w3 = wkb[m + 3];
                            float x0 = mkb[(m) * KD + d0],     y0 = mkb[(m) * KD + d0 + 1];
                            float x1 = mkb[(m + 1) * KD + d0], y1 = mkb[(m + 1) * KD + d0 + 1];
                            float x2 = mkb[(m + 2) * KD + d0], y2 = mkb[(m + 2) * KD + d0 + 1];
                            float x3 = mkb[(m + 3) * KD + d0], y3 = mkb[(m + 3) * KD + d0 + 1];
                            v0 += w0 * x0 + w1 * x1 + w2 * x2 + w3 * x3;
                            v1 += w0 * y0 + w1 * y1 + w2 * y2 + w3 * y3;
                        }
                        for (; m < t; m++) {
                            float w = wkb[m];
                            v0 += w * mkb[m * KD + d0];
                            v1 += w * mkb[m * KD + d0 + 1];
                        }
                    } else {
                        for (int m = 0; m < t; m++) v0 += wkb[m] * ckb[m];
                    }
                    v0 *= gv; v1 *= gv;
                    __nv_bfloat16 h0 = __float2bfloat16_rn(v0);
                    __nv_bfloat16 h1 = __float2bfloat16_rn(v1);
                    int ch = d0 >> 4, kk = d0 & 15;
                    int lane_a = (r & 7) * 4 + ((kk & 7) >> 1);
                    int w = (r >> 3) + ((kk >> 3) << 1);
                    size_t widx = ((size_t)(m16 * NCHP + ch)) * 128 + lane_a * 4 + w;
                    oH[widx] = (unsigned)__bfloat16_as_ushort(h1) << 16 |
                               __bfloat16_as_ushort(h0);
                    oL[widx] = packbf2(v0 - __bfloat162float(h0),
                                       v1 - __bfloat162float(h1));
                }
            }
            gridBarrier();  // key_r, M_k visible for next step
        } else {  // t == 32: y_lin + argmax
            if (bx >= 64 && bx < 128 && wid < 8) {
                int bb = (bx - 64) * 8 + wid;
                const float* hb = d_h + (size_t)bb * HD;
                float yv[4];
#pragma unroll
                for (int yi = 0; yi < YD; yi++) {
                    float s = 0.f;
                    for (int l = lane; l < HD; l += 32) s += hb[l] * W_y[yi * HD + l];
#pragma unroll
                    for (int o = 16; o; o >>= 1) s += __shfl_xor_sync(0xffffffffu, s, o);
                    yv[yi] = s + b_y[yi];
                }
                if (lane == 0) {
                    int am = 0; float bst = yv[0];
#pragma unroll
                    for (int yi = 1; yi < YD; yi++)
                        if (yv[yi] > bst) { bst = yv[yi]; am = yi; }
                    if (out_size >= BD * YD) {
                        float* of = (float*)outp;
                        of[bb * 4 + 0] = yv[0];
                        of[bb * 4 + 1] = yv[1];
                        of[bb * 4 + 2] = yv[2];
                        of[bb * 4 + 3] = yv[3];
                        if (out_size >= BD * YD + BD) of[BD * YD + bb] = (float)am;
                    } else {
                        ((int*)outp)[bb] = am;
                    }
                }
            }
        }
    }
}

// ------------------------------- launcher ----------------------------------
extern "C" void kernel_launch(void* const* d_in, const int* in_sizes, int n_in,
                              void* d_out, int out_size)
{
    const float* x_seq  = (const float*)d_in[0];
    const float* W_enc  = (const float*)d_in[1];
    const float* gamma  = (const float*)d_in[2];
    const float* beta   = (const float*)d_in[3];
    const float* W_ih   = (const float*)d_in[4];
    const float* W_hh   = (const float*)d_in[5];
    const float* b_ih   = (const float*)d_in[6];
    const float* b_hh   = (const float*)d_in[7];
    const float* W_key  = (const float*)d_in[8];
    const float* b_key  = (const float*)d_in[9];
    const float* W_g    = (const float*)d_in[10];
    const float* b_g    = (const float*)d_in[11];
    const float* cgain  = (const float*)d_in[12];
    const float* cbias  = (const float*)d_in[13];
    const float* W_y    = (const float*)d_in[14];
    const float* b_y    = (const float*)d_in[15];

    cudaFuncSetAttribute(recur, cudaFuncAttributeMaxDynamicSharedMemorySize,
                         SMEM_RECUR);

    prep_kernel<<<1024, 256>>>(W_ih, W_hh, b_ih, b_hh, W_key, W_enc);
    enc_gemm2<<<128, 256>>>(x_seq);
    norm_attn<<<BD, 256>>>(gamma, beta, cgain, cbias);
    recur<<<NB, NT, SMEM_RECUR>>>(b_key, W_g, b_g, W_y, b_y, d_out, out_size);
}

// round 12
// speedup vs baseline: 3.4582x; 1.0335x over previous
#include <cuda_runtime.h>
#include <cuda_bf16.h>
#include <math.h>

// ---------------------------------------------------------------------------
// Model_24730421690434  (R11)
//   B=512, T=32, Z=128, K=256, H=512, 4H=2048, Y=4, M=33
// R11: t=0 GEMM skipped (zero inputs); barrier2 replaced by key_r producer
//      flag consumed mid-Phase-A (chunks reordered h-first); 4-deep cp.async
//      group pipeline (144 KB smem).
// ---------------------------------------------------------------------------

#define NB 128
#define NT 512

#define BD 512
#define TD 32
#define ZD 128
#define KD 256
#define HD 512
#define YD 4
#define MD 33
#define G4 2048
#define NCHP 51     // padded chunks: 0..16 key_r, 17..48 h, 49..50 zero
#define NGRP 17
#define ZP 129
#define CHW 3072    // words/staged chunk: A[0,1024) | Bhi[1024,2048) | Blo[2048,3072)
#define SMEM_RECUR (12 * CHW * 4)   // 4 groups x 3 chunks = 144 KB

// ------------------------------- device state ------------------------------
__device__ __align__(256) unsigned d_BfH[256 * NCHP * 64];
__device__ __align__(256) unsigned d_BfL[256 * NCHP * 64];
__device__ __align__(256) unsigned d_WKfH[32 * 32 * 64];
__device__ __align__(256) unsigned d_WKfL[32 * 32 * 64];
__device__ __align__(256) unsigned d_WEfH[16 * 64 * 64];
__device__ __align__(256) unsigned d_WEfL[16 * 64 * 64];
__device__ __align__(256) unsigned d_AfH[2][32 * NCHP * 128];
__device__ __align__(256) unsigned d_AfL[2][32 * NCHP * 128];

__device__ __align__(256) float d_biasg[G4];
__device__ __align__(256) float d_zbuf[BD * TD * ZD];
__device__ __align__(256) float d_h[BD * HD];
__device__ __align__(256) float d_Mk[(size_t)BD * MD * KD];
__device__ __align__(256) float d_wk[(size_t)BD * MD * MD];
__device__ __align__(256) float d_ck[(size_t)BD * MD * MD];
__device__ unsigned g_cnt1[8 * 32];
__device__ unsigned g_cnt2;
__device__ unsigned g_gen;
__device__ unsigned g_kr;          // key_r producer arrivals (reset in prep)

// reordered chunk index: h chunks (17..48) first, then key_r (0..16), pads
__device__ __forceinline__ int ordc(int i) {
    return (i < 32) ? (17 + i) : ((i < 49) ? (i - 32) : i);
}

__device__ __forceinline__ float tanhap(float x) {
    float y; asm("tanh.approx.f32 %0, %1;" : "=f"(y) : "f"(x)); return y;
}
__device__ __forceinline__ float sigm(float x) {
    return fmaf(tanhap(x * 0.5f), 0.5f, 0.5f);
}

__device__ __forceinline__ void gridBarrier() {
    __syncthreads();
    if (threadIdx.x == 0) {
        const int grp = (blockIdx.x & 7) * 32;
        unsigned gen = *(volatile unsigned*)&g_gen;
        __threadfence();
        if (atomicAdd(&g_cnt1[grp], 1u) == 15u) {
            g_cnt1[grp] = 0u;
            __threadfence();
            if (atomicAdd(&g_cnt2, 1u) == 7u) {
                g_cnt2 = 0u;
                __threadfence();
                atomicAdd(&g_gen, 1u);
            }
        }
        while (*(volatile unsigned*)&g_gen == gen) { __nanosleep(64); }
        __threadfence();
    }
    __syncthreads();
}

__device__ __forceinline__ void cpasync16(void* dst, const void* src) {
    unsigned saddr = (unsigned)__cvta_generic_to_shared(dst);
    asm volatile("cp.async.cg.shared.global [%0], [%1], 16;\n" ::"r"(saddr), "l"(src));
}
#define CPCOMMIT() asm volatile("cp.async.commit_group;\n" ::)
#define CPWAIT(n)  asm volatile("cp.async.wait_group %0;\n" ::"n"(n))

__device__ __forceinline__ void mma16816(float* d, const unsigned* a, const unsigned* b) {
    asm volatile(
        "mma.sync.aligned.m16n8k16.row.col.f32.bf16.bf16.f32 "
        "{%0,%1,%2,%3},{%4,%5,%6,%7},{%8,%9},{%0,%1,%2,%3};"
        : "+f"(d[0]), "+f"(d[1]), "+f"(d[2]), "+f"(d[3])
        : "r"(a[0]), "r"(a[1]), "r"(a[2]), "r"(a[3]), "r"(b[0]), "r"(b[1]));
}

__device__ __forceinline__ unsigned packbf2(float v0, float v1) {
    unsigned short u0 = __bfloat16_as_ushort(__float2bfloat16_rn(v0));
    unsigned short u1 = __bfloat16_as_ushort(__float2bfloat16_rn(v1));
    return (unsigned)u1 << 16 | u0;
}
__device__ __forceinline__ void splitbf2(float v0, float v1, unsigned& hi, unsigned& lo) {
    __nv_bfloat16 h0 = __float2bfloat16_rn(v0);
    __nv_bfloat16 h1 = __float2bfloat16_rn(v1);
    hi = (unsigned)__bfloat16_as_ushort(h1) << 16 | __bfloat16_as_ushort(h0);
    lo = packbf2(v0 - __bfloat162float(h0), v1 - __bfloat162float(h1));
}

// ------------------------------- prep kernel -------------------------------
__device__ __forceinline__ float fetchW(const float* W_ih, const float* W_hh,
                                        int n, int k) {
    if (k < 257) return W_ih[n * 257 + k];
    if (k >= 272 && k < 784) return W_hh[n * HD + (k - 272)];
    return 0.f;
}

__global__ void __launch_bounds__(256) prep_kernel(
    const float* __restrict__ W_ih, const float* __restrict__ W_hh,
    const float* __restrict__ b_ih, const float* __restrict__ b_hh,
    const float* __restrict__ W_key, const float* __restrict__ W_enc)
{
    const int stride = gridDim.x * blockDim.x;
    const int gtid = blockIdx.x * blockDim.x + threadIdx.x;
    if (gtid == 0) g_kr = 0u;

    for (int idx = gtid; idx < 256 * NCHP * 64; idx += stride) {
        int n8 = idx / (NCHP * 64);
        int rem = idx - n8 * (NCHP * 64);
        int c = rem >> 6;
        int lw = rem & 63;
        int lane = lw >> 1, w = lw & 1;
        int lr = lane >> 2, lc = lane & 3;
        int np = n8 * 8 + lr;
        int g = np & 3, j = np >> 2;
        int orig = g * 512 + j;
        int k = c * 16 + w * 8 + lc * 2;
        float v0 = (k < 784) ? fetchW(W_ih, W_hh, orig, k) : 0.f;
        float v1 = (k + 1 < 784) ? fetchW(W_ih, W_hh, orig, k + 1) : 0.f;
        splitbf2(v0, v1, d_BfH[idx], d_BfL[idx]);
    }
    for (int idx = gtid; idx < 32 * 32 * 64; idx += stride) {
        int n8 = idx / (32 * 64);
        int rem = idx - n8 * (32 * 64);
        int c = rem >> 6;
        int lw = rem & 63;
        int lane = lw >> 1, w = lw & 1;
        int lr = lane >> 2, lc = lane & 3;
        int n = n8 * 8 + lr;
        int k = c * 16 + w * 8 + lc * 2;
        splitbf2(W_key[n * HD + k], W_key[n * HD + k + 1],
                 d_WKfH[idx], d_WKfL[idx]);
    }
    for (int idx = gtid; idx < 16 * 64 * 64; idx += stride) {
        int n8 = idx / (64 * 64);
        int rem = idx - n8 * (64 * 64);
        int c = rem >> 6;
        int lw = rem & 63;
        int lane = lw >> 1, w = lw & 1;
        int lr = lane >> 2, lc = lane & 3;
        int n = n8 * 8 + lr;
        int k = c * 16 + w * 8 + lc * 2;
        splitbf2(W_enc[k * ZD + n], W_enc[(k + 1) * ZD + n],
                 d_WEfH[idx], d_WEfL[idx]);
    }
    for (int np = gtid; np < G4; np += stride) {
        int orig = (np & 3) * 512 + (np >> 2);
        d_biasg[np] = b_ih[orig] + b_hh[orig];
    }
    for (int idx = gtid; idx < 32 * NCHP * 128; idx += stride) {
        d_AfH[0][idx] = 0u; d_AfL[0][idx] = 0u;
        d_AfH[1][idx] = 0u; d_AfL[1][idx] = 0u;
    }
}

// ------------------- encoder GEMM on tensor cores --------------------------
__global__ void __launch_bounds__(256) enc_gemm2(const float* __restrict__ X)
{
    const int tid = threadIdx.x;
    const int lane = tid & 31, wid = tid >> 5;
    const int lr = lane >> 2, lc = lane & 3;
    const int m16 = blockIdx.x * 8 + wid;

    const float* xr0 = X + (size_t)(m16 * 16 + lr) * 1024;
    const float* xr1 = xr0 + 8 * 1024;

    float acc[16][4];
#pragma unroll
    for (int n8 = 0; n8 < 16; n8++)
#pragma unroll
        for (int r = 0; r < 4; r++) acc[n8][r] = 0.f;

#pragma unroll 1
    for (int c = 0; c < 64; c++) {
        int k = c * 16 + lc * 2;
        float2 x00 = *(const float2*)(xr0 + k);
        float2 x10 = *(const float2*)(xr1 + k);
        float2 x01 = *(const float2*)(xr0 + k + 8);
        float2 x11 = *(const float2*)(xr1 + k + 8);
        unsigned aH[4], aL[4];
        splitbf2(x00.x, x00.y, aH[0], aL[0]);
        splitbf2(x10.x, x10.y, aH[1], aL[1]);
        splitbf2(x01.x, x01.y, aH[2], aL[2]);
        splitbf2(x11.x, x11.y, aH[3], aL[3]);
#pragma unroll
        for (int n8 = 0; n8 < 16; n8++) {
            const unsigned* pH = d_WEfH + (size_t)(n8 * 64 + c) * 64 + lane * 2;
            const unsigned* pL = d_WEfL + (size_t)(n8 * 64 + c) * 64 + lane * 2;
            unsigned bH[2], bL[2];
            *(uint2*)bH = *(const uint2*)pH;
            *(uint2*)bL = *(const uint2*)pL;
            mma16816(acc[n8], aH, bH);
            mma16816(acc[n8], aH, bL);
            mma16816(acc[n8], aL, bH);
        }
    }
    int row0 = m16 * 16 + lr;
#pragma unroll
    for (int n8 = 0; n8 < 16; n8++) {
        int col = n8 * 8 + lc * 2;
        *(float2*)(d_zbuf + (size_t)row0 * ZD + col)       = make_float2(acc[n8][0], acc[n8][1]);
        *(float2*)(d_zbuf + (size_t)(row0 + 8) * ZD + col) = make_float2(acc[n8][2], acc[n8][3]);
    }
}

// ------- fused context norm + attention precompute (per batch block) -------
__global__ void __launch_bounds__(256) norm_attn(
    const float* __restrict__ gamma, const float* __restrict__ beta,
    const float* __restrict__ cgain, const float* __restrict__ cbias)
{
    __shared__ float zs[TD * ZP];
    __shared__ float S[TD * TD];
    const int b = blockIdx.x, tid = threadIdx.x;
    const int lane = tid & 31, w = tid >> 5;

    if (tid < 128) {
        float v[TD];
        float s = 0.f;
#pragma unroll
        for (int t = 0; t < TD; t++) {
            v[t] = d_zbuf[((size_t)(b * TD) + t) * ZD + tid];
            s += v[t];
        }
        float mu = s * (1.f / TD);
        float q = 0.f;
#pragma unroll
        for (int t = 0; t < TD; t++) { float d = v[t] - mu; q += d * d; }
        float inv = rsqrtf(q * (1.f / TD) + 1e-8f);
        float ga = gamma[tid], be = beta[tid];
#pragma unroll
        for (int t = 0; t < TD; t++)
            zs[t * ZP + tid] = (v[t] - mu) * inv * ga + be;
    }
    __syncthreads();

    const float cg = cgain[0], cb = cbias[0];
    for (int p = tid; p < TD * TD; p += 256) {
        int t = p >> 5, m = p & 31;
        if (m < t) {
            const float* zt = zs + t * ZP;
            const float* zm = zs + m * ZP;
            float s = 0.f;
#pragma unroll 8
            for (int i = 0; i < ZD; i++) s += zt[i] * zm[i];
            S[p] = s;
        }
    }
    __syncthreads();
#pragma unroll
    for (int it = 0; it < 4; it++) {
        int t = 1 + w + it * 8;
        if (t > 31) break;
        float sv = (lane < t) ? S[t * TD + lane] : -3.4e38f;
        float mx = sv;
#pragma unroll
        for (int o = 16; o; o >>= 1) mx = fmaxf(mx, __shfl_xor_sync(0xffffffffu, mx, o));
        float e = (lane < t) ? __expf(sv - mx) : 0.f;
        float sum = e;
#pragma unroll
        for (int o = 16; o; o >>= 1) sum += __shfl_xor_sync(0xffffffffu, sum, o);
        float inv = __fdividef(1.f, sum);
        if (lane < t) {
            d_wk[((size_t)b * MD + t) * MD + lane] = e * inv;
            d_ck[((size_t)b * MD + t) * MD + lane] = sigm(sv * cg + cb);
        }
    }
}

// ------------------------- persistent recurrence ---------------------------
__global__ void __launch_bounds__(NT) recur(
    const float* __restrict__ b_key, const float* __restrict__ W_g,
    const float* __restrict__ b_g,   const float* __restrict__ W_y,
    const float* __restrict__ b_y,   void* outp, int out_size)
{
    extern __shared__ unsigned sS[];   // 4 groups x 3 chunks x 3072 words

    const int tid = threadIdx.x;
    const int bx = blockIdx.x;
    const int lane = tid & 31, wid = tid >> 5;
    const int lr = lane >> 2, lc = lane & 3;

    const int mblk = bx >> 4, nblk = bx & 15;
    const int wmm = wid & 3;
    const int wn  = wid >> 2;
    const int m16g = mblk * 4 + wmm;

    const int t8      = tid & 255;
    const int a_plane = t8 >> 7;
    const int a_m16A  = mblk * 4 + ((t8 >> 5) & 3);
    const int a_widx  = (t8 & 31) * 4;
    const int a_soff  = a_plane * 512 + ((t8 >> 5) & 3) * 128 + a_widx;

    const int b_plane = tid >> 8;
    const int b_n8l   = (tid >> 4) & 15;
    const int b_w4    = (tid & 15) * 4;
    const int b_soff  = 1024 + b_plane * 1024 + b_n8l * 64 + b_w4;
    const unsigned* bSrc = (b_plane ? d_BfL : d_BfH) +
                           (size_t)(nblk * 16 + b_n8l) * (NCHP * 64) + b_w4;

    float4 bias4[4];
#pragma unroll
    for (int jj = 0; jj < 4; jj++) {
        int n8g = nblk * 16 + wn * 4 + jj;
        int jq = n8g * 2 + (lc >> 1);
        bias4[jj] = *(const float4*)(d_biasg + jq * 4);
    }

    const bool odd = (lc & 1);
    float cc4[4] = {0.f, 0.f, 0.f, 0.f};

    for (int t = 0; t < MD; t++) {
        const int cur = t & 1, pn = (t + 1) & 1;
        // ============ Phase A: gate GEMM + fused cell =======================
        {
            float acc[4][4];
#pragma unroll
            for (int j = 0; j < 4; j++)
#pragma unroll
                for (int r = 0; r < 4; r++) acc[j][r] = 0.f;

            if (t > 0) {   // t==0: inputs all zero -> gates = bias only
                const unsigned* aSrc = (a_plane ? d_AfL[cur] : d_AfH[cur]) +
                                       (size_t)a_m16A * (NCHP * 128) + a_widx;
                // prologue: stage groups 0..2 (all h chunks)
#pragma unroll
                for (int p = 0; p < 3; p++) {
#pragma unroll
                    for (int ccq = 0; ccq < 3; ccq++) {
                        int ch = ordc(p * 3 + ccq);
                        unsigned* dst = sS + (p * 3 + ccq) * CHW;
                        if (tid < 256) cpasync16(dst + a_soff, aSrc + ch * 128);
                        cpasync16(dst + b_soff, bSrc + ch * 64);
                    }
                    CPCOMMIT();
                }

                int bufIdx = 0;
#pragma unroll 1
                for (int g = 0; g < NGRP; g++) {
                    int sg = g + 3;
                    CPWAIT(2);
                    __syncthreads();
                    if (sg == 10) {   // about to stage first key_r chunk
                        if (tid == 0) {
                            unsigned tgt = 128u * (unsigned)t;
                            while (*(volatile unsigned*)&g_kr < tgt) { __nanosleep(64); }
                            __threadfence();
                        }
                        __syncthreads();
                    }
                    if (sg < NGRP) {
                        int nbuf = bufIdx + 3; if (nbuf >= 4) nbuf -= 4;
#pragma unroll
                        for (int ccq = 0; ccq < 3; ccq++) {
                            int ch = ordc(sg * 3 + ccq);
                            unsigned* dst = sS + (nbuf * 3 + ccq) * CHW;
                            if (tid < 256) cpasync16(dst + a_soff, aSrc + ch * 128);
                            cpasync16(dst + b_soff, bSrc + ch * 64);
                        }
                    }
                    CPCOMMIT();
                    const unsigned* gb = sS + bufIdx * 3 * CHW;
#pragma unroll
                    for (int ccq = 0; ccq < 3; ccq++) {
                        const unsigned* base = gb + ccq * CHW;
                        unsigned aH[4], aL[4];
                        *(uint4*)aH = *(const uint4*)(base + wmm * 128 + lane * 4);
                        *(uint4*)aL = *(const uint4*)(base + 512 + wmm * 128 + lane * 4);
                        unsigned bH[4][2], bL[4][2];
#pragma unroll
                        for (int jj = 0; jj < 4; jj++) {
                            *(uint2*)bH[jj] = *(const uint2*)(base + 1024 + (wn * 4 + jj) * 64 + lane * 2);
                            *(uint2*)bL[jj] = *(const uint2*)(base + 2048 + (wn * 4 + jj) * 64 + lane * 2);
                        }
#pragma unroll
                        for (int jj = 0; jj < 4; jj++) mma16816(acc[jj], aH, bH[jj]);
#pragma unroll
                        for (int jj = 0; jj < 4; jj++) mma16816(acc[jj], aH, bL[jj]);
#pragma unroll
                        for (int jj = 0; jj < 4; jj++) mma16816(acc[jj], aL, bH[jj]);
                    }
                    bufIdx++; if (bufIdx == 4) bufIdx = 0;
                }
            }

            // ---- fused epilogue: gates + cell update + h frag stores ----
            unsigned* hOutH = d_AfH[pn];
            unsigned* hOutL = d_AfL[pn];
#pragma unroll
            for (int jj = 0; jj < 4; jj++) {
                float a0 = acc[jj][0], a1 = acc[jj][1];
                float a2 = acc[jj][2], a3 = acc[jj][3];
                float p0 = __shfl_xor_sync(0xffffffffu, odd ? a0 : a2, 1);
                float p1 = __shfl_xor_sync(0xffffffffu, odd ? a1 : a3, 1);
                float4 bb4 = bias4[jj];
                float gi, gf, gg, go;
                if (!odd) { gi = a0 + bb4.x; gf = a1 + bb4.y; gg = p0 + bb4.z; go = p1 + bb4.w; }
                else      { gi = p0 + bb4.x; gf = p1 + bb4.y; gg = a2 + bb4.z; go = a3 + bb4.w; }
                float cn = sigm(gf) * cc4[jj] + sigm(gi) * tanhap(gg);
                cc4[jj] = cn;
                float hv = sigm(go) * tanhap(cn);
                int n8g = nblk * 16 + wn * 4 + jj;
                int jq = n8g * 2 + (lc >> 1);
                int row = m16g * 16 + lr + (odd ? 8 : 0);
                d_h[row * HD + jq] = hv;
                __nv_bfloat16 hh = __float2bfloat16_rn(hv);
                __nv_bfloat16 hl = __float2bfloat16_rn(hv - __bfloat162float(hh));
                unsigned uh = (unsigned)__bfloat16_as_ushort(hh);
                unsigned ul = (unsigned)__bfloat16_as_ushort(hl);
                unsigned ph = __shfl_xor_sync(0xffffffffu, uh, 2);
                unsigned pl = __shfl_xor_sync(0xffffffffu, ul, 2);
                if ((lc & 2) == 0) {
                    int kk = jq & 15;
                    int ch = 17 + (jq >> 4);
                    int lane_a = lr * 4 + ((kk & 7) >> 1);
                    int w = (odd ? 1 : 0) + ((kk >> 3) << 1);
                    size_t widx = ((size_t)(m16g * NCHP + ch)) * 128 + lane_a * 4 + w;
                    hOutH[widx] = (ph << 16) | uh;
                    hOutL[widx] = (pl << 16) | ul;
                }
            }
        }
        gridBarrier();  // h, Mk(t-1) visible everywhere

        // ============ Phase C ==============================================
        if (t < TD) {
            if (bx < 64) {  // key_w = relu(h @ W_key^T + b_key), dual-chain
                const int m16 = (bx >> 3) * 4 + (wid & 3);
                const int n8  = (bx & 7) * 4 + (wid >> 2);
                const unsigned* pAH = d_AfH[pn] + ((size_t)m16 * NCHP + 17) * 128 + lane * 4;
                const unsigned* pAL = d_AfL[pn] + ((size_t)m16 * NCHP + 17) * 128 + lane * 4;
                const unsigned* pWH = d_WKfH + (size_t)n8 * (32 * 64) + lane * 2;
                const unsigned* pWL = d_WKfL + (size_t)n8 * (32 * 64) + lane * 2;
                float ka[4] = {0.f, 0.f, 0.f, 0.f};
                float kb[4] = {0.f, 0.f, 0.f, 0.f};
                unsigned cAH0[4], cAL0[4], cW0H[2], cW0L[2];
                unsigned cAH1[4], cAL1[4], cW1H[2], cW1L[2];
                *(uint4*)cAH0 = *(const uint4*)(pAH);
                *(uint4*)cAL0 = *(const uint4*)(pAL);
                *(uint2*)cW0H = *(const uint2*)(pWH);
                *(uint2*)cW0L = *(const uint2*)(pWL);
                *(uint4*)cAH1 = *(const uint4*)(pAH + 16 * 128);
                *(uint4*)cAL1 = *(const uint4*)(pAL + 16 * 128);
                *(uint2*)cW1H = *(const uint2*)(pWH + 16 * 64);
                *(uint2*)cW1L = *(const uint2*)(pWL + 16 * 64);
#pragma unroll 1
                for (int ch = 0; ch < 16; ch++) {
                    unsigned nAH0[4], nAL0[4], nW0H[2], nW0L[2];
                    unsigned nAH1[4], nAL1[4], nW1H[2], nW1L[2];
                    if (ch < 15) {
                        *(uint4*)nAH0 = *(const uint4*)(pAH + (ch + 1) * 128);
                        *(uint4*)nAL0 = *(const uint4*)(pAL + (ch + 1) * 128);
                        *(uint2*)nW0H = *(const uint2*)(pWH + (ch + 1) * 64);
                        *(uint2*)nW0L = *(const uint2*)(pWL + (ch + 1) * 64);
                        *(uint4*)nAH1 = *(const uint4*)(pAH + (ch + 17) * 128);
                        *(uint4*)nAL1 = *(const uint4*)(pAL + (ch + 17) * 128);
                        *(uint2*)nW1H = *(const uint2*)(pWH + (ch + 17) * 64);
                        *(uint2*)nW1L = *(const uint2*)(pWL + (ch + 17) * 64);
                    }
                    mma16816(ka, cAH0, cW0H);
                    mma16816(kb, cAH1, cW1H);
                    mma16816(ka, cAH0, cW0L);
                    mma16816(kb, cAH1, cW1L);
                    mma16816(ka, cAL0, cW0H);
                    mma16816(kb, cAL1, cW1H);
                    if (ch < 15) {
                        *(uint4*)cAH0 = *(uint4*)nAH0; *(uint4*)cAL0 = *(uint4*)nAL0;
                        *(uint2*)cW0H = *(uint2*)nW0H; *(uint2*)cW0L = *(uint2*)nW0L;
                        *(uint4*)cAH1 = *(uint4*)nAH1; *(uint4*)cAL1 = *(uint4*)nAL1;
                        *(uint2*)cW1H = *(uint2*)nW1H; *(uint2*)cW1L = *(uint2*)nW1L;
                    }
                }
#pragma unroll
                for (int r = 0; r < 4; r++) ka[r] += kb[r];
                int col = n8 * 8 + lc * 2;
                float bk0 = b_key[col], bk1 = b_key[col + 1];
                int row0 = m16 * 16 + lr;
                float2 v0 = {fmaxf(ka[0] + bk0, 0.f), fmaxf(ka[1] + bk1, 0.f)};
                float2 v1 = {fmaxf(ka[2] + bk0, 0.f), fmaxf(ka[3] + bk1, 0.f)};
                *(float2*)(d_Mk + ((size_t)row0 * MD + t) * KD + col) = v0;
                *(float2*)(d_Mk + ((size_t)(row0 + 8) * MD + t) * KD + col) = v1;
            } else {  // gate g + attention read -> key_r fragments (parity pn)
                int bb = (bx - 64) * 8 + (wid & 7);
                const float* hb = d_h + (size_t)bb * HD;
                float s = 0.f;
                for (int l = lane; l < HD; l += 32) s += hb[l] * W_g[l];
#pragma unroll
                for (int o = 16; o; o >>= 1) s += __shfl_xor_sync(0xffffffffu, s, o);
                float gv = sigm(s + b_g[0]);
                const float* wkb = d_wk + ((size_t)bb * MD + t) * MD;
                const float* ckb = d_ck + ((size_t)bb * MD + t) * MD;
                const float* mkb = d_Mk + (size_t)bb * MD * KD;
                int m16 = bb >> 4, r = bb & 15;
                unsigned* oH = d_AfH[pn];
                unsigned* oL = d_AfL[pn];
                for (int dp = lane + ((wid >> 3) << 5); dp < 129; dp += 64) {
                    int d0 = dp * 2;
                    float v0 = 0.f, v1 = 0.f;
                    if (d0 < 256) {
                        int m = 0;
                        for (; m + 4 <= t; m += 4) {
                            float w0 = wkb[m], w1 = wkb[m + 1];
                            float w2 = wkb[m + 2], w3 = wkb[m + 3];
                            float x0 = mkb[(m) * KD + d0],     y0 = mkb[(m) * KD + d0 + 1];
                            float x1 = mkb[(m + 1) * KD + d0], y1 = mkb[(m + 1) * KD + d0 + 1];
                            float x2 = mkb[(m + 2) * KD + d0], y2 = mkb[(m + 2) * KD + d0 + 1];
                            float x3 = mkb[(m + 3) * KD + d0], y3 = mkb[(m + 3) * KD + d0 + 1];
                            v0 += w0 * x0 + w1 * x1 + w2 * x2 + w3 * x3;
                            v1 += w0 * y0 + w1 * y1 + w2 * y2 + w3 * y3;
                        }
                        for (; m < t; m++) {
                            float w = wkb[m];
                            v0 += w * mkb[m * KD + d0];
                            v1 += w * mkb[m * KD + d0 + 1];
                        }
                    } else {
                        for (int m = 0; m < t; m++) v0 += wkb[m] * ckb[m];
                    }
                    v0 *= gv; v1 *= gv;
                    __nv_bfloat16 h0 = __float2bfloat16_rn(v0);
                    __nv_bfloat16 h1 = __float2bfloat16_rn(v1);
                    int ch = d0 >> 4, kk = d0 & 15;
                    int lane_a = (r & 7) * 4 + ((kk & 7) >> 1);
                    int w = (r >> 3) + ((kk >> 3) << 1);
                    size_t widx = ((size_t)(m16 * NCHP + ch)) * 128 + lane_a * 4 + w;
                    oH[widx] = (unsigned)__bfloat16_as_ushort(h1) << 16 |
                               __bfloat16_as_ushort(h0);
                    oL[widx] = packbf2(v0 - __bfloat162float(h0),
                                       v1 - __bfloat162float(h1));
                }
            }
            // producer arrival: key_r (and Mk) for step t complete on this block
            __syncthreads();
            if (tid == 0) { __threadfence(); atomicAdd(&g_kr, 1u); }
        } else {  // t == 32: y_lin + argmax
            if (bx >= 64 && bx < 128 && wid < 8) {
                int bb = (bx - 64) * 8 + wid;
                const float* hb = d_h + (size_t)bb * HD;
                float yv[4];
#pragma unroll
                for (int yi = 0; yi < YD; yi++) {
                    float s = 0.f;
                    for (int l = lane; l < HD; l += 32) s += hb[l] * W_y[yi * HD + l];
#pragma unroll
                    for (int o = 16; o; o >>= 1) s += __shfl_xor_sync(0xffffffffu, s, o);
                    yv[yi] = s + b_y[yi];
                }
                if (lane == 0) {
                    int am = 0; float bst = yv[0];
#pragma unroll
                    for (int yi = 1; yi < YD; yi++)
                        if (yv[yi] > bst) { bst = yv[yi]; am = yi; }
                    if (out_size >= BD * YD) {
                        float* of = (float*)outp;
                        of[bb * 4 + 0] = yv[0];
                        of[bb * 4 + 1] = yv[1];
                        of[bb * 4 + 2] = yv[2];
                        of[bb * 4 + 3] = yv[3];
                        if (out_size >= BD * YD + BD) of[BD * YD + bb] = (float)am;
                    } else {
                        ((int*)outp)[bb] = am;
                    }
                }
            }
        }
    }
}

// ------------------------------- launcher ----------------------------------
extern "C" void kernel_launch(void* const* d_in, const int* in_sizes, int n_in,
                              void* d_out, int out_size)
{
    const float* x_seq  = (const float*)d_in[0];
    const float* W_enc  = (const float*)d_in[1];
    const float* gamma  = (const float*)d_in[2];
    const float* beta   = (const float*)d_in[3];
    const float* W_ih   = (const float*)d_in[4];
    const float* W_hh   = (const float*)d_in[5];
    const float* b_ih   = (const float*)d_in[6];
    const float* b_hh   = (const float*)d_in[7];
    const float* W_key  = (const float*)d_in[8];
    const float* b_key  = (const float*)d_in[9];
    const float* W_g    = (const float*)d_in[10];
    const float* b_g    = (const float*)d_in[11];
    const float* cgain  = (const float*)d_in[12];
    const float* cbias  = (const float*)d_in[13];
    const float* W_y    = (const float*)d_in[14];
    const float* b_y    = (const float*)d_in[15];

    cudaFuncSetAttribute(recur, cudaFuncAttributeMaxDynamicSharedMemorySize,
                         SMEM_RECUR);

    prep_kernel<<<1024, 256>>>(W_ih, W_hh, b_ih, b_hh, W_key, W_enc);
    enc_gemm2<<<128, 256>>>(x_seq);
    norm_attn<<<BD, 256>>>(gamma, beta, cgain, cbias);
    recur<<<NB, NT, SMEM_RECUR>>>(b_key, W_g, b_g, W_y, b_y, d_out, out_size);
}